// round 11
// baseline (speedup 1.0000x reference)
#include <cuda_runtime.h>
#include <cuda.h>
#include <cuda_bf16.h>
#include <cstdint>
#include <cstring>
#include <math.h>

#define SEQ   2048
#define BATCH 2
#define DM    1024
#define NH    16
#define HD    64
#define BSROWS (BATCH*SEQ)   // 4096
#define QLD   (3*DM)         // 3072

#if defined(__CUDA_ARCH_FEAT_SM103_ALL) || defined(__CUDA_ARCH_FEAT_SM100_ALL) || \
    (defined(__CUDA_ARCH_SPECIFIC__) && (__CUDA_ARCH_SPECIFIC__ >= 1000))
#define HAS_TCGEN05 1
#else
#define HAS_TCGEN05 0
#endif

// ---------------------------------------------------------------------------
// Scratch: everything mid-pipeline is bf16 hi/lo
// ---------------------------------------------------------------------------
__device__ __nv_bfloat16 g_x_hi[(size_t)BSROWS * DM];
__device__ __nv_bfloat16 g_x_lo[(size_t)BSROWS * DM];
__device__ __nv_bfloat16 g_qkv_hi[(size_t)BSROWS * QLD];
__device__ __nv_bfloat16 g_qkv_lo[(size_t)BSROWS * QLD];
__device__ __nv_bfloat16 g_val_hi[(size_t)BSROWS * DM];
__device__ __nv_bfloat16 g_val_lo[(size_t)BSROWS * DM];
__device__ __nv_bfloat16 g_wqkvT_hi[(size_t)QLD * DM];
__device__ __nv_bfloat16 g_wqkvT_lo[(size_t)QLD * DM];
__device__ __nv_bfloat16 g_woutT_hi[(size_t)DM * DM];
__device__ __nv_bfloat16 g_woutT_lo[(size_t)DM * DM];

// ---------------------------------------------------------------------------
// Generic helpers
// ---------------------------------------------------------------------------
__device__ __forceinline__ uint32_t su32(const void* p) {
    return (uint32_t)__cvta_generic_to_shared(p);
}
__device__ __forceinline__ uint32_t pk_hi(float a, float b) {
    __nv_bfloat162 t = __floats2bfloat162_rn(a, b);
    return *(uint32_t*)&t;
}
__device__ __forceinline__ uint32_t pk_lo(float a, float b) {
    float ah = __bfloat162float(__float2bfloat16_rn(a));
    float bh = __bfloat162float(__float2bfloat16_rn(b));
    __nv_bfloat162 t = __floats2bfloat162_rn(a - ah, b - bh);
    return *(uint32_t*)&t;
}
#define SMEM_SWZ(off) ((off) ^ (((off) >> 3) & 0x70))

// cp.async (sm_80+) — still used by attention
__device__ __forceinline__ void cp16(uint32_t dst, const void* src) {
    asm volatile("cp.async.cg.shared.global [%0], [%1], 16;" :: "r"(dst), "l"(src) : "memory");
}
#define CP_COMMIT() asm volatile("cp.async.commit_group;" ::: "memory")
#define CP_WAIT0()  asm volatile("cp.async.wait_group 0;" ::: "memory")

#if HAS_TCGEN05
__device__ __forceinline__ bool elect1() {
    uint32_t r;
    asm volatile("{\n\t.reg .pred p;\n\telect.sync _|p, 0xFFFFFFFF;\n\tselp.b32 %0, 1, 0, p;\n\t}" : "=r"(r));
    return r != 0;
}
#define MBAR_INIT(addr, cnt) \
    asm volatile("mbarrier.init.shared.b64 [%0], %1;" :: "r"(addr), "r"(cnt) : "memory")
#define MBAR_EXPECT_TX(addr, tx) \
    asm volatile("mbarrier.arrive.expect_tx.shared.b64 _, [%0], %1;" :: "r"(addr), "r"(tx) : "memory")
#define MBAR_WAIT(addr, ph) do {                                              \
    uint32_t _m = (addr), _p = (ph), _d;                                      \
    asm volatile("{\n\t.reg .pred p;\n\t"                                     \
        "mbarrier.try_wait.parity.acquire.cta.shared::cta.b64 p, [%1], %2;\n\t" \
        "selp.b32 %0, 1, 0, p;\n\t}" : "=r"(_d) : "r"(_m), "r"(_p) : "memory"); \
    if (!_d) {                                                                \
        asm volatile("{\n\t.reg .pred P1;\n\t"                                \
            "WL_%=:\n\t"                                                      \
            "mbarrier.try_wait.parity.acquire.cta.shared::cta.b64 P1, [%0], %1, 0x989680;\n\t" \
            "@P1 bra.uni WD_%=;\n\tbra.uni WL_%=;\n\tWD_%=:\n\t}"             \
            :: "r"(_m), "r"(_p) : "memory");                                  \
    }                                                                         \
} while (0)
#define TC_ALLOC(smem_addr, ncols) \
    asm volatile("tcgen05.alloc.cta_group::1.sync.aligned.shared::cta.b32 [%0], %1;" \
                 :: "r"(smem_addr), "r"(ncols) : "memory")
#define TC_RELINQ() \
    asm volatile("tcgen05.relinquish_alloc_permit.cta_group::1.sync.aligned;")
#define TC_DEALLOC(tmem, ncols) \
    asm volatile("tcgen05.dealloc.cta_group::1.sync.aligned.b32 %0, %1;" :: "r"(tmem), "r"(ncols))
#define TC_COMMIT(mbar) \
    asm volatile("tcgen05.commit.cta_group::1.mbarrier::arrive::one.shared::cluster.b64 [%0];" \
                 :: "r"(mbar) : "memory")
#define TC_FENCE_AFTER()  asm volatile("tcgen05.fence::after_thread_sync;" ::: "memory")
#define TC_FENCE_BEFORE() asm volatile("tcgen05.fence::before_thread_sync;" ::: "memory")
#define TC_WAIT_LD()      asm volatile("tcgen05.wait::ld.sync.aligned;" ::: "memory")
#define TC_WAIT_ST()      asm volatile("tcgen05.wait::st.sync.aligned;" ::: "memory")
#define FENCE_ASYNC()     asm volatile("fence.proxy.async.shared::cta;" ::: "memory")

// 2D TMA load (global -> shared::cta), single thread
__device__ __forceinline__ void tma2d(uint32_t smem, const CUtensorMap* m,
                                      int x, int y, uint32_t mbar) {
    asm volatile(
        "cp.async.bulk.tensor.2d.shared::cta.global.tile.mbarrier::complete_tx::bytes "
        "[%0], [%1, {%2, %3}], [%4];"
        :: "r"(smem), "l"(m), "r"(x), "r"(y), "r"(mbar) : "memory");
}

#define LDTM_X32(r, a) \
    asm volatile("tcgen05.ld.sync.aligned.32x32b.x32.b32 "                    \
        "{%0, %1, %2, %3, %4, %5, %6, %7, %8, %9, %10, %11, %12, %13, %14, %15, " \
        " %16, %17, %18, %19, %20, %21, %22, %23, %24, %25, %26, %27, %28, %29, %30, %31}, [%32];" \
        : "=r"((r)[0]),  "=r"((r)[1]),  "=r"((r)[2]),  "=r"((r)[3]),          \
          "=r"((r)[4]),  "=r"((r)[5]),  "=r"((r)[6]),  "=r"((r)[7]),          \
          "=r"((r)[8]),  "=r"((r)[9]),  "=r"((r)[10]), "=r"((r)[11]),         \
          "=r"((r)[12]), "=r"((r)[13]), "=r"((r)[14]), "=r"((r)[15]),         \
          "=r"((r)[16]), "=r"((r)[17]), "=r"((r)[18]), "=r"((r)[19]),         \
          "=r"((r)[20]), "=r"((r)[21]), "=r"((r)[22]), "=r"((r)[23]),         \
          "=r"((r)[24]), "=r"((r)[25]), "=r"((r)[26]), "=r"((r)[27]),         \
          "=r"((r)[28]), "=r"((r)[29]), "=r"((r)[30]), "=r"((r)[31])          \
        : "r"(a))

#define STTM_X16(a, r) \
    asm volatile("tcgen05.st.sync.aligned.32x32b.x16.b32 [%0], "              \
        "{%1, %2, %3, %4, %5, %6, %7, %8, %9, %10, %11, %12, %13, %14, %15, %16};" \
        :: "r"(a),                                                            \
           "r"((r)[0]),  "r"((r)[1]),  "r"((r)[2]),  "r"((r)[3]),             \
           "r"((r)[4]),  "r"((r)[5]),  "r"((r)[6]),  "r"((r)[7]),             \
           "r"((r)[8]),  "r"((r)[9]),  "r"((r)[10]), "r"((r)[11]),            \
           "r"((r)[12]), "r"((r)[13]), "r"((r)[14]), "r"((r)[15])             \
        : "memory")

// K-major SW128 desc (128B rows): SBO=64, LBO=1
static __device__ __forceinline__ uint64_t make_desc(uint32_t addr) {
    const uint64_t base = (uint64_t(2) << 61) | (uint64_t(1) << 46)
                        | (uint64_t(64) << 32) | (uint64_t(1) << 16);
    return base | ((uint64_t)(addr >> 4) & 0x3FFF);
}
__device__ __forceinline__ void mma_bf16_ss(uint32_t d, uint64_t ad, uint64_t bd,
                                            uint32_t idesc, bool acc) {
    uint32_t en = acc ? 1u : 0u;
    asm volatile(
        "{\n\t.reg .pred p;\n\tsetp.ne.u32 p, %4, 0;\n\t"
        "tcgen05.mma.cta_group::1.kind::f16 [%0], %1, %2, %3, {%5, %5, %5, %5}, p;\n\t}"
        :: "r"(d), "l"(ad), "l"(bd), "r"(idesc), "r"(en), "r"(0u) : "memory");
}
__device__ __forceinline__ void mma_bf16_ts(uint32_t d, uint32_t a, uint64_t bd,
                                            uint32_t idesc, bool acc) {
    uint32_t en = acc ? 1u : 0u;
    asm volatile(
        "{\n\t.reg .pred p;\n\tsetp.ne.u32 p, %4, 0;\n\t"
        "tcgen05.mma.cta_group::1.kind::f16 [%0], [%1], %2, %3, {%5, %5, %5, %5}, p;\n\t}"
        :: "r"(d), "r"(a), "l"(bd), "r"(idesc), "r"(en), "r"(0u) : "memory");
}
#define GEMM_IDESC  ((1u << 4) | (1u << 7) | (1u << 10) | (16u << 17) | (8u << 24))  // M128 N128
#define ATTN_IDESC1 ((1u << 4) | (1u << 7) | (1u << 10) | (16u << 17) | (8u << 24))  // M128 N128
#define ATTN_IDESC2 ((1u << 4) | (1u << 7) | (1u << 10) | (8u  << 17) | (8u << 24))  // M128 N64
#endif  // HAS_TCGEN05

// ---------------------------------------------------------------------------
// Elementwise split: fp32 -> bf16 hi/lo (8 elems/thread)
// ---------------------------------------------------------------------------
__global__ __launch_bounds__(256) void split_f32_kernel(
    const float* __restrict__ X, __nv_bfloat16* __restrict__ Xhi,
    __nv_bfloat16* __restrict__ Xlo)
{
    const size_t i = ((size_t)blockIdx.x * 256 + threadIdx.x) * 8;
    float4 a = *(const float4*)(X + i);
    float4 b = *(const float4*)(X + i + 4);
    uint4 h, l;
    h.x = pk_hi(a.x, a.y); h.y = pk_hi(a.z, a.w);
    h.z = pk_hi(b.x, b.y); h.w = pk_hi(b.z, b.w);
    l.x = pk_lo(a.x, a.y); l.y = pk_lo(a.z, a.w);
    l.z = pk_lo(b.x, b.y); l.w = pk_lo(b.z, b.w);
    *(uint4*)(Xhi + i) = h;
    *(uint4*)(Xlo + i) = l;
}

// ---------------------------------------------------------------------------
// Transpose + bf16 hi/lo split: W[K,N] -> Thi/Tlo[N,K]
// ---------------------------------------------------------------------------
__global__ __launch_bounds__(256) void transpose_split_kernel(
    const float* __restrict__ W, __nv_bfloat16* __restrict__ Thi,
    __nv_bfloat16* __restrict__ Tlo, int K, int N)
{
    __shared__ float t[32][33];
    const int n0 = blockIdx.x << 5, k0 = blockIdx.y << 5;
    const int x = threadIdx.x, y = threadIdx.y;
    #pragma unroll
    for (int i = y; i < 32; i += 8)
        t[i][x] = W[(size_t)(k0 + i) * N + n0 + x];
    __syncthreads();
    #pragma unroll
    for (int i = y; i < 32; i += 8) {
        float v  = t[x][i];
        __nv_bfloat16 hb = __float2bfloat16_rn(v);
        size_t o = (size_t)(n0 + i) * K + k0 + x;
        Thi[o] = hb;
        Tlo[o] = __float2bfloat16_rn(v - __bfloat162float(hb));
    }
}

// ---------------------------------------------------------------------------
// GEMM via TMA: C = A[M,K] @ Bt[N,K]^T + bias, pre-split bf16 operands.
// 128x128 tile, BK=64, 3 buffers. Thread 0 runs the whole pipeline (TMA +
// MMA issue, mbar waits); no per-stage __syncthreads.
// ---------------------------------------------------------------------------
__global__ __launch_bounds__(256)
void gemm_tma_kernel(const __grid_constant__ CUtensorMap mAhi,
                     const __grid_constant__ CUtensorMap mAlo,
                     const __grid_constant__ CUtensorMap mBhi,
                     const __grid_constant__ CUtensorMap mBlo,
                     const __nv_bfloat16* __restrict__ Ahi,
                     const __nv_bfloat16* __restrict__ Alo,
                     const __nv_bfloat16* __restrict__ Bhi,
                     const __nv_bfloat16* __restrict__ Blo,
                     const float* __restrict__ bias,
                     float* __restrict__ Cf,
                     __nv_bfloat16* __restrict__ Chi,
                     __nv_bfloat16* __restrict__ Clo,
                     int M, int N, int K)
{
#if HAS_TCGEN05
    extern __shared__ char dyn[];
    char* tiles = (char*)(((uintptr_t)dyn + 1023) & ~(uintptr_t)1023);
    float*    biass = (float*)(tiles + 196608);
    uint64_t* mbar  = (uint64_t*)(tiles + 196608 + 512);   // [0..2]=tma, [3..5]=mma
    uint32_t* tptr  = (uint32_t*)(tiles + 196608 + 512 + 48);

    const int tid  = threadIdx.x;
    const int wid  = tid >> 5;
    const int lane = tid & 31;
    const int row0 = blockIdx.y << 7, col0 = blockIdx.x << 7;

    const uint32_t tiles_u = su32(tiles);
    const uint32_t mbar_u  = su32(mbar);

    if (tid == 0) {
        #pragma unroll
        for (int i = 0; i < 6; i++) MBAR_INIT(mbar_u + i * 8, 1);
    }
    if (wid == 0) { TC_ALLOC(su32(tptr), 128); TC_RELINQ(); }
    if (tid < 128) biass[tid] = bias[col0 + tid];
    __syncthreads();
    const uint32_t tmem = *tptr;

    const int NS = K >> 6;

    if (tid == 0) {
        auto tma_load = [&](int s) {
            int b = s % 3;
            uint32_t base = tiles_u + b * 65536;
            uint32_t mb   = mbar_u + b * 8;
            MBAR_EXPECT_TX(mb, 65536);
            int x = s << 6;
            tma2d(base,         &mAhi, x, row0, mb);
            tma2d(base + 16384, &mAlo, x, row0, mb);
            tma2d(base + 32768, &mBhi, x, col0, mb);
            tma2d(base + 49152, &mBlo, x, col0, mb);
        };
        auto issue_stage = [&](int s, bool first) {
            uint32_t a0 = tiles_u + (s % 3) * 65536;
            uint64_t dAh = make_desc(a0);
            uint64_t dAl = make_desc(a0 + 16384);
            uint64_t dBh = make_desc(a0 + 32768);
            uint64_t dBl = make_desc(a0 + 49152);
            #pragma unroll
            for (int j = 0; j < 4; j++) {
                mma_bf16_ss(tmem, dAh + j * 2, dBh + j * 2, GEMM_IDESC, !(first && j == 0));
                mma_bf16_ss(tmem, dAh + j * 2, dBl + j * 2, GEMM_IDESC, true);
                mma_bf16_ss(tmem, dAl + j * 2, dBh + j * 2, GEMM_IDESC, true);
            }
            TC_COMMIT(mbar_u + (3 + s % 3) * 8);
        };

        int ptT[3] = {0, 0, 0}, ptM[3] = {0, 0, 0};
        tma_load(0);
        tma_load(1);
        for (int s = 0; s < NS; s++) {
            if (s >= 1) {      // free buffer (s-1)%3 == (s+2)%3
                int b = (s - 1) % 3;
                MBAR_WAIT(mbar_u + (3 + b) * 8, ptM[b]); ptM[b] ^= 1;
            }
            if (s + 2 < NS) tma_load(s + 2);
            {
                int b = s % 3;
                MBAR_WAIT(mbar_u + b * 8, ptT[b]); ptT[b] ^= 1;
            }
            issue_stage(s, s == 0);
        }
        { int b = (NS - 1) % 3; MBAR_WAIT(mbar_u + (3 + b) * 8, ptM[b]); }
    }
    __syncthreads();

    TC_FENCE_AFTER();
    if (tid < 128) {
        const int er = row0 + wid * 32 + lane;
        #pragma unroll
        for (int c0 = 0; c0 < 128; c0 += 32) {
            uint32_t rg[32];
            LDTM_X32(rg, tmem + c0);
            TC_WAIT_LD();
            float v[32];
            #pragma unroll
            for (int j = 0; j < 32; j++)
                v[j] = __uint_as_float(rg[j]) + biass[c0 + j];
            if (Chi) {
                __nv_bfloat16* ph = Chi + (size_t)er * N + col0 + c0;
                __nv_bfloat16* pl = Clo + (size_t)er * N + col0 + c0;
                #pragma unroll
                for (int q = 0; q < 4; q++) {
                    uint4 hh, ll;
                    hh.x = pk_hi(v[8*q+0], v[8*q+1]); ll.x = pk_lo(v[8*q+0], v[8*q+1]);
                    hh.y = pk_hi(v[8*q+2], v[8*q+3]); ll.y = pk_lo(v[8*q+2], v[8*q+3]);
                    hh.z = pk_hi(v[8*q+4], v[8*q+5]); ll.z = pk_lo(v[8*q+4], v[8*q+5]);
                    hh.w = pk_hi(v[8*q+6], v[8*q+7]); ll.w = pk_lo(v[8*q+6], v[8*q+7]);
                    *(uint4*)(ph + 8*q) = hh;
                    *(uint4*)(pl + 8*q) = ll;
                }
            } else {
                float* cp = Cf + (size_t)er * N + col0 + c0;
                #pragma unroll
                for (int j = 0; j < 8; j++) {
                    float4 o;
                    o.x = v[4*j+0]; o.y = v[4*j+1]; o.z = v[4*j+2]; o.w = v[4*j+3];
                    *(float4*)(cp + 4 * j) = o;
                }
            }
        }
    }
    __syncthreads();
    if (wid == 0) TC_DEALLOC(tmem, 128);

#else  // ------- generic fallback (compile-only on this rig) -------
    extern __shared__ char dyn[];
    float* As = (float*)dyn;
    float* Bs = As + 16 * 132;

    const int tid = threadIdx.x;
    const int tx  = tid & 15, ty = tid >> 4;
    const int row0 = blockIdx.y << 7, col0 = blockIdx.x << 7;

    float acc[8][8] = {};
    for (int k0 = 0; k0 < K; k0 += 16) {
        __syncthreads();
        #pragma unroll
        for (int t = 0; t < 2; t++) {
            int ch = tid + (t << 8);
            int rr = ch >> 2, c4 = (ch & 3) << 2;
            size_t ao = (size_t)(row0 + rr) * K + k0 + c4;
            size_t bo = (size_t)(col0 + rr) * K + k0 + c4;
            #pragma unroll
            for (int q = 0; q < 4; q++) {
                As[(c4 + q) * 132 + rr] = __bfloat162float(Ahi[ao + q]) + __bfloat162float(Alo[ao + q]);
                Bs[(c4 + q) * 132 + rr] = __bfloat162float(Bhi[bo + q]) + __bfloat162float(Blo[bo + q]);
            }
        }
        __syncthreads();
        #pragma unroll
        for (int kk = 0; kk < 16; kk++) {
            float a[8], b[8];
            #pragma unroll
            for (int i = 0; i < 8; i++) a[i] = As[kk * 132 + ty * 8 + i];
            #pragma unroll
            for (int j = 0; j < 8; j++) b[j] = Bs[kk * 132 + tx * 8 + j];
            #pragma unroll
            for (int i = 0; i < 8; i++)
                #pragma unroll
                for (int j = 0; j < 8; j++) acc[i][j] += a[i] * b[j];
        }
    }
    #pragma unroll
    for (int i = 0; i < 8; i++)
        #pragma unroll
        for (int j = 0; j < 8; j++) {
            float v = acc[i][j] + bias[col0 + tx * 8 + j];
            size_t o = (size_t)(row0 + ty * 8 + i) * N + col0 + tx * 8 + j;
            if (Chi) {
                __nv_bfloat16 hb = __float2bfloat16_rn(v);
                Chi[o] = hb;
                Clo[o] = __float2bfloat16_rn(v - __bfloat162float(hb));
            } else {
                Cf[o] = v;
            }
        }
#endif
}

// ---------------------------------------------------------------------------
// Attention, bf16x2 tcgen05, static softmax base (m=0). CTA = (b,h,128-q tile).
// (unchanged from R10)
// ---------------------------------------------------------------------------
#define AS_QHI  0
#define AS_QLO  16384
#define AS_KHI  32768
#define AS_KLO  49152
#define AS_VHI  65536
#define AS_VLO  81920
#define AS_PSUM 98304
#define AS_RED  99328
#define AS_MBAR 99840
#define AS_TPTR 99856
#define ATTN_SMEM_BYTES (1024 + 99872)

#define TM_S    0
#define TM_PHI  128
#define TM_PLO  192

__global__ __launch_bounds__(256, 2) void attn_tc_kernel()
{
#if HAS_TCGEN05
    extern __shared__ char dyn[];
    char* smc = (char*)(((uintptr_t)dyn + 1023) & ~(uintptr_t)1023);
    const uint32_t smu = su32(smc);

    const int tid  = threadIdx.x;
    const int wid  = tid >> 5;
    const int lane = tid & 31;
    const int sp   = wid & 3;
    const int half = wid >> 2;
    const int qb   = (gridDim.x - 1) - blockIdx.x;   // big tiles first
    const int h = blockIdx.y, b = blockIdx.z;
    const int q0   = qb << 7;
    const int r    = sp * 32 + lane;

    const size_t hbase = (size_t)b * SEQ * QLD + h * (3 * HD);
    const __nv_bfloat16* qh = g_qkv_hi + hbase;
    const __nv_bfloat16* ql = g_qkv_lo + hbase;
    const __nv_bfloat16* kh = qh + HD;
    const __nv_bfloat16* kl = ql + HD;
    const __nv_bfloat16* vh = qh + 2 * HD;
    const __nv_bfloat16* vl = ql + 2 * HD;

    float* psums = (float*)(smc + AS_PSUM);
    float* red   = (float*)(smc + AS_RED);
    const uint32_t mb1 = smu + AS_MBAR;
    const uint32_t mb2 = smu + AS_MBAR + 8;

    if (tid == 0) { MBAR_INIT(mb1, 1); MBAR_INIT(mb2, 1); }
    if (wid == 0) { TC_ALLOC(smu + AS_TPTR, 256); TC_RELINQ(); }
    __syncthreads();
    const uint32_t tmem = *(uint32_t*)(smc + AS_TPTR);
    const uint32_t warpoff = (uint32_t)sp << 21;

    const float C = 0.125f * 1.44269504f;

    // ---- Load Q (cp.async, coalesced) ----
    #pragma unroll
    for (int i = 0; i < 4; i++) {
        int cg  = tid + (i << 8);
        int row = cg >> 3, ch = cg & 7;
        uint32_t sw = SMEM_SWZ((uint32_t)(row * 128 + ch * 16));
        size_t off = (size_t)(q0 + row) * QLD + (ch << 3);
        cp16(smu + AS_QHI + sw, qh + off);
        cp16(smu + AS_QLO + sw, ql + off);
    }
    CP_COMMIT();

    float O[32];
    #pragma unroll
    for (int i = 0; i < 32; i++) O[i] = 0.0f;
    float l_run = 0.0f;
    int pt1 = 0, pt2 = 0;

    const int vp_p  = tid & 63;
    const int vp_dh = tid >> 6;
    const int vp_panel = vp_p >> 5;
    const int vp_pc    = vp_p & 31;

    for (int kb = 0; kb <= qb; kb++) {
        const int k0 = kb << 7;
        __syncthreads();

        // ---- Load K (cp.async) ----
        #pragma unroll
        for (int i = 0; i < 4; i++) {
            int cg  = tid + (i << 8);
            int row = cg >> 3, ch = cg & 7;
            uint32_t sw = SMEM_SWZ((uint32_t)(row * 128 + ch * 16));
            size_t off = (size_t)(k0 + row) * QLD + (ch << 3);
            cp16(smu + AS_KHI + sw, kh + off);
            cp16(smu + AS_KLO + sw, kl + off);
        }
        CP_COMMIT();

        // ---- Load V transposed (PRMT-pack) ----
        {
            const size_t e_off = (size_t)(k0 + 2 * vp_p) * QLD + (vp_dh << 4);
            const size_t o_off = e_off + QLD;
            uint32_t E[8], Od[8], El[8], Ol[8];
            *(uint4*)&E[0]  = *(const uint4*)(vh + e_off);
            *(uint4*)&E[4]  = *(const uint4*)(vh + e_off + 8);
            *(uint4*)&Od[0] = *(const uint4*)(vh + o_off);
            *(uint4*)&Od[4] = *(const uint4*)(vh + o_off + 8);
            *(uint4*)&El[0] = *(const uint4*)(vl + e_off);
            *(uint4*)&El[4] = *(const uint4*)(vl + e_off + 8);
            *(uint4*)&Ol[0] = *(const uint4*)(vl + o_off);
            *(uint4*)&Ol[4] = *(const uint4*)(vl + o_off + 8);
            #pragma unroll
            for (int j = 0; j < 8; j++) {
                int d = (vp_dh << 4) + 2 * j;
                uint32_t w0h = __byte_perm(E[j],  Od[j], 0x5410);
                uint32_t w1h = __byte_perm(E[j],  Od[j], 0x7632);
                uint32_t w0l = __byte_perm(El[j], Ol[j], 0x5410);
                uint32_t w1l = __byte_perm(El[j], Ol[j], 0x7632);
                uint32_t off0 = SMEM_SWZ((uint32_t)(d * 128 + vp_pc * 4));
                uint32_t off1 = SMEM_SWZ((uint32_t)((d + 1) * 128 + vp_pc * 4));
                *(uint32_t*)(smc + AS_VHI + vp_panel * 8192 + off0) = w0h;
                *(uint32_t*)(smc + AS_VHI + vp_panel * 8192 + off1) = w1h;
                *(uint32_t*)(smc + AS_VLO + vp_panel * 8192 + off0) = w0l;
                *(uint32_t*)(smc + AS_VLO + vp_panel * 8192 + off1) = w1l;
            }
        }
        CP_WAIT0();
        FENCE_ASYNC();
        __syncthreads();

        // ---- MMA1: S = Q @ K^T ----
        if (wid == 0) {
            TC_FENCE_AFTER();
            if (elect1()) {
                uint64_t dQh = make_desc(smu + AS_QHI);
                uint64_t dQl = make_desc(smu + AS_QLO);
                uint64_t dKh = make_desc(smu + AS_KHI);
                uint64_t dKl = make_desc(smu + AS_KLO);
                bool first = true;
                #pragma unroll
                for (int j = 0; j < 4; j++) {
                    mma_bf16_ss(tmem + TM_S, dQh + j * 2, dKh + j * 2, ATTN_IDESC1, !first);
                    first = false;
                    mma_bf16_ss(tmem + TM_S, dQh + j * 2, dKl + j * 2, ATTN_IDESC1, true);
                    mma_bf16_ss(tmem + TM_S, dQl + j * 2, dKh + j * 2, ATTN_IDESC1, true);
                }
                TC_COMMIT(mb1);
            }
        }
        MBAR_WAIT(mb1, pt1); pt1 ^= 1;
        TC_FENCE_AFTER();

        // ---- Softmax (single pass, m=0) ----
        const int qg = q0 + r;
        float ps = 0.0f;
        #pragma unroll
        for (int c = 0; c < 2; c++) {
            uint32_t u[32];
            LDTM_X32(u, tmem + TM_S + half * 64 + c * 32);
            TC_WAIT_LD();
            const int cb = k0 + half * 64 + c * 32;
            float p[32];
            #pragma unroll
            for (int j = 0; j < 32; j++) {
                float e = exp2f(__uint_as_float(u[j]) * C);
                if (kb == qb && cb + j > qg) e = 0.0f;
                p[j] = e;
                ps += e;
            }
            uint32_t hw[16], lw[16];
            #pragma unroll
            for (int j = 0; j < 16; j++) {
                hw[j] = pk_hi(p[2 * j], p[2 * j + 1]);
                lw[j] = pk_lo(p[2 * j], p[2 * j + 1]);
            }
            STTM_X16(tmem + TM_PHI + half * 32 + c * 16 + warpoff, hw);
            STTM_X16(tmem + TM_PLO + half * 32 + c * 16 + warpoff, lw);
        }
        psums[r * 2 + half] = ps;
        TC_WAIT_ST();
        TC_FENCE_BEFORE();
        __syncthreads();

        if (half == 0)
            l_run += psums[r * 2] + psums[r * 2 + 1];

        // ---- MMA2: U = P @ Vt^T ----
        if (wid == 0) {
            TC_FENCE_AFTER();
            if (elect1()) {
                bool first = true;
                #pragma unroll
                for (int panel = 0; panel < 2; panel++) {
                    uint64_t dVh = make_desc(smu + AS_VHI + panel * 8192);
                    uint64_t dVl = make_desc(smu + AS_VLO + panel * 8192);
                    #pragma unroll
                    for (int j = 0; j < 4; j++) {
                        uint32_t acol = panel * 32 + j * 8;
                        mma_bf16_ts(tmem + TM_S, tmem + TM_PHI + acol, dVh + j * 2, ATTN_IDESC2, !first);
                        first = false;
                        mma_bf16_ts(tmem + TM_S, tmem + TM_PHI + acol, dVl + j * 2, ATTN_IDESC2, true);
                        mma_bf16_ts(tmem + TM_S, tmem + TM_PLO + acol, dVh + j * 2, ATTN_IDESC2, true);
                    }
                }
                TC_COMMIT(mb2);
            }
        }
        MBAR_WAIT(mb2, pt2); pt2 ^= 1;
        TC_FENCE_AFTER();

        // ---- O += U ----
        {
            uint32_t u[32];
            LDTM_X32(u, tmem + TM_S + half * 32);
            TC_WAIT_LD();
            #pragma unroll
            for (int j = 0; j < 32; j++)
                O[j] += __uint_as_float(u[j]);
        }
        TC_FENCE_BEFORE();
    }

    // ---- Epilogue: write val bf16 hi/lo ----
    if (half == 0) red[r] = 1.0f / l_run;
    __syncthreads();
    {
        const float inv = red[r];
        const size_t vo = ((size_t)b * SEQ + q0 + r) * DM + h * HD + half * 32;
        float v[32];
        #pragma unroll
        for (int c = 0; c < 32; c++) v[c] = O[c] * inv;
        uint4 hh, ll;
        #pragma unroll
        for (int q = 0; q < 4; q++) {
            hh.x = pk_hi(v[8*q+0], v[8*q+1]); ll.x = pk_lo(v[8*q+0], v[8*q+1]);
            hh.y = pk_hi(v[8*q+2], v[8*q+3]); ll.y = pk_lo(v[8*q+2], v[8*q+3]);
            hh.z = pk_hi(v[8*q+4], v[8*q+5]); ll.z = pk_lo(v[8*q+4], v[8*q+5]);
            hh.w = pk_hi(v[8*q+6], v[8*q+7]); ll.w = pk_lo(v[8*q+6], v[8*q+7]);
            *(uint4*)(g_val_hi + vo + 8*q) = hh;
            *(uint4*)(g_val_lo + vo + 8*q) = ll;
        }
    }
    __syncthreads();
    if (wid == 0) TC_DEALLOC(tmem, 256);

#else  // ------- generic fallback (compile-only on this rig) -------
    extern __shared__ float sm[];
    float* Qs = sm;
    float* Ks = sm + 64 * 68;
    float* Vs = sm + 2 * 64 * 68;
    float* Ps = sm + 3 * 64 * 68;

    const int tid = threadIdx.x;
    const int tx  = tid & 15, ty = tid >> 4;
    const int h = blockIdx.y, b = blockIdx.z;

    const size_t hbase = (size_t)b * SEQ * QLD + h * (3 * HD);

    for (int sub = 0; sub < 2; sub++) {
        const int q0 = (blockIdx.x << 7) + (sub << 6);
        __syncthreads();
        for (int idx = tid; idx < 64 * 64; idx += 256) {
            int rr = idx >> 6, d = idx & 63;
            size_t o = hbase + (size_t)(q0 + rr) * QLD + d;
            Qs[d * 68 + rr] = (__bfloat162float(g_qkv_hi[o]) + __bfloat162float(g_qkv_lo[o])) * 0.125f;
        }

        float m_i[4] = {-3e38f, -3e38f, -3e38f, -3e38f};
        float l_i[4] = {};
        float acc[4][4] = {};
        const int nkb = (q0 >> 6) + 1;

        for (int kb = 0; kb < nkb; kb++) {
            const int k0 = kb << 6;
            __syncthreads();
            for (int idx = tid; idx < 64 * 64; idx += 256) {
                int c = idx >> 6, d = idx & 63;
                size_t ko = hbase + (size_t)(k0 + c) * QLD + HD + d;
                size_t vo = ko + HD;
                Ks[d * 68 + c] = __bfloat162float(g_qkv_hi[ko]) + __bfloat162float(g_qkv_lo[ko]);
                Vs[c * 68 + d] = __bfloat162float(g_qkv_hi[vo]) + __bfloat162float(g_qkv_lo[vo]);
            }
            __syncthreads();

            float s[4][4] = {};
            for (int d = 0; d < 64; d++) {
                float a0 = Qs[d*68+(ty<<2)], a1 = Qs[d*68+(ty<<2)+1];
                float a2 = Qs[d*68+(ty<<2)+2], a3 = Qs[d*68+(ty<<2)+3];
                float b0 = Ks[d*68+(tx<<2)], b1 = Ks[d*68+(tx<<2)+1];
                float b2 = Ks[d*68+(tx<<2)+2], b3 = Ks[d*68+(tx<<2)+3];
                s[0][0]+=a0*b0; s[0][1]+=a0*b1; s[0][2]+=a0*b2; s[0][3]+=a0*b3;
                s[1][0]+=a1*b0; s[1][1]+=a1*b1; s[1][2]+=a1*b2; s[1][3]+=a1*b3;
                s[2][0]+=a2*b0; s[2][1]+=a2*b1; s[2][2]+=a2*b2; s[2][3]+=a2*b3;
                s[3][0]+=a3*b0; s[3][1]+=a3*b1; s[3][2]+=a3*b2; s[3][3]+=a3*b3;
            }
            if (kb == nkb - 1)
                for (int i = 0; i < 4; i++)
                    for (int j = 0; j < 4; j++)
                        if ((tx<<2)+j > (ty<<2)+i) s[i][j] = -1e9f;
            for (int i = 0; i < 4; i++) {
                float mx = fmaxf(fmaxf(s[i][0], s[i][1]), fmaxf(s[i][2], s[i][3]));
                for (int off = 8; off > 0; off >>= 1)
                    mx = fmaxf(mx, __shfl_xor_sync(0xffffffffu, mx, off, 16));
                float mnew = fmaxf(m_i[i], mx);
                float p0 = __expf(s[i][0]-mnew), p1 = __expf(s[i][1]-mnew);
                float p2 = __expf(s[i][2]-mnew), p3 = __expf(s[i][3]-mnew);
                float ls = p0+p1+p2+p3;
                for (int off = 8; off > 0; off >>= 1)
                    ls += __shfl_xor_sync(0xffffffffu, ls, off, 16);
                float alpha = __expf(m_i[i] - mnew);
                l_i[i] = l_i[i]*alpha + ls;
                m_i[i] = mnew;
                acc[i][0]*=alpha; acc[i][1]*=alpha; acc[i][2]*=alpha; acc[i][3]*=alpha;
                s[i][0]=p0; s[i][1]=p1; s[i][2]=p2; s[i][3]=p3;
            }
            for (int i = 0; i < 4; i++)
                for (int j = 0; j < 4; j++)
                    Ps[((tx<<2)+j)*68 + (ty<<2)+i] = s[i][j];
            __syncthreads();
            for (int c = 0; c < 64; c++) {
                float a0 = Ps[c*68+(ty<<2)], a1 = Ps[c*68+(ty<<2)+1];
                float a2 = Ps[c*68+(ty<<2)+2], a3 = Ps[c*68+(ty<<2)+3];
                float b0 = Vs[c*68+(tx<<2)], b1 = Vs[c*68+(tx<<2)+1];
                float b2 = Vs[c*68+(tx<<2)+2], b3 = Vs[c*68+(tx<<2)+3];
                acc[0][0]+=a0*b0; acc[0][1]+=a0*b1; acc[0][2]+=a0*b2; acc[0][3]+=a0*b3;
                acc[1][0]+=a1*b0; acc[1][1]+=a1*b1; acc[1][2]+=a1*b2; acc[1][3]+=a1*b3;
                acc[2][0]+=a2*b0; acc[2][1]+=a2*b1; acc[2][2]+=a2*b2; acc[2][3]+=a2*b3;
                acc[3][0]+=a3*b0; acc[3][1]+=a3*b1; acc[3][2]+=a3*b2; acc[3][3]+=a3*b3;
            }
        }
        for (int i = 0; i < 4; i++) {
            float inv = 1.0f / l_i[i];
            for (int j = 0; j < 4; j++) {
                float v = acc[i][j] * inv;
                size_t o = ((size_t)b * SEQ + q0 + (ty<<2)+i) * DM + h * HD + (tx<<2)+j;
                __nv_bfloat16 hb = __float2bfloat16_rn(v);
                g_val_hi[o] = hb;
                g_val_lo[o] = __float2bfloat16_rn(v - __bfloat162float(hb));
            }
        }
        __syncthreads();
    }
#endif
}

// ---------------------------------------------------------------------------
// Host: tensormap creation via driver entry point (no -lcuda needed)
// ---------------------------------------------------------------------------
typedef CUresult (*PFN_encodeTiled)(CUtensorMap*, CUtensorMapDataType, cuuint32_t, void*,
    const cuuint64_t*, const cuuint64_t*, const cuuint32_t*, const cuuint32_t*,
    CUtensorMapInterleave, CUtensorMapSwizzle, CUtensorMapL2promotion, CUtensorMapFloatOOBfill);

static PFN_encodeTiled get_encode_fn() {
    static PFN_encodeTiled fn = nullptr;
    if (!fn) {
        void* p = nullptr;
        cudaDriverEntryPointQueryResult qr;
        cudaGetDriverEntryPoint("cuTensorMapEncodeTiled", &p, cudaEnableDefault, &qr);
        fn = (PFN_encodeTiled)p;
    }
    return fn;
}

static CUtensorMap mk_map(void* ptr, uint64_t Kdim, uint64_t rows) {
    CUtensorMap m;
    memset(&m, 0, sizeof(m));
    cuuint64_t dims[2] = {Kdim, rows};
    cuuint64_t str[1]  = {Kdim * 2};         // row stride in bytes (bf16)
    cuuint32_t box[2]  = {64, 128};          // 64 bf16 = 128B inner (SW128 limit)
    cuuint32_t es[2]   = {1, 1};
    get_encode_fn()(&m, CU_TENSOR_MAP_DATA_TYPE_BFLOAT16, 2, ptr, dims, str, box, es,
                    CU_TENSOR_MAP_INTERLEAVE_NONE, CU_TENSOR_MAP_SWIZZLE_128B,
                    CU_TENSOR_MAP_L2_PROMOTION_L2_128B, CU_TENSOR_MAP_FLOAT_OOB_FILL_NONE);
    return m;
}

// ---------------------------------------------------------------------------
// Launch
// ---------------------------------------------------------------------------
extern "C" void kernel_launch(void* const* d_in, const int* in_sizes, int n_in,
                              void* d_out, int out_size)
{
    const float* x    = (const float*)d_in[0];
    const float* Wqkv = (const float*)d_in[1];
    const float* bqkv = (const float*)d_in[2];
    const float* Wout = (const float*)d_in[3];
    const float* bout = (const float*)d_in[4];
    float* out = (float*)d_out;

    __nv_bfloat16 *x_hi, *x_lo, *qkv_hi, *qkv_lo, *val_hi, *val_lo;
    __nv_bfloat16 *wq_hi, *wq_lo, *wo_hi, *wo_lo;
    cudaGetSymbolAddress((void**)&x_hi,   g_x_hi);
    cudaGetSymbolAddress((void**)&x_lo,   g_x_lo);
    cudaGetSymbolAddress((void**)&qkv_hi, g_qkv_hi);
    cudaGetSymbolAddress((void**)&qkv_lo, g_qkv_lo);
    cudaGetSymbolAddress((void**)&val_hi, g_val_hi);
    cudaGetSymbolAddress((void**)&val_lo, g_val_lo);
    cudaGetSymbolAddress((void**)&wq_hi,  g_wqkvT_hi);
    cudaGetSymbolAddress((void**)&wq_lo,  g_wqkvT_lo);
    cudaGetSymbolAddress((void**)&wo_hi,  g_woutT_hi);
    cudaGetSymbolAddress((void**)&wo_lo,  g_woutT_lo);

    const int gemm_smem = 1024 + 196608 + 512 + 64;
    const int attn_smem = ATTN_SMEM_BYTES;
    cudaFuncSetAttribute(gemm_tma_kernel,
                         cudaFuncAttributeMaxDynamicSharedMemorySize, gemm_smem);
    cudaFuncSetAttribute(attn_tc_kernel,
                         cudaFuncAttributeMaxDynamicSharedMemorySize, attn_smem);

    // Tensormaps (host-side, once per capture)
    CUtensorMap mXh  = mk_map(x_hi,   DM, BSROWS);
    CUtensorMap mXl  = mk_map(x_lo,   DM, BSROWS);
    CUtensorMap mWqh = mk_map(wq_hi,  DM, QLD);
    CUtensorMap mWql = mk_map(wq_lo,  DM, QLD);
    CUtensorMap mVh  = mk_map(val_hi, DM, BSROWS);
    CUtensorMap mVl  = mk_map(val_lo, DM, BSROWS);
    CUtensorMap mWoh = mk_map(wo_hi,  DM, DM);
    CUtensorMap mWol = mk_map(wo_lo,  DM, DM);

    // Preludes
    split_f32_kernel<<<(BSROWS * DM) / (256 * 8), 256>>>(x, x_hi, x_lo);
    transpose_split_kernel<<<dim3(QLD / 32, DM / 32), dim3(32, 8)>>>(Wqkv, wq_hi, wq_lo, DM, QLD);
    transpose_split_kernel<<<dim3(DM / 32, DM / 32), dim3(32, 8)>>>(Wout, wo_hi, wo_lo, DM, DM);

    // QKV projection -> bf16 hi/lo qkv
    gemm_tma_kernel<<<dim3(QLD / 128, BSROWS / 128), 256, gemm_smem>>>(
        mXh, mXl, mWqh, mWql, x_hi, x_lo, wq_hi, wq_lo,
        bqkv, nullptr, qkv_hi, qkv_lo, BSROWS, QLD, DM);

    // Attention -> bf16 hi/lo val
    attn_tc_kernel<<<dim3(SEQ / 128, NH, BATCH), 256, attn_smem>>>();

    // Output projection -> fp32 out
    gemm_tma_kernel<<<dim3(DM / 128, BSROWS / 128), 256, gemm_smem>>>(
        mVh, mVl, mWoh, mWol, val_hi, val_lo, wo_hi, wo_lo,
        bout, out, nullptr, nullptr, BSROWS, DM, DM);
}

// round 12
// speedup vs baseline: 1.0059x; 1.0059x over previous
#include <cuda_runtime.h>
#include <cuda.h>
#include <cuda_bf16.h>
#include <cstdint>
#include <cstring>
#include <math.h>

#define SEQ   2048
#define BATCH 2
#define DM    1024
#define NH    16
#define HD    64
#define BSROWS (BATCH*SEQ)   // 4096
#define QLD   (3*DM)         // 3072

#if defined(__CUDA_ARCH_FEAT_SM103_ALL) || defined(__CUDA_ARCH_FEAT_SM100_ALL) || \
    (defined(__CUDA_ARCH_SPECIFIC__) && (__CUDA_ARCH_SPECIFIC__ >= 1000))
#define HAS_TCGEN05 1
#else
#define HAS_TCGEN05 0
#endif

// ---------------------------------------------------------------------------
// Scratch: everything mid-pipeline is bf16 hi/lo
// ---------------------------------------------------------------------------
__device__ __nv_bfloat16 g_x_hi[(size_t)BSROWS * DM];
__device__ __nv_bfloat16 g_x_lo[(size_t)BSROWS * DM];
__device__ __nv_bfloat16 g_qkv_hi[(size_t)BSROWS * QLD];
__device__ __nv_bfloat16 g_qkv_lo[(size_t)BSROWS * QLD];
__device__ __nv_bfloat16 g_val_hi[(size_t)BSROWS * DM];
__device__ __nv_bfloat16 g_val_lo[(size_t)BSROWS * DM];
__device__ __nv_bfloat16 g_wqkvT_hi[(size_t)QLD * DM];
__device__ __nv_bfloat16 g_wqkvT_lo[(size_t)QLD * DM];
__device__ __nv_bfloat16 g_woutT_hi[(size_t)DM * DM];
__device__ __nv_bfloat16 g_woutT_lo[(size_t)DM * DM];

// ---------------------------------------------------------------------------
// Generic helpers
// ---------------------------------------------------------------------------
__device__ __forceinline__ uint32_t su32(const void* p) {
    return (uint32_t)__cvta_generic_to_shared(p);
}
__device__ __forceinline__ uint32_t pk_hi(float a, float b) {
    __nv_bfloat162 t = __floats2bfloat162_rn(a, b);
    return *(uint32_t*)&t;
}
__device__ __forceinline__ uint32_t pk_lo(float a, float b) {
    float ah = __bfloat162float(__float2bfloat16_rn(a));
    float bh = __bfloat162float(__float2bfloat16_rn(b));
    __nv_bfloat162 t = __floats2bfloat162_rn(a - ah, b - bh);
    return *(uint32_t*)&t;
}
#define SMEM_SWZ(off) ((off) ^ (((off) >> 3) & 0x70))

// cp.async (sm_80+) — still used by attention
__device__ __forceinline__ void cp16(uint32_t dst, const void* src) {
    asm volatile("cp.async.cg.shared.global [%0], [%1], 16;" :: "r"(dst), "l"(src) : "memory");
}
#define CP_COMMIT() asm volatile("cp.async.commit_group;" ::: "memory")
#define CP_WAIT0()  asm volatile("cp.async.wait_group 0;" ::: "memory")

#if HAS_TCGEN05
__device__ __forceinline__ bool elect1() {
    uint32_t r;
    asm volatile("{\n\t.reg .pred p;\n\telect.sync _|p, 0xFFFFFFFF;\n\tselp.b32 %0, 1, 0, p;\n\t}" : "=r"(r));
    return r != 0;
}
#define MBAR_INIT(addr, cnt) \
    asm volatile("mbarrier.init.shared.b64 [%0], %1;" :: "r"(addr), "r"(cnt) : "memory")
#define MBAR_EXPECT_TX(addr, tx) \
    asm volatile("mbarrier.arrive.expect_tx.shared.b64 _, [%0], %1;" :: "r"(addr), "r"(tx) : "memory")
#define MBAR_WAIT(addr, ph) do {                                              \
    uint32_t _m = (addr), _p = (ph), _d;                                      \
    asm volatile("{\n\t.reg .pred p;\n\t"                                     \
        "mbarrier.try_wait.parity.acquire.cta.shared::cta.b64 p, [%1], %2;\n\t" \
        "selp.b32 %0, 1, 0, p;\n\t}" : "=r"(_d) : "r"(_m), "r"(_p) : "memory"); \
    if (!_d) {                                                                \
        asm volatile("{\n\t.reg .pred P1;\n\t"                                \
            "WL_%=:\n\t"                                                      \
            "mbarrier.try_wait.parity.acquire.cta.shared::cta.b64 P1, [%0], %1, 0x989680;\n\t" \
            "@P1 bra.uni WD_%=;\n\tbra.uni WL_%=;\n\tWD_%=:\n\t}"             \
            :: "r"(_m), "r"(_p) : "memory");                                  \
    }                                                                         \
} while (0)
#define TC_ALLOC(smem_addr, ncols) \
    asm volatile("tcgen05.alloc.cta_group::1.sync.aligned.shared::cta.b32 [%0], %1;" \
                 :: "r"(smem_addr), "r"(ncols) : "memory")
#define TC_RELINQ() \
    asm volatile("tcgen05.relinquish_alloc_permit.cta_group::1.sync.aligned;")
#define TC_DEALLOC(tmem, ncols) \
    asm volatile("tcgen05.dealloc.cta_group::1.sync.aligned.b32 %0, %1;" :: "r"(tmem), "r"(ncols))
#define TC_COMMIT(mbar) \
    asm volatile("tcgen05.commit.cta_group::1.mbarrier::arrive::one.shared::cluster.b64 [%0];" \
                 :: "r"(mbar) : "memory")
#define TC_FENCE_AFTER()  asm volatile("tcgen05.fence::after_thread_sync;" ::: "memory")
#define TC_FENCE_BEFORE() asm volatile("tcgen05.fence::before_thread_sync;" ::: "memory")
#define TC_WAIT_LD()      asm volatile("tcgen05.wait::ld.sync.aligned;" ::: "memory")
#define TC_WAIT_ST()      asm volatile("tcgen05.wait::st.sync.aligned;" ::: "memory")
#define FENCE_ASYNC()     asm volatile("fence.proxy.async.shared::cta;" ::: "memory")

// 2D TMA load (global -> shared::cta), single thread
__device__ __forceinline__ void tma2d(uint32_t smem, const CUtensorMap* m,
                                      int x, int y, uint32_t mbar) {
    asm volatile(
        "cp.async.bulk.tensor.2d.shared::cta.global.tile.mbarrier::complete_tx::bytes "
        "[%0], [%1, {%2, %3}], [%4];"
        :: "r"(smem), "l"(m), "r"(x), "r"(y), "r"(mbar) : "memory");
}

#define LDTM_X32(r, a) \
    asm volatile("tcgen05.ld.sync.aligned.32x32b.x32.b32 "                    \
        "{%0, %1, %2, %3, %4, %5, %6, %7, %8, %9, %10, %11, %12, %13, %14, %15, " \
        " %16, %17, %18, %19, %20, %21, %22, %23, %24, %25, %26, %27, %28, %29, %30, %31}, [%32];" \
        : "=r"((r)[0]),  "=r"((r)[1]),  "=r"((r)[2]),  "=r"((r)[3]),          \
          "=r"((r)[4]),  "=r"((r)[5]),  "=r"((r)[6]),  "=r"((r)[7]),          \
          "=r"((r)[8]),  "=r"((r)[9]),  "=r"((r)[10]), "=r"((r)[11]),         \
          "=r"((r)[12]), "=r"((r)[13]), "=r"((r)[14]), "=r"((r)[15]),         \
          "=r"((r)[16]), "=r"((r)[17]), "=r"((r)[18]), "=r"((r)[19]),         \
          "=r"((r)[20]), "=r"((r)[21]), "=r"((r)[22]), "=r"((r)[23]),         \
          "=r"((r)[24]), "=r"((r)[25]), "=r"((r)[26]), "=r"((r)[27]),         \
          "=r"((r)[28]), "=r"((r)[29]), "=r"((r)[30]), "=r"((r)[31])          \
        : "r"(a))

#define STTM_X16(a, r) \
    asm volatile("tcgen05.st.sync.aligned.32x32b.x16.b32 [%0], "              \
        "{%1, %2, %3, %4, %5, %6, %7, %8, %9, %10, %11, %12, %13, %14, %15, %16};" \
        :: "r"(a),                                                            \
           "r"((r)[0]),  "r"((r)[1]),  "r"((r)[2]),  "r"((r)[3]),             \
           "r"((r)[4]),  "r"((r)[5]),  "r"((r)[6]),  "r"((r)[7]),             \
           "r"((r)[8]),  "r"((r)[9]),  "r"((r)[10]), "r"((r)[11]),            \
           "r"((r)[12]), "r"((r)[13]), "r"((r)[14]), "r"((r)[15])             \
        : "memory")

// K-major SW128 desc (128B rows): SBO=64, LBO=1
static __device__ __forceinline__ uint64_t make_desc(uint32_t addr) {
    const uint64_t base = (uint64_t(2) << 61) | (uint64_t(1) << 46)
                        | (uint64_t(64) << 32) | (uint64_t(1) << 16);
    return base | ((uint64_t)(addr >> 4) & 0x3FFF);
}
__device__ __forceinline__ void mma_bf16_ss(uint32_t d, uint64_t ad, uint64_t bd,
                                            uint32_t idesc, bool acc) {
    uint32_t en = acc ? 1u : 0u;
    asm volatile(
        "{\n\t.reg .pred p;\n\tsetp.ne.u32 p, %4, 0;\n\t"
        "tcgen05.mma.cta_group::1.kind::f16 [%0], %1, %2, %3, {%5, %5, %5, %5}, p;\n\t}"
        :: "r"(d), "l"(ad), "l"(bd), "r"(idesc), "r"(en), "r"(0u) : "memory");
}
__device__ __forceinline__ void mma_bf16_ts(uint32_t d, uint32_t a, uint64_t bd,
                                            uint32_t idesc, bool acc) {
    uint32_t en = acc ? 1u : 0u;
    asm volatile(
        "{\n\t.reg .pred p;\n\tsetp.ne.u32 p, %4, 0;\n\t"
        "tcgen05.mma.cta_group::1.kind::f16 [%0], [%1], %2, %3, {%5, %5, %5, %5}, p;\n\t}"
        :: "r"(d), "r"(a), "l"(bd), "r"(idesc), "r"(en), "r"(0u) : "memory");
}
#define GEMM_IDESC  ((1u << 4) | (1u << 7) | (1u << 10) | (16u << 17) | (8u << 24))  // M128 N128
#define ATTN_IDESC1 ((1u << 4) | (1u << 7) | (1u << 10) | (16u << 17) | (8u << 24))  // M128 N128
#define ATTN_IDESC2 ((1u << 4) | (1u << 7) | (1u << 10) | (8u  << 17) | (8u << 24))  // M128 N64
#endif  // HAS_TCGEN05

// ---------------------------------------------------------------------------
// Elementwise split: fp32 -> bf16 hi/lo (8 elems/thread)
// ---------------------------------------------------------------------------
__global__ __launch_bounds__(256) void split_f32_kernel(
    const float* __restrict__ X, __nv_bfloat16* __restrict__ Xhi,
    __nv_bfloat16* __restrict__ Xlo)
{
    const size_t i = ((size_t)blockIdx.x * 256 + threadIdx.x) * 8;
    float4 a = *(const float4*)(X + i);
    float4 b = *(const float4*)(X + i + 4);
    uint4 h, l;
    h.x = pk_hi(a.x, a.y); h.y = pk_hi(a.z, a.w);
    h.z = pk_hi(b.x, b.y); h.w = pk_hi(b.z, b.w);
    l.x = pk_lo(a.x, a.y); l.y = pk_lo(a.z, a.w);
    l.z = pk_lo(b.x, b.y); l.w = pk_lo(b.z, b.w);
    *(uint4*)(Xhi + i) = h;
    *(uint4*)(Xlo + i) = l;
}

// ---------------------------------------------------------------------------
// Transpose + bf16 hi/lo split: W[K,N] -> Thi/Tlo[N,K]
// ---------------------------------------------------------------------------
__global__ __launch_bounds__(256) void transpose_split_kernel(
    const float* __restrict__ W, __nv_bfloat16* __restrict__ Thi,
    __nv_bfloat16* __restrict__ Tlo, int K, int N)
{
    __shared__ float t[32][33];
    const int n0 = blockIdx.x << 5, k0 = blockIdx.y << 5;
    const int x = threadIdx.x, y = threadIdx.y;
    #pragma unroll
    for (int i = y; i < 32; i += 8)
        t[i][x] = W[(size_t)(k0 + i) * N + n0 + x];
    __syncthreads();
    #pragma unroll
    for (int i = y; i < 32; i += 8) {
        float v  = t[x][i];
        __nv_bfloat16 hb = __float2bfloat16_rn(v);
        size_t o = (size_t)(n0 + i) * K + k0 + x;
        Thi[o] = hb;
        Tlo[o] = __float2bfloat16_rn(v - __bfloat162float(hb));
    }
}

// ---------------------------------------------------------------------------
// GEMM via TMA: C = A[M,K] @ Bt[N,K]^T + bias, pre-split bf16 operands.
// 128x128 tile, BK=64, 3 buffers. Thread 0 drives; MMA(s) is issued BEFORE
// waiting on MMA(s-1), keeping 2 stages in the tensor queue (R11 fix).
// ---------------------------------------------------------------------------
__global__ __launch_bounds__(256)
void gemm_tma_kernel(const __grid_constant__ CUtensorMap mAhi,
                     const __grid_constant__ CUtensorMap mAlo,
                     const __grid_constant__ CUtensorMap mBhi,
                     const __grid_constant__ CUtensorMap mBlo,
                     const __nv_bfloat16* __restrict__ Ahi,
                     const __nv_bfloat16* __restrict__ Alo,
                     const __nv_bfloat16* __restrict__ Bhi,
                     const __nv_bfloat16* __restrict__ Blo,
                     const float* __restrict__ bias,
                     float* __restrict__ Cf,
                     __nv_bfloat16* __restrict__ Chi,
                     __nv_bfloat16* __restrict__ Clo,
                     int M, int N, int K)
{
#if HAS_TCGEN05
    extern __shared__ char dyn[];
    char* tiles = (char*)(((uintptr_t)dyn + 1023) & ~(uintptr_t)1023);
    float*    biass = (float*)(tiles + 196608);
    uint64_t* mbar  = (uint64_t*)(tiles + 196608 + 512);   // [0..2]=tma, [3..5]=mma
    uint32_t* tptr  = (uint32_t*)(tiles + 196608 + 512 + 48);

    const int tid  = threadIdx.x;
    const int wid  = tid >> 5;
    const int lane = tid & 31;
    const int row0 = blockIdx.y << 7, col0 = blockIdx.x << 7;

    const uint32_t tiles_u = su32(tiles);
    const uint32_t mbar_u  = su32(mbar);

    if (tid == 0) {
        #pragma unroll
        for (int i = 0; i < 6; i++) MBAR_INIT(mbar_u + i * 8, 1);
    }
    if (wid == 0) { TC_ALLOC(su32(tptr), 128); TC_RELINQ(); }
    if (tid < 128) biass[tid] = bias[col0 + tid];
    __syncthreads();
    const uint32_t tmem = *tptr;

    const int NS = K >> 6;

    if (tid == 0) {
        auto tma_load = [&](int s) {
            int b = s % 3;
            uint32_t base = tiles_u + b * 65536;
            uint32_t mb   = mbar_u + b * 8;
            MBAR_EXPECT_TX(mb, 65536);
            int x = s << 6;
            tma2d(base,         &mAhi, x, row0, mb);
            tma2d(base + 16384, &mAlo, x, row0, mb);
            tma2d(base + 32768, &mBhi, x, col0, mb);
            tma2d(base + 49152, &mBlo, x, col0, mb);
        };
        auto issue_stage = [&](int s, bool first) {
            uint32_t a0 = tiles_u + (s % 3) * 65536;
            uint64_t dAh = make_desc(a0);
            uint64_t dAl = make_desc(a0 + 16384);
            uint64_t dBh = make_desc(a0 + 32768);
            uint64_t dBl = make_desc(a0 + 49152);
            #pragma unroll
            for (int j = 0; j < 4; j++) {
                mma_bf16_ss(tmem, dAh + j * 2, dBh + j * 2, GEMM_IDESC, !(first && j == 0));
                mma_bf16_ss(tmem, dAh + j * 2, dBl + j * 2, GEMM_IDESC, true);
                mma_bf16_ss(tmem, dAl + j * 2, dBh + j * 2, GEMM_IDESC, true);
            }
            TC_COMMIT(mbar_u + (3 + s % 3) * 8);
        };

        int ptT[3] = {0, 0, 0}, ptM[3] = {0, 0, 0};
        tma_load(0);
        tma_load(1);
        for (int s = 0; s < NS; s++) {
            int b = s % 3;
            // 1) stage s data ready (usually already complete)
            MBAR_WAIT(mbar_u + b * 8, ptT[b]); ptT[b] ^= 1;
            // 2) enqueue MMA(s) right away -> tensor queue holds (s-1, s)
            issue_stage(s, s == 0);
            // 3) recycle buffer (s-1)%3 once MMA(s-1) drains
            if (s >= 1) {
                int pb = (s - 1) % 3;
                MBAR_WAIT(mbar_u + (3 + pb) * 8, ptM[pb]); ptM[pb] ^= 1;
            }
            // 4) refill it for stage s+2 (latency hides under MMA(s))
            if (s + 2 < NS) tma_load(s + 2);
        }
        { int b = (NS - 1) % 3; MBAR_WAIT(mbar_u + (3 + b) * 8, ptM[b]); }
    }
    __syncthreads();

    TC_FENCE_AFTER();
    if (tid < 128) {
        const int er = row0 + wid * 32 + lane;
        #pragma unroll
        for (int c0 = 0; c0 < 128; c0 += 32) {
            uint32_t rg[32];
            LDTM_X32(rg, tmem + c0);
            TC_WAIT_LD();
            float v[32];
            #pragma unroll
            for (int j = 0; j < 32; j++)
                v[j] = __uint_as_float(rg[j]) + biass[c0 + j];
            if (Chi) {
                __nv_bfloat16* ph = Chi + (size_t)er * N + col0 + c0;
                __nv_bfloat16* pl = Clo + (size_t)er * N + col0 + c0;
                #pragma unroll
                for (int q = 0; q < 4; q++) {
                    uint4 hh, ll;
                    hh.x = pk_hi(v[8*q+0], v[8*q+1]); ll.x = pk_lo(v[8*q+0], v[8*q+1]);
                    hh.y = pk_hi(v[8*q+2], v[8*q+3]); ll.y = pk_lo(v[8*q+2], v[8*q+3]);
                    hh.z = pk_hi(v[8*q+4], v[8*q+5]); ll.z = pk_lo(v[8*q+4], v[8*q+5]);
                    hh.w = pk_hi(v[8*q+6], v[8*q+7]); ll.w = pk_lo(v[8*q+6], v[8*q+7]);
                    *(uint4*)(ph + 8*q) = hh;
                    *(uint4*)(pl + 8*q) = ll;
                }
            } else {
                float* cp = Cf + (size_t)er * N + col0 + c0;
                #pragma unroll
                for (int j = 0; j < 8; j++) {
                    float4 o;
                    o.x = v[4*j+0]; o.y = v[4*j+1]; o.z = v[4*j+2]; o.w = v[4*j+3];
                    *(float4*)(cp + 4 * j) = o;
                }
            }
        }
    }
    __syncthreads();
    if (wid == 0) TC_DEALLOC(tmem, 128);

#else  // ------- generic fallback (compile-only on this rig) -------
    extern __shared__ char dyn[];
    float* As = (float*)dyn;
    float* Bs = As + 16 * 132;

    const int tid = threadIdx.x;
    const int tx  = tid & 15, ty = tid >> 4;
    const int row0 = blockIdx.y << 7, col0 = blockIdx.x << 7;

    float acc[8][8] = {};
    for (int k0 = 0; k0 < K; k0 += 16) {
        __syncthreads();
        #pragma unroll
        for (int t = 0; t < 2; t++) {
            int ch = tid + (t << 8);
            int rr = ch >> 2, c4 = (ch & 3) << 2;
            size_t ao = (size_t)(row0 + rr) * K + k0 + c4;
            size_t bo = (size_t)(col0 + rr) * K + k0 + c4;
            #pragma unroll
            for (int q = 0; q < 4; q++) {
                As[(c4 + q) * 132 + rr] = __bfloat162float(Ahi[ao + q]) + __bfloat162float(Alo[ao + q]);
                Bs[(c4 + q) * 132 + rr] = __bfloat162float(Bhi[bo + q]) + __bfloat162float(Blo[bo + q]);
            }
        }
        __syncthreads();
        #pragma unroll
        for (int kk = 0; kk < 16; kk++) {
            float a[8], b[8];
            #pragma unroll
            for (int i = 0; i < 8; i++) a[i] = As[kk * 132 + ty * 8 + i];
            #pragma unroll
            for (int j = 0; j < 8; j++) b[j] = Bs[kk * 132 + tx * 8 + j];
            #pragma unroll
            for (int i = 0; i < 8; i++)
                #pragma unroll
                for (int j = 0; j < 8; j++) acc[i][j] += a[i] * b[j];
        }
    }
    #pragma unroll
    for (int i = 0; i < 8; i++)
        #pragma unroll
        for (int j = 0; j < 8; j++) {
            float v = acc[i][j] + bias[col0 + tx * 8 + j];
            size_t o = (size_t)(row0 + ty * 8 + i) * N + col0 + tx * 8 + j;
            if (Chi) {
                __nv_bfloat16 hb = __float2bfloat16_rn(v);
                Chi[o] = hb;
                Clo[o] = __float2bfloat16_rn(v - __bfloat162float(hb));
            } else {
                Cf[o] = v;
            }
        }
#endif
}

// ---------------------------------------------------------------------------
// Attention, bf16x2 tcgen05, static softmax base (m=0). CTA = (b,h,128-q tile).
// (unchanged from R10)
// ---------------------------------------------------------------------------
#define AS_QHI  0
#define AS_QLO  16384
#define AS_KHI  32768
#define AS_KLO  49152
#define AS_VHI  65536
#define AS_VLO  81920
#define AS_PSUM 98304
#define AS_RED  99328
#define AS_MBAR 99840
#define AS_TPTR 99856
#define ATTN_SMEM_BYTES (1024 + 99872)

#define TM_S    0
#define TM_PHI  128
#define TM_PLO  192

__global__ __launch_bounds__(256, 2) void attn_tc_kernel()
{
#if HAS_TCGEN05
    extern __shared__ char dyn[];
    char* smc = (char*)(((uintptr_t)dyn + 1023) & ~(uintptr_t)1023);
    const uint32_t smu = su32(smc);

    const int tid  = threadIdx.x;
    const int wid  = tid >> 5;
    const int lane = tid & 31;
    const int sp   = wid & 3;
    const int half = wid >> 2;
    const int qb   = (gridDim.x - 1) - blockIdx.x;   // big tiles first
    const int h = blockIdx.y, b = blockIdx.z;
    const int q0   = qb << 7;
    const int r    = sp * 32 + lane;

    const size_t hbase = (size_t)b * SEQ * QLD + h * (3 * HD);
    const __nv_bfloat16* qh = g_qkv_hi + hbase;
    const __nv_bfloat16* ql = g_qkv_lo + hbase;
    const __nv_bfloat16* kh = qh + HD;
    const __nv_bfloat16* kl = ql + HD;
    const __nv_bfloat16* vh = qh + 2 * HD;
    const __nv_bfloat16* vl = ql + 2 * HD;

    float* psums = (float*)(smc + AS_PSUM);
    float* red   = (float*)(smc + AS_RED);
    const uint32_t mb1 = smu + AS_MBAR;
    const uint32_t mb2 = smu + AS_MBAR + 8;

    if (tid == 0) { MBAR_INIT(mb1, 1); MBAR_INIT(mb2, 1); }
    if (wid == 0) { TC_ALLOC(smu + AS_TPTR, 256); TC_RELINQ(); }
    __syncthreads();
    const uint32_t tmem = *(uint32_t*)(smc + AS_TPTR);
    const uint32_t warpoff = (uint32_t)sp << 21;

    const float C = 0.125f * 1.44269504f;

    // ---- Load Q (cp.async, coalesced) ----
    #pragma unroll
    for (int i = 0; i < 4; i++) {
        int cg  = tid + (i << 8);
        int row = cg >> 3, ch = cg & 7;
        uint32_t sw = SMEM_SWZ((uint32_t)(row * 128 + ch * 16));
        size_t off = (size_t)(q0 + row) * QLD + (ch << 3);
        cp16(smu + AS_QHI + sw, qh + off);
        cp16(smu + AS_QLO + sw, ql + off);
    }
    CP_COMMIT();

    float O[32];
    #pragma unroll
    for (int i = 0; i < 32; i++) O[i] = 0.0f;
    float l_run = 0.0f;
    int pt1 = 0, pt2 = 0;

    const int vp_p  = tid & 63;
    const int vp_dh = tid >> 6;
    const int vp_panel = vp_p >> 5;
    const int vp_pc    = vp_p & 31;

    for (int kb = 0; kb <= qb; kb++) {
        const int k0 = kb << 7;
        __syncthreads();

        // ---- Load K (cp.async) ----
        #pragma unroll
        for (int i = 0; i < 4; i++) {
            int cg  = tid + (i << 8);
            int row = cg >> 3, ch = cg & 7;
            uint32_t sw = SMEM_SWZ((uint32_t)(row * 128 + ch * 16));
            size_t off = (size_t)(k0 + row) * QLD + (ch << 3);
            cp16(smu + AS_KHI + sw, kh + off);
            cp16(smu + AS_KLO + sw, kl + off);
        }
        CP_COMMIT();

        // ---- Load V transposed (PRMT-pack) ----
        {
            const size_t e_off = (size_t)(k0 + 2 * vp_p) * QLD + (vp_dh << 4);
            const size_t o_off = e_off + QLD;
            uint32_t E[8], Od[8], El[8], Ol[8];
            *(uint4*)&E[0]  = *(const uint4*)(vh + e_off);
            *(uint4*)&E[4]  = *(const uint4*)(vh + e_off + 8);
            *(uint4*)&Od[0] = *(const uint4*)(vh + o_off);
            *(uint4*)&Od[4] = *(const uint4*)(vh + o_off + 8);
            *(uint4*)&El[0] = *(const uint4*)(vl + e_off);
            *(uint4*)&El[4] = *(const uint4*)(vl + e_off + 8);
            *(uint4*)&Ol[0] = *(const uint4*)(vl + o_off);
            *(uint4*)&Ol[4] = *(const uint4*)(vl + o_off + 8);
            #pragma unroll
            for (int j = 0; j < 8; j++) {
                int d = (vp_dh << 4) + 2 * j;
                uint32_t w0h = __byte_perm(E[j],  Od[j], 0x5410);
                uint32_t w1h = __byte_perm(E[j],  Od[j], 0x7632);
                uint32_t w0l = __byte_perm(El[j], Ol[j], 0x5410);
                uint32_t w1l = __byte_perm(El[j], Ol[j], 0x7632);
                uint32_t off0 = SMEM_SWZ((uint32_t)(d * 128 + vp_pc * 4));
                uint32_t off1 = SMEM_SWZ((uint32_t)((d + 1) * 128 + vp_pc * 4));
                *(uint32_t*)(smc + AS_VHI + vp_panel * 8192 + off0) = w0h;
                *(uint32_t*)(smc + AS_VHI + vp_panel * 8192 + off1) = w1h;
                *(uint32_t*)(smc + AS_VLO + vp_panel * 8192 + off0) = w0l;
                *(uint32_t*)(smc + AS_VLO + vp_panel * 8192 + off1) = w1l;
            }
        }
        CP_WAIT0();
        FENCE_ASYNC();
        __syncthreads();

        // ---- MMA1: S = Q @ K^T ----
        if (wid == 0) {
            TC_FENCE_AFTER();
            if (elect1()) {
                uint64_t dQh = make_desc(smu + AS_QHI);
                uint64_t dQl = make_desc(smu + AS_QLO);
                uint64_t dKh = make_desc(smu + AS_KHI);
                uint64_t dKl = make_desc(smu + AS_KLO);
                bool first = true;
                #pragma unroll
                for (int j = 0; j < 4; j++) {
                    mma_bf16_ss(tmem + TM_S, dQh + j * 2, dKh + j * 2, ATTN_IDESC1, !first);
                    first = false;
                    mma_bf16_ss(tmem + TM_S, dQh + j * 2, dKl + j * 2, ATTN_IDESC1, true);
                    mma_bf16_ss(tmem + TM_S, dQl + j * 2, dKh + j * 2, ATTN_IDESC1, true);
                }
                TC_COMMIT(mb1);
            }
        }
        MBAR_WAIT(mb1, pt1); pt1 ^= 1;
        TC_FENCE_AFTER();

        // ---- Softmax (single pass, m=0) ----
        const int qg = q0 + r;
        float ps = 0.0f;
        #pragma unroll
        for (int c = 0; c < 2; c++) {
            uint32_t u[32];
            LDTM_X32(u, tmem + TM_S + half * 64 + c * 32);
            TC_WAIT_LD();
            const int cb = k0 + half * 64 + c * 32;
            float p[32];
            #pragma unroll
            for (int j = 0; j < 32; j++) {
                float e = exp2f(__uint_as_float(u[j]) * C);
                if (kb == qb && cb + j > qg) e = 0.0f;
                p[j] = e;
                ps += e;
            }
            uint32_t hw[16], lw[16];
            #pragma unroll
            for (int j = 0; j < 16; j++) {
                hw[j] = pk_hi(p[2 * j], p[2 * j + 1]);
                lw[j] = pk_lo(p[2 * j], p[2 * j + 1]);
            }
            STTM_X16(tmem + TM_PHI + half * 32 + c * 16 + warpoff, hw);
            STTM_X16(tmem + TM_PLO + half * 32 + c * 16 + warpoff, lw);
        }
        psums[r * 2 + half] = ps;
        TC_WAIT_ST();
        TC_FENCE_BEFORE();
        __syncthreads();

        if (half == 0)
            l_run += psums[r * 2] + psums[r * 2 + 1];

        // ---- MMA2: U = P @ Vt^T ----
        if (wid == 0) {
            TC_FENCE_AFTER();
            if (elect1()) {
                bool first = true;
                #pragma unroll
                for (int panel = 0; panel < 2; panel++) {
                    uint64_t dVh = make_desc(smu + AS_VHI + panel * 8192);
                    uint64_t dVl = make_desc(smu + AS_VLO + panel * 8192);
                    #pragma unroll
                    for (int j = 0; j < 4; j++) {
                        uint32_t acol = panel * 32 + j * 8;
                        mma_bf16_ts(tmem + TM_S, tmem + TM_PHI + acol, dVh + j * 2, ATTN_IDESC2, !first);
                        first = false;
                        mma_bf16_ts(tmem + TM_S, tmem + TM_PHI + acol, dVl + j * 2, ATTN_IDESC2, true);
                        mma_bf16_ts(tmem + TM_S, tmem + TM_PLO + acol, dVh + j * 2, ATTN_IDESC2, true);
                    }
                }
                TC_COMMIT(mb2);
            }
        }
        MBAR_WAIT(mb2, pt2); pt2 ^= 1;
        TC_FENCE_AFTER();

        // ---- O += U ----
        {
            uint32_t u[32];
            LDTM_X32(u, tmem + TM_S + half * 32);
            TC_WAIT_LD();
            #pragma unroll
            for (int j = 0; j < 32; j++)
                O[j] += __uint_as_float(u[j]);
        }
        TC_FENCE_BEFORE();
    }

    // ---- Epilogue: write val bf16 hi/lo ----
    if (half == 0) red[r] = 1.0f / l_run;
    __syncthreads();
    {
        const float inv = red[r];
        const size_t vo = ((size_t)b * SEQ + q0 + r) * DM + h * HD + half * 32;
        float v[32];
        #pragma unroll
        for (int c = 0; c < 32; c++) v[c] = O[c] * inv;
        uint4 hh, ll;
        #pragma unroll
        for (int q = 0; q < 4; q++) {
            hh.x = pk_hi(v[8*q+0], v[8*q+1]); ll.x = pk_lo(v[8*q+0], v[8*q+1]);
            hh.y = pk_hi(v[8*q+2], v[8*q+3]); ll.y = pk_lo(v[8*q+2], v[8*q+3]);
            hh.z = pk_hi(v[8*q+4], v[8*q+5]); ll.z = pk_lo(v[8*q+4], v[8*q+5]);
            hh.w = pk_hi(v[8*q+6], v[8*q+7]); ll.w = pk_lo(v[8*q+6], v[8*q+7]);
            *(uint4*)(g_val_hi + vo + 8*q) = hh;
            *(uint4*)(g_val_lo + vo + 8*q) = ll;
        }
    }
    __syncthreads();
    if (wid == 0) TC_DEALLOC(tmem, 256);

#else  // ------- generic fallback (compile-only on this rig) -------
    extern __shared__ float sm[];
    float* Qs = sm;
    float* Ks = sm + 64 * 68;
    float* Vs = sm + 2 * 64 * 68;
    float* Ps = sm + 3 * 64 * 68;

    const int tid = threadIdx.x;
    const int tx  = tid & 15, ty = tid >> 4;
    const int h = blockIdx.y, b = blockIdx.z;

    const size_t hbase = (size_t)b * SEQ * QLD + h * (3 * HD);

    for (int sub = 0; sub < 2; sub++) {
        const int q0 = (blockIdx.x << 7) + (sub << 6);
        __syncthreads();
        for (int idx = tid; idx < 64 * 64; idx += 256) {
            int rr = idx >> 6, d = idx & 63;
            size_t o = hbase + (size_t)(q0 + rr) * QLD + d;
            Qs[d * 68 + rr] = (__bfloat162float(g_qkv_hi[o]) + __bfloat162float(g_qkv_lo[o])) * 0.125f;
        }

        float m_i[4] = {-3e38f, -3e38f, -3e38f, -3e38f};
        float l_i[4] = {};
        float acc[4][4] = {};
        const int nkb = (q0 >> 6) + 1;

        for (int kb = 0; kb < nkb; kb++) {
            const int k0 = kb << 6;
            __syncthreads();
            for (int idx = tid; idx < 64 * 64; idx += 256) {
                int c = idx >> 6, d = idx & 63;
                size_t ko = hbase + (size_t)(k0 + c) * QLD + HD + d;
                size_t vo = ko + HD;
                Ks[d * 68 + c] = __bfloat162float(g_qkv_hi[ko]) + __bfloat162float(g_qkv_lo[ko]);
                Vs[c * 68 + d] = __bfloat162float(g_qkv_hi[vo]) + __bfloat162float(g_qkv_lo[vo]);
            }
            __syncthreads();

            float s[4][4] = {};
            for (int d = 0; d < 64; d++) {
                float a0 = Qs[d*68+(ty<<2)], a1 = Qs[d*68+(ty<<2)+1];
                float a2 = Qs[d*68+(ty<<2)+2], a3 = Qs[d*68+(ty<<2)+3];
                float b0 = Ks[d*68+(tx<<2)], b1 = Ks[d*68+(tx<<2)+1];
                float b2 = Ks[d*68+(tx<<2)+2], b3 = Ks[d*68+(tx<<2)+3];
                s[0][0]+=a0*b0; s[0][1]+=a0*b1; s[0][2]+=a0*b2; s[0][3]+=a0*b3;
                s[1][0]+=a1*b0; s[1][1]+=a1*b1; s[1][2]+=a1*b2; s[1][3]+=a1*b3;
                s[2][0]+=a2*b0; s[2][1]+=a2*b1; s[2][2]+=a2*b2; s[2][3]+=a2*b3;
                s[3][0]+=a3*b0; s[3][1]+=a3*b1; s[3][2]+=a3*b2; s[3][3]+=a3*b3;
            }
            if (kb == nkb - 1)
                for (int i = 0; i < 4; i++)
                    for (int j = 0; j < 4; j++)
                        if ((tx<<2)+j > (ty<<2)+i) s[i][j] = -1e9f;
            for (int i = 0; i < 4; i++) {
                float mx = fmaxf(fmaxf(s[i][0], s[i][1]), fmaxf(s[i][2], s[i][3]));
                for (int off = 8; off > 0; off >>= 1)
                    mx = fmaxf(mx, __shfl_xor_sync(0xffffffffu, mx, off, 16));
                float mnew = fmaxf(m_i[i], mx);
                float p0 = __expf(s[i][0]-mnew), p1 = __expf(s[i][1]-mnew);
                float p2 = __expf(s[i][2]-mnew), p3 = __expf(s[i][3]-mnew);
                float ls = p0+p1+p2+p3;
                for (int off = 8; off > 0; off >>= 1)
                    ls += __shfl_xor_sync(0xffffffffu, ls, off, 16);
                float alpha = __expf(m_i[i] - mnew);
                l_i[i] = l_i[i]*alpha + ls;
                m_i[i] = mnew;
                acc[i][0]*=alpha; acc[i][1]*=alpha; acc[i][2]*=alpha; acc[i][3]*=alpha;
                s[i][0]=p0; s[i][1]=p1; s[i][2]=p2; s[i][3]=p3;
            }
            for (int i = 0; i < 4; i++)
                for (int j = 0; j < 4; j++)
                    Ps[((tx<<2)+j)*68 + (ty<<2)+i] = s[i][j];
            __syncthreads();
            for (int c = 0; c < 64; c++) {
                float a0 = Ps[c*68+(ty<<2)], a1 = Ps[c*68+(ty<<2)+1];
                float a2 = Ps[c*68+(ty<<2)+2], a3 = Ps[c*68+(ty<<2)+3];
                float b0 = Vs[c*68+(tx<<2)], b1 = Vs[c*68+(tx<<2)+1];
                float b2 = Vs[c*68+(tx<<2)+2], b3 = Vs[c*68+(tx<<2)+3];
                acc[0][0]+=a0*b0; acc[0][1]+=a0*b1; acc[0][2]+=a0*b2; acc[0][3]+=a0*b3;
                acc[1][0]+=a1*b0; acc[1][1]+=a1*b1; acc[1][2]+=a1*b2; acc[1][3]+=a1*b3;
                acc[2][0]+=a2*b0; acc[2][1]+=a2*b1; acc[2][2]+=a2*b2; acc[2][3]+=a2*b3;
                acc[3][0]+=a3*b0; acc[3][1]+=a3*b1; acc[3][2]+=a3*b2; acc[3][3]+=a3*b3;
            }
        }
        for (int i = 0; i < 4; i++) {
            float inv = 1.0f / l_i[i];
            for (int j = 0; j < 4; j++) {
                float v = acc[i][j] * inv;
                size_t o = ((size_t)b * SEQ + q0 + (ty<<2)+i) * DM + h * HD + (tx<<2)+j;
                __nv_bfloat16 hb = __float2bfloat16_rn(v);
                g_val_hi[o] = hb;
                g_val_lo[o] = __float2bfloat16_rn(v - __bfloat162float(hb));
            }
        }
        __syncthreads();
    }
#endif
}

// ---------------------------------------------------------------------------
// Host: tensormap creation via driver entry point (no -lcuda needed)
// ---------------------------------------------------------------------------
typedef CUresult (*PFN_encodeTiled)(CUtensorMap*, CUtensorMapDataType, cuuint32_t, void*,
    const cuuint64_t*, const cuuint64_t*, const cuuint32_t*, const cuuint32_t*,
    CUtensorMapInterleave, CUtensorMapSwizzle, CUtensorMapL2promotion, CUtensorMapFloatOOBfill);

static PFN_encodeTiled get_encode_fn() {
    static PFN_encodeTiled fn = nullptr;
    if (!fn) {
        void* p = nullptr;
        cudaDriverEntryPointQueryResult qr;
        cudaGetDriverEntryPoint("cuTensorMapEncodeTiled", &p, cudaEnableDefault, &qr);
        fn = (PFN_encodeTiled)p;
    }
    return fn;
}

static CUtensorMap mk_map(void* ptr, uint64_t Kdim, uint64_t rows) {
    CUtensorMap m;
    memset(&m, 0, sizeof(m));
    cuuint64_t dims[2] = {Kdim, rows};
    cuuint64_t str[1]  = {Kdim * 2};         // row stride in bytes (bf16)
    cuuint32_t box[2]  = {64, 128};          // 64 bf16 = 128B inner (SW128 limit)
    cuuint32_t es[2]   = {1, 1};
    get_encode_fn()(&m, CU_TENSOR_MAP_DATA_TYPE_BFLOAT16, 2, ptr, dims, str, box, es,
                    CU_TENSOR_MAP_INTERLEAVE_NONE, CU_TENSOR_MAP_SWIZZLE_128B,
                    CU_TENSOR_MAP_L2_PROMOTION_L2_128B, CU_TENSOR_MAP_FLOAT_OOB_FILL_NONE);
    return m;
}

// ---------------------------------------------------------------------------
// Launch
// ---------------------------------------------------------------------------
extern "C" void kernel_launch(void* const* d_in, const int* in_sizes, int n_in,
                              void* d_out, int out_size)
{
    const float* x    = (const float*)d_in[0];
    const float* Wqkv = (const float*)d_in[1];
    const float* bqkv = (const float*)d_in[2];
    const float* Wout = (const float*)d_in[3];
    const float* bout = (const float*)d_in[4];
    float* out = (float*)d_out;

    __nv_bfloat16 *x_hi, *x_lo, *qkv_hi, *qkv_lo, *val_hi, *val_lo;
    __nv_bfloat16 *wq_hi, *wq_lo, *wo_hi, *wo_lo;
    cudaGetSymbolAddress((void**)&x_hi,   g_x_hi);
    cudaGetSymbolAddress((void**)&x_lo,   g_x_lo);
    cudaGetSymbolAddress((void**)&qkv_hi, g_qkv_hi);
    cudaGetSymbolAddress((void**)&qkv_lo, g_qkv_lo);
    cudaGetSymbolAddress((void**)&val_hi, g_val_hi);
    cudaGetSymbolAddress((void**)&val_lo, g_val_lo);
    cudaGetSymbolAddress((void**)&wq_hi,  g_wqkvT_hi);
    cudaGetSymbolAddress((void**)&wq_lo,  g_wqkvT_lo);
    cudaGetSymbolAddress((void**)&wo_hi,  g_woutT_hi);
    cudaGetSymbolAddress((void**)&wo_lo,  g_woutT_lo);

    const int gemm_smem = 1024 + 196608 + 512 + 64;
    const int attn_smem = ATTN_SMEM_BYTES;
    cudaFuncSetAttribute(gemm_tma_kernel,
                         cudaFuncAttributeMaxDynamicSharedMemorySize, gemm_smem);
    cudaFuncSetAttribute(attn_tc_kernel,
                         cudaFuncAttributeMaxDynamicSharedMemorySize, attn_smem);

    // Tensormaps (host-side, once per capture)
    CUtensorMap mXh  = mk_map(x_hi,   DM, BSROWS);
    CUtensorMap mXl  = mk_map(x_lo,   DM, BSROWS);
    CUtensorMap mWqh = mk_map(wq_hi,  DM, QLD);
    CUtensorMap mWql = mk_map(wq_lo,  DM, QLD);
    CUtensorMap mVh  = mk_map(val_hi, DM, BSROWS);
    CUtensorMap mVl  = mk_map(val_lo, DM, BSROWS);
    CUtensorMap mWoh = mk_map(wo_hi,  DM, DM);
    CUtensorMap mWol = mk_map(wo_lo,  DM, DM);

    // Preludes
    split_f32_kernel<<<(BSROWS * DM) / (256 * 8), 256>>>(x, x_hi, x_lo);
    transpose_split_kernel<<<dim3(QLD / 32, DM / 32), dim3(32, 8)>>>(Wqkv, wq_hi, wq_lo, DM, QLD);
    transpose_split_kernel<<<dim3(DM / 32, DM / 32), dim3(32, 8)>>>(Wout, wo_hi, wo_lo, DM, DM);

    // QKV projection -> bf16 hi/lo qkv
    gemm_tma_kernel<<<dim3(QLD / 128, BSROWS / 128), 256, gemm_smem>>>(
        mXh, mXl, mWqh, mWql, x_hi, x_lo, wq_hi, wq_lo,
        bqkv, nullptr, qkv_hi, qkv_lo, BSROWS, QLD, DM);

    // Attention -> bf16 hi/lo val
    attn_tc_kernel<<<dim3(SEQ / 128, NH, BATCH), 256, attn_smem>>>();

    // Output projection -> fp32 out
    gemm_tma_kernel<<<dim3(DM / 128, BSROWS / 128), 256, gemm_smem>>>(
        mVh, mVl, mWoh, mWol, val_hi, val_lo, wo_hi, wo_lo,
        bout, out, nullptr, nullptr, BSROWS, DM, DM);
}

// round 13
// speedup vs baseline: 1.0764x; 1.0700x over previous
#include <cuda_runtime.h>
#include <cuda_bf16.h>
#include <cstdint>
#include <math.h>

#define SEQ   2048
#define BATCH 2
#define DM    1024
#define NH    16
#define HD    64
#define BSROWS (BATCH*SEQ)   // 4096
#define QLD   (3*DM)         // 3072

#if defined(__CUDA_ARCH_FEAT_SM103_ALL) || defined(__CUDA_ARCH_FEAT_SM100_ALL) || \
    (defined(__CUDA_ARCH_SPECIFIC__) && (__CUDA_ARCH_SPECIFIC__ >= 1000))
#define HAS_TCGEN05 1
#else
#define HAS_TCGEN05 0
#endif

// ---------------------------------------------------------------------------
// Scratch: everything mid-pipeline is bf16 hi/lo
// ---------------------------------------------------------------------------
__device__ __nv_bfloat16 g_x_hi[(size_t)BSROWS * DM];
__device__ __nv_bfloat16 g_x_lo[(size_t)BSROWS * DM];
__device__ __nv_bfloat16 g_qkv_hi[(size_t)BSROWS * QLD];
__device__ __nv_bfloat16 g_qkv_lo[(size_t)BSROWS * QLD];
__device__ __nv_bfloat16 g_val_hi[(size_t)BSROWS * DM];
__device__ __nv_bfloat16 g_val_lo[(size_t)BSROWS * DM];
__device__ __nv_bfloat16 g_wqkvT_hi[(size_t)QLD * DM];
__device__ __nv_bfloat16 g_wqkvT_lo[(size_t)QLD * DM];
__device__ __nv_bfloat16 g_woutT_hi[(size_t)DM * DM];
__device__ __nv_bfloat16 g_woutT_lo[(size_t)DM * DM];

// ---------------------------------------------------------------------------
// Generic helpers
// ---------------------------------------------------------------------------
__device__ __forceinline__ uint32_t su32(const void* p) {
    return (uint32_t)__cvta_generic_to_shared(p);
}
__device__ __forceinline__ uint32_t pk_hi(float a, float b) {
    __nv_bfloat162 t = __floats2bfloat162_rn(a, b);
    return *(uint32_t*)&t;
}
__device__ __forceinline__ uint32_t pk_lo(float a, float b) {
    float ah = __bfloat162float(__float2bfloat16_rn(a));
    float bh = __bfloat162float(__float2bfloat16_rn(b));
    __nv_bfloat162 t = __floats2bfloat162_rn(a - ah, b - bh);
    return *(uint32_t*)&t;
}
#define SMEM_SWZ(off) ((off) ^ (((off) >> 3) & 0x70))

// cp.async (sm_80+)
__device__ __forceinline__ void cp16(uint32_t dst, const void* src) {
    asm volatile("cp.async.cg.shared.global [%0], [%1], 16;" :: "r"(dst), "l"(src) : "memory");
}
#define CP_COMMIT() asm volatile("cp.async.commit_group;" ::: "memory")
#define CP_WAIT0()  asm volatile("cp.async.wait_group 0;" ::: "memory")
#define CP_WAIT1()  asm volatile("cp.async.wait_group 1;" ::: "memory")

#if HAS_TCGEN05
__device__ __forceinline__ bool elect1() {
    uint32_t r;
    asm volatile("{\n\t.reg .pred p;\n\telect.sync _|p, 0xFFFFFFFF;\n\tselp.b32 %0, 1, 0, p;\n\t}" : "=r"(r));
    return r != 0;
}
#define MBAR_INIT(addr, cnt) \
    asm volatile("mbarrier.init.shared.b64 [%0], %1;" :: "r"(addr), "r"(cnt) : "memory")
#define MBAR_WAIT(addr, ph) do {                                              \
    uint32_t _m = (addr), _p = (ph), _d;                                      \
    asm volatile("{\n\t.reg .pred p;\n\t"                                     \
        "mbarrier.try_wait.parity.acquire.cta.shared::cta.b64 p, [%1], %2;\n\t" \
        "selp.b32 %0, 1, 0, p;\n\t}" : "=r"(_d) : "r"(_m), "r"(_p) : "memory"); \
    if (!_d) {                                                                \
        asm volatile("{\n\t.reg .pred P1;\n\t"                                \
            "WL_%=:\n\t"                                                      \
            "mbarrier.try_wait.parity.acquire.cta.shared::cta.b64 P1, [%0], %1, 0x989680;\n\t" \
            "@P1 bra.uni WD_%=;\n\tbra.uni WL_%=;\n\tWD_%=:\n\t}"             \
            :: "r"(_m), "r"(_p) : "memory");                                  \
    }                                                                         \
} while (0)
#define TC_ALLOC(smem_addr, ncols) \
    asm volatile("tcgen05.alloc.cta_group::1.sync.aligned.shared::cta.b32 [%0], %1;" \
                 :: "r"(smem_addr), "r"(ncols) : "memory")
#define TC_RELINQ() \
    asm volatile("tcgen05.relinquish_alloc_permit.cta_group::1.sync.aligned;")
#define TC_DEALLOC(tmem, ncols) \
    asm volatile("tcgen05.dealloc.cta_group::1.sync.aligned.b32 %0, %1;" :: "r"(tmem), "r"(ncols))
#define TC_COMMIT(mbar) \
    asm volatile("tcgen05.commit.cta_group::1.mbarrier::arrive::one.shared::cluster.b64 [%0];" \
                 :: "r"(mbar) : "memory")
#define TC_FENCE_AFTER()  asm volatile("tcgen05.fence::after_thread_sync;" ::: "memory")
#define TC_FENCE_BEFORE() asm volatile("tcgen05.fence::before_thread_sync;" ::: "memory")
#define TC_WAIT_LD()      asm volatile("tcgen05.wait::ld.sync.aligned;" ::: "memory")
#define TC_WAIT_ST()      asm volatile("tcgen05.wait::st.sync.aligned;" ::: "memory")
#define FENCE_ASYNC()     asm volatile("fence.proxy.async.shared::cta;" ::: "memory")

#define LDTM_X32(r, a) \
    asm volatile("tcgen05.ld.sync.aligned.32x32b.x32.b32 "                    \
        "{%0, %1, %2, %3, %4, %5, %6, %7, %8, %9, %10, %11, %12, %13, %14, %15, " \
        " %16, %17, %18, %19, %20, %21, %22, %23, %24, %25, %26, %27, %28, %29, %30, %31}, [%32];" \
        : "=r"((r)[0]),  "=r"((r)[1]),  "=r"((r)[2]),  "=r"((r)[3]),          \
          "=r"((r)[4]),  "=r"((r)[5]),  "=r"((r)[6]),  "=r"((r)[7]),          \
          "=r"((r)[8]),  "=r"((r)[9]),  "=r"((r)[10]), "=r"((r)[11]),         \
          "=r"((r)[12]), "=r"((r)[13]), "=r"((r)[14]), "=r"((r)[15]),         \
          "=r"((r)[16]), "=r"((r)[17]), "=r"((r)[18]), "=r"((r)[19]),         \
          "=r"((r)[20]), "=r"((r)[21]), "=r"((r)[22]), "=r"((r)[23]),         \
          "=r"((r)[24]), "=r"((r)[25]), "=r"((r)[26]), "=r"((r)[27]),         \
          "=r"((r)[28]), "=r"((r)[29]), "=r"((r)[30]), "=r"((r)[31])          \
        : "r"(a))

#define STTM_X16(a, r) \
    asm volatile("tcgen05.st.sync.aligned.32x32b.x16.b32 [%0], "              \
        "{%1, %2, %3, %4, %5, %6, %7, %8, %9, %10, %11, %12, %13, %14, %15, %16};" \
        :: "r"(a),                                                            \
           "r"((r)[0]),  "r"((r)[1]),  "r"((r)[2]),  "r"((r)[3]),             \
           "r"((r)[4]),  "r"((r)[5]),  "r"((r)[6]),  "r"((r)[7]),             \
           "r"((r)[8]),  "r"((r)[9]),  "r"((r)[10]), "r"((r)[11]),            \
           "r"((r)[12]), "r"((r)[13]), "r"((r)[14]), "r"((r)[15])             \
        : "memory")

// K-major SW128 desc (128B rows): SBO=64, LBO=1
static __device__ __forceinline__ uint64_t make_desc(uint32_t addr) {
    const uint64_t base = (uint64_t(2) << 61) | (uint64_t(1) << 46)
                        | (uint64_t(64) << 32) | (uint64_t(1) << 16);
    return base | ((uint64_t)(addr >> 4) & 0x3FFF);
}
__device__ __forceinline__ void mma_bf16_ss(uint32_t d, uint64_t ad, uint64_t bd,
                                            uint32_t idesc, bool acc) {
    uint32_t en = acc ? 1u : 0u;
    asm volatile(
        "{\n\t.reg .pred p;\n\tsetp.ne.u32 p, %4, 0;\n\t"
        "tcgen05.mma.cta_group::1.kind::f16 [%0], %1, %2, %3, {%5, %5, %5, %5}, p;\n\t}"
        :: "r"(d), "l"(ad), "l"(bd), "r"(idesc), "r"(en), "r"(0u) : "memory");
}
__device__ __forceinline__ void mma_bf16_ts(uint32_t d, uint32_t a, uint64_t bd,
                                            uint32_t idesc, bool acc) {
    uint32_t en = acc ? 1u : 0u;
    asm volatile(
        "{\n\t.reg .pred p;\n\tsetp.ne.u32 p, %4, 0;\n\t"
        "tcgen05.mma.cta_group::1.kind::f16 [%0], [%1], %2, %3, {%5, %5, %5, %5}, p;\n\t}"
        :: "r"(d), "r"(a), "l"(bd), "r"(idesc), "r"(en), "r"(0u) : "memory");
}
#define GEMM_IDESC  ((1u << 4) | (1u << 7) | (1u << 10) | (16u << 17) | (8u << 24))  // M128 N128
#define ATTN_IDESC1 ((1u << 4) | (1u << 7) | (1u << 10) | (16u << 17) | (8u << 24))  // M128 N128
#define ATTN_IDESC2 ((1u << 4) | (1u << 7) | (1u << 10) | (8u  << 17) | (8u << 24))  // M128 N64
#endif  // HAS_TCGEN05

// ---------------------------------------------------------------------------
// Elementwise split: fp32 -> bf16 hi/lo (8 elems/thread)
// ---------------------------------------------------------------------------
__global__ __launch_bounds__(256) void split_f32_kernel(
    const float* __restrict__ X, __nv_bfloat16* __restrict__ Xhi,
    __nv_bfloat16* __restrict__ Xlo)
{
    const size_t i = ((size_t)blockIdx.x * 256 + threadIdx.x) * 8;
    float4 a = *(const float4*)(X + i);
    float4 b = *(const float4*)(X + i + 4);
    uint4 h, l;
    h.x = pk_hi(a.x, a.y); h.y = pk_hi(a.z, a.w);
    h.z = pk_hi(b.x, b.y); h.w = pk_hi(b.z, b.w);
    l.x = pk_lo(a.x, a.y); l.y = pk_lo(a.z, a.w);
    l.z = pk_lo(b.x, b.y); l.w = pk_lo(b.z, b.w);
    *(uint4*)(Xhi + i) = h;
    *(uint4*)(Xlo + i) = l;
}

// ---------------------------------------------------------------------------
// Transpose + bf16 hi/lo split: W[K,N] -> Thi/Tlo[N,K]
// ---------------------------------------------------------------------------
__global__ __launch_bounds__(256) void transpose_split_kernel(
    const float* __restrict__ W, __nv_bfloat16* __restrict__ Thi,
    __nv_bfloat16* __restrict__ Tlo, int K, int N)
{
    __shared__ float t[32][33];
    const int n0 = blockIdx.x << 5, k0 = blockIdx.y << 5;
    const int x = threadIdx.x, y = threadIdx.y;
    #pragma unroll
    for (int i = y; i < 32; i += 8)
        t[i][x] = W[(size_t)(k0 + i) * N + n0 + x];
    __syncthreads();
    #pragma unroll
    for (int i = y; i < 32; i += 8) {
        float v  = t[x][i];
        __nv_bfloat16 hb = __float2bfloat16_rn(v);
        size_t o = (size_t)(n0 + i) * K + k0 + x;
        Thi[o] = hb;
        Tlo[o] = __float2bfloat16_rn(v - __bfloat162float(hb));
    }
}

// ---------------------------------------------------------------------------
// GEMM (R10 proven version): cp.async loads, depth-2 overlap w/ safe tail,
// bf16x2 MMA. 128x128, BK=64, 3 buffers.
// ---------------------------------------------------------------------------
__global__ __launch_bounds__(256)
void gemm_bf16pre_kernel(const __nv_bfloat16* __restrict__ Ahi,
                         const __nv_bfloat16* __restrict__ Alo,
                         const __nv_bfloat16* __restrict__ Bhi,
                         const __nv_bfloat16* __restrict__ Blo,
                         const float* __restrict__ bias,
                         float* __restrict__ Cf,
                         __nv_bfloat16* __restrict__ Chi,
                         __nv_bfloat16* __restrict__ Clo,
                         int M, int N, int K)
{
#if HAS_TCGEN05
    extern __shared__ char dyn[];
    char* tiles = (char*)(((uintptr_t)dyn + 1023) & ~(uintptr_t)1023);
    float*    biass = (float*)(tiles + 196608);
    uint64_t* mbar  = (uint64_t*)(tiles + 196608 + 512);
    uint32_t* tptr  = (uint32_t*)(tiles + 196608 + 512 + 24);

    const int tid  = threadIdx.x;
    const int wid  = tid >> 5;
    const int lane = tid & 31;
    const int row0 = blockIdx.y << 7, col0 = blockIdx.x << 7;

    const uint32_t tiles_u = su32(tiles);
    const uint32_t mbar_u  = su32(mbar);

    if (tid == 0) { MBAR_INIT(mbar_u, 1); MBAR_INIT(mbar_u + 8, 1); MBAR_INIT(mbar_u + 16, 1); }
    if (wid == 0) { TC_ALLOC(su32(tptr), 128); TC_RELINQ(); }
    if (tid < 128) biass[tid] = bias[col0 + tid];
    __syncthreads();
    const uint32_t tmem = *tptr;

    const int NS = K >> 6;

    auto load_stage = [&](int s, int b) {
        uint32_t base = tiles_u + b * 65536;
        const int koff = s << 6;
        #pragma unroll
        for (int i = 0; i < 4; i++) {
            int cg  = tid + (i << 8);
            int row = cg >> 3, ch = cg & 7;
            uint32_t sw = SMEM_SWZ((uint32_t)(row * 128 + ch * 16));
            size_t aoff = (size_t)(row0 + row) * K + koff + (ch << 3);
            size_t boff = (size_t)(col0 + row) * K + koff + (ch << 3);
            cp16(base + sw,         Ahi + aoff);
            cp16(base + 16384 + sw, Alo + aoff);
            cp16(base + 32768 + sw, Bhi + boff);
            cp16(base + 49152 + sw, Blo + boff);
        }
        CP_COMMIT();
    };

    auto issue_stage = [&](int s, int b, bool first) {
        uint32_t a0 = tiles_u + b * 65536;
        uint64_t dAh = make_desc(a0);
        uint64_t dAl = make_desc(a0 + 16384);
        uint64_t dBh = make_desc(a0 + 32768);
        uint64_t dBl = make_desc(a0 + 49152);
        #pragma unroll
        for (int j = 0; j < 4; j++) {
            mma_bf16_ss(tmem, dAh + j * 2, dBh + j * 2, GEMM_IDESC, !(first && j == 0));
            mma_bf16_ss(tmem, dAh + j * 2, dBl + j * 2, GEMM_IDESC, true);
            mma_bf16_ss(tmem, dAl + j * 2, dBh + j * 2, GEMM_IDESC, true);
        }
        TC_COMMIT(mbar_u + (uint32_t)(s % 3) * 8);
    };

    load_stage(0, 0);
    load_stage(1, 1);
    CP_WAIT1();
    FENCE_ASYNC();
    __syncthreads();
    if (wid == 0 && elect1()) issue_stage(0, 0, true);

    for (int s = 0; s < NS; s++) {
        if (s >= 1) { int w = s - 1; MBAR_WAIT(mbar_u + (w % 3) * 8, (w / 3) & 1); }
        const bool loaded = (s + 2 < NS);
        if (loaded) load_stage(s + 2, (s + 2) % 3);
        if (s + 1 < NS) {
            if (loaded) CP_WAIT1(); else CP_WAIT0();
            FENCE_ASYNC();
            __syncthreads();
            if (wid == 0 && elect1()) issue_stage(s + 1, (s + 1) % 3, false);
        }
    }
    { int w = NS - 1; MBAR_WAIT(mbar_u + (w % 3) * 8, (w / 3) & 1); }
    CP_WAIT0();

    TC_FENCE_AFTER();
    if (tid < 128) {
        const int er = row0 + wid * 32 + lane;
        #pragma unroll
        for (int c0 = 0; c0 < 128; c0 += 32) {
            uint32_t rg[32];
            LDTM_X32(rg, tmem + c0);
            TC_WAIT_LD();
            float v[32];
            #pragma unroll
            for (int j = 0; j < 32; j++)
                v[j] = __uint_as_float(rg[j]) + biass[c0 + j];
            if (Chi) {
                __nv_bfloat16* ph = Chi + (size_t)er * N + col0 + c0;
                __nv_bfloat16* pl = Clo + (size_t)er * N + col0 + c0;
                #pragma unroll
                for (int q = 0; q < 4; q++) {
                    uint4 hh, ll;
                    hh.x = pk_hi(v[8*q+0], v[8*q+1]); ll.x = pk_lo(v[8*q+0], v[8*q+1]);
                    hh.y = pk_hi(v[8*q+2], v[8*q+3]); ll.y = pk_lo(v[8*q+2], v[8*q+3]);
                    hh.z = pk_hi(v[8*q+4], v[8*q+5]); ll.z = pk_lo(v[8*q+4], v[8*q+5]);
                    hh.w = pk_hi(v[8*q+6], v[8*q+7]); ll.w = pk_lo(v[8*q+6], v[8*q+7]);
                    *(uint4*)(ph + 8*q) = hh;
                    *(uint4*)(pl + 8*q) = ll;
                }
            } else {
                float* cp = Cf + (size_t)er * N + col0 + c0;
                #pragma unroll
                for (int j = 0; j < 8; j++) {
                    float4 o;
                    o.x = v[4*j+0]; o.y = v[4*j+1]; o.z = v[4*j+2]; o.w = v[4*j+3];
                    *(float4*)(cp + 4 * j) = o;
                }
            }
        }
    }
    __syncthreads();
    if (wid == 0) TC_DEALLOC(tmem, 128);

#else  // ------- generic fallback (compile-only on this rig) -------
    extern __shared__ char dyn[];
    float* As = (float*)dyn;
    float* Bs = As + 16 * 132;

    const int tid = threadIdx.x;
    const int tx  = tid & 15, ty = tid >> 4;
    const int row0 = blockIdx.y << 7, col0 = blockIdx.x << 7;

    float acc[8][8] = {};
    for (int k0 = 0; k0 < K; k0 += 16) {
        __syncthreads();
        #pragma unroll
        for (int t = 0; t < 2; t++) {
            int ch = tid + (t << 8);
            int rr = ch >> 2, c4 = (ch & 3) << 2;
            size_t ao = (size_t)(row0 + rr) * K + k0 + c4;
            size_t bo = (size_t)(col0 + rr) * K + k0 + c4;
            #pragma unroll
            for (int q = 0; q < 4; q++) {
                As[(c4 + q) * 132 + rr] = __bfloat162float(Ahi[ao + q]) + __bfloat162float(Alo[ao + q]);
                Bs[(c4 + q) * 132 + rr] = __bfloat162float(Bhi[bo + q]) + __bfloat162float(Blo[bo + q]);
            }
        }
        __syncthreads();
        #pragma unroll
        for (int kk = 0; kk < 16; kk++) {
            float a[8], b[8];
            #pragma unroll
            for (int i = 0; i < 8; i++) a[i] = As[kk * 132 + ty * 8 + i];
            #pragma unroll
            for (int j = 0; j < 8; j++) b[j] = Bs[kk * 132 + tx * 8 + j];
            #pragma unroll
            for (int i = 0; i < 8; i++)
                #pragma unroll
                for (int j = 0; j < 8; j++) acc[i][j] += a[i] * b[j];
        }
    }
    #pragma unroll
    for (int i = 0; i < 8; i++)
        #pragma unroll
        for (int j = 0; j < 8; j++) {
            float v = acc[i][j] + bias[col0 + tx * 8 + j];
            size_t o = (size_t)(row0 + ty * 8 + i) * N + col0 + tx * 8 + j;
            if (Chi) {
                __nv_bfloat16 hb = __float2bfloat16_rn(v);
                Chi[o] = hb;
                Clo[o] = __float2bfloat16_rn(v - __bfloat162float(hb));
            } else {
                Cf[o] = v;
            }
        }
#endif
}

// ---------------------------------------------------------------------------
// Attention, bf16x2 tcgen05, m=0 softmax, software-pipelined loads:
//   V(kb) is fetched to REGISTERS during MMA2(kb-1); PRMT+STS at loop top.
//   K(kb+1) cp.async is issued right after softmax (K smem free post-MMA1).
// ---------------------------------------------------------------------------
#define AS_QHI  0
#define AS_QLO  16384
#define AS_KHI  32768
#define AS_KLO  49152
#define AS_VHI  65536
#define AS_VLO  81920
#define AS_PSUM 98304
#define AS_RED  99328
#define AS_MBAR 99840
#define AS_TPTR 99856
#define ATTN_SMEM_BYTES (1024 + 99872)

#define TM_S    0
#define TM_PHI  128
#define TM_PLO  192

__global__ __launch_bounds__(256, 2) void attn_tc_kernel()
{
#if HAS_TCGEN05
    extern __shared__ char dyn[];
    char* smc = (char*)(((uintptr_t)dyn + 1023) & ~(uintptr_t)1023);
    const uint32_t smu = su32(smc);

    const int tid  = threadIdx.x;
    const int wid  = tid >> 5;
    const int lane = tid & 31;
    const int sp   = wid & 3;
    const int half = wid >> 2;
    const int qb   = (gridDim.x - 1) - blockIdx.x;   // big tiles first
    const int h = blockIdx.y, b = blockIdx.z;
    const int q0   = qb << 7;
    const int r    = sp * 32 + lane;

    const size_t hbase = (size_t)b * SEQ * QLD + h * (3 * HD);
    const __nv_bfloat16* qh = g_qkv_hi + hbase;
    const __nv_bfloat16* ql = g_qkv_lo + hbase;
    const __nv_bfloat16* kh = qh + HD;
    const __nv_bfloat16* kl = ql + HD;
    const __nv_bfloat16* vh = qh + 2 * HD;
    const __nv_bfloat16* vl = ql + 2 * HD;

    float* psums = (float*)(smc + AS_PSUM);
    float* red   = (float*)(smc + AS_RED);
    const uint32_t mb1 = smu + AS_MBAR;
    const uint32_t mb2 = smu + AS_MBAR + 8;

    if (tid == 0) { MBAR_INIT(mb1, 1); MBAR_INIT(mb2, 1); }
    if (wid == 0) { TC_ALLOC(smu + AS_TPTR, 256); TC_RELINQ(); }
    __syncthreads();
    const uint32_t tmem = *(uint32_t*)(smc + AS_TPTR);
    const uint32_t warpoff = (uint32_t)sp << 21;

    const float C = 0.125f * 1.44269504f;

    // thread mapping for K/Q tile copies
    auto load_k_tile = [&](int k0) {
        #pragma unroll
        for (int i = 0; i < 4; i++) {
            int cg  = tid + (i << 8);
            int row = cg >> 3, ch = cg & 7;
            uint32_t sw = SMEM_SWZ((uint32_t)(row * 128 + ch * 16));
            size_t off = (size_t)(k0 + row) * QLD + (ch << 3);
            cp16(smu + AS_KHI + sw, kh + off);
            cp16(smu + AS_KLO + sw, kl + off);
        }
        CP_COMMIT();
    };

    // V-transpose mapping
    const int vp_p  = tid & 63;
    const int vp_dh = tid >> 6;
    const int vp_panel = vp_p >> 5;
    const int vp_pc    = vp_p & 31;

    uint32_t E[8], Od[8], El[8], Ol[8];   // V(kb) staged in regs
    auto load_v_regs = [&](int k0) {
        const size_t e_off = (size_t)(k0 + 2 * vp_p) * QLD + (vp_dh << 4);
        const size_t o_off = e_off + QLD;
        *(uint4*)&E[0]  = *(const uint4*)(vh + e_off);
        *(uint4*)&E[4]  = *(const uint4*)(vh + e_off + 8);
        *(uint4*)&Od[0] = *(const uint4*)(vh + o_off);
        *(uint4*)&Od[4] = *(const uint4*)(vh + o_off + 8);
        *(uint4*)&El[0] = *(const uint4*)(vl + e_off);
        *(uint4*)&El[4] = *(const uint4*)(vl + e_off + 8);
        *(uint4*)&Ol[0] = *(const uint4*)(vl + o_off);
        *(uint4*)&Ol[4] = *(const uint4*)(vl + o_off + 8);
    };
    auto store_v_smem = [&]() {
        #pragma unroll
        for (int j = 0; j < 8; j++) {
            int d = (vp_dh << 4) + 2 * j;
            uint32_t w0h = __byte_perm(E[j],  Od[j], 0x5410);
            uint32_t w1h = __byte_perm(E[j],  Od[j], 0x7632);
            uint32_t w0l = __byte_perm(El[j], Ol[j], 0x5410);
            uint32_t w1l = __byte_perm(El[j], Ol[j], 0x7632);
            uint32_t off0 = SMEM_SWZ((uint32_t)(d * 128 + vp_pc * 4));
            uint32_t off1 = SMEM_SWZ((uint32_t)((d + 1) * 128 + vp_pc * 4));
            *(uint32_t*)(smc + AS_VHI + vp_panel * 8192 + off0) = w0h;
            *(uint32_t*)(smc + AS_VHI + vp_panel * 8192 + off1) = w1h;
            *(uint32_t*)(smc + AS_VLO + vp_panel * 8192 + off0) = w0l;
            *(uint32_t*)(smc + AS_VLO + vp_panel * 8192 + off1) = w1l;
        }
    };

    // ---- Prologue: Q copy, K(0) copy, V(0) -> regs ----
    #pragma unroll
    for (int i = 0; i < 4; i++) {
        int cg  = tid + (i << 8);
        int row = cg >> 3, ch = cg & 7;
        uint32_t sw = SMEM_SWZ((uint32_t)(row * 128 + ch * 16));
        size_t off = (size_t)(q0 + row) * QLD + (ch << 3);
        cp16(smu + AS_QHI + sw, qh + off);
        cp16(smu + AS_QLO + sw, ql + off);
    }
    CP_COMMIT();
    load_k_tile(0);
    load_v_regs(0);

    float O[32];
    #pragma unroll
    for (int i = 0; i < 32; i++) O[i] = 0.0f;
    float l_run = 0.0f;
    int pt1 = 0, pt2 = 0;

    for (int kb = 0; kb <= qb; kb++) {
        const int k0 = kb << 7;

        // ---- V(kb) regs -> smem (V smem free: MMA2(kb-1) waited) ----
        store_v_smem();
        CP_WAIT0();          // Q (+K up to kb) groups drained
        FENCE_ASYNC();
        __syncthreads();

        // ---- MMA1: S = Q @ K^T ----
        if (wid == 0) {
            TC_FENCE_AFTER();
            if (elect1()) {
                uint64_t dQh = make_desc(smu + AS_QHI);
                uint64_t dQl = make_desc(smu + AS_QLO);
                uint64_t dKh = make_desc(smu + AS_KHI);
                uint64_t dKl = make_desc(smu + AS_KLO);
                bool first = true;
                #pragma unroll
                for (int j = 0; j < 4; j++) {
                    mma_bf16_ss(tmem + TM_S, dQh + j * 2, dKh + j * 2, ATTN_IDESC1, !first);
                    first = false;
                    mma_bf16_ss(tmem + TM_S, dQh + j * 2, dKl + j * 2, ATTN_IDESC1, true);
                    mma_bf16_ss(tmem + TM_S, dQl + j * 2, dKh + j * 2, ATTN_IDESC1, true);
                }
                TC_COMMIT(mb1);
            }
        }
        MBAR_WAIT(mb1, pt1); pt1 ^= 1;
        TC_FENCE_AFTER();

        // ---- Softmax (single pass, m=0) ----
        const int qg = q0 + r;
        float ps = 0.0f;
        #pragma unroll
        for (int c = 0; c < 2; c++) {
            uint32_t u[32];
            LDTM_X32(u, tmem + TM_S + half * 64 + c * 32);
            TC_WAIT_LD();
            const int cb = k0 + half * 64 + c * 32;
            float p[32];
            #pragma unroll
            for (int j = 0; j < 32; j++) {
                float e = exp2f(__uint_as_float(u[j]) * C);
                if (kb == qb && cb + j > qg) e = 0.0f;
                p[j] = e;
                ps += e;
            }
            uint32_t hw[16], lw[16];
            #pragma unroll
            for (int j = 0; j < 16; j++) {
                hw[j] = pk_hi(p[2 * j], p[2 * j + 1]);
                lw[j] = pk_lo(p[2 * j], p[2 * j + 1]);
            }
            STTM_X16(tmem + TM_PHI + half * 32 + c * 16 + warpoff, hw);
            STTM_X16(tmem + TM_PLO + half * 32 + c * 16 + warpoff, lw);
        }
        psums[r * 2 + half] = ps;
        TC_WAIT_ST();
        TC_FENCE_BEFORE();
        __syncthreads();

        if (half == 0)
            l_run += psums[r * 2] + psums[r * 2 + 1];

        // ---- Prefetch K(kb+1) (K smem free: MMA1 done) ----
        if (kb < qb) load_k_tile(k0 + 128);

        // ---- MMA2: U = P @ Vt^T ----
        if (wid == 0) {
            TC_FENCE_AFTER();
            if (elect1()) {
                bool first = true;
                #pragma unroll
                for (int panel = 0; panel < 2; panel++) {
                    uint64_t dVh = make_desc(smu + AS_VHI + panel * 8192);
                    uint64_t dVl = make_desc(smu + AS_VLO + panel * 8192);
                    #pragma unroll
                    for (int j = 0; j < 4; j++) {
                        uint32_t acol = panel * 32 + j * 8;
                        mma_bf16_ts(tmem + TM_S, tmem + TM_PHI + acol, dVh + j * 2, ATTN_IDESC2, !first);
                        first = false;
                        mma_bf16_ts(tmem + TM_S, tmem + TM_PHI + acol, dVl + j * 2, ATTN_IDESC2, true);
                        mma_bf16_ts(tmem + TM_S, tmem + TM_PLO + acol, dVh + j * 2, ATTN_IDESC2, true);
                    }
                }
                TC_COMMIT(mb2);
            }
        }

        // ---- Prefetch V(kb+1) into regs (hides under MMA2) ----
        if (kb < qb) load_v_regs(k0 + 128);

        MBAR_WAIT(mb2, pt2); pt2 ^= 1;
        TC_FENCE_AFTER();

        // ---- O += U ----
        {
            uint32_t u[32];
            LDTM_X32(u, tmem + TM_S + half * 32);
            TC_WAIT_LD();
            #pragma unroll
            for (int j = 0; j < 32; j++)
                O[j] += __uint_as_float(u[j]);
        }
        TC_FENCE_BEFORE();
        __syncthreads();   // all readers of V smem done before next store_v_smem
    }

    // ---- Epilogue: write val bf16 hi/lo ----
    if (half == 0) red[r] = 1.0f / l_run;
    __syncthreads();
    {
        const float inv = red[r];
        const size_t vo = ((size_t)b * SEQ + q0 + r) * DM + h * HD + half * 32;
        float v[32];
        #pragma unroll
        for (int c = 0; c < 32; c++) v[c] = O[c] * inv;
        uint4 hh, ll;
        #pragma unroll
        for (int q = 0; q < 4; q++) {
            hh.x = pk_hi(v[8*q+0], v[8*q+1]); ll.x = pk_lo(v[8*q+0], v[8*q+1]);
            hh.y = pk_hi(v[8*q+2], v[8*q+3]); ll.y = pk_lo(v[8*q+2], v[8*q+3]);
            hh.z = pk_hi(v[8*q+4], v[8*q+5]); ll.z = pk_lo(v[8*q+4], v[8*q+5]);
            hh.w = pk_hi(v[8*q+6], v[8*q+7]); ll.w = pk_lo(v[8*q+6], v[8*q+7]);
            *(uint4*)(g_val_hi + vo + 8*q) = hh;
            *(uint4*)(g_val_lo + vo + 8*q) = ll;
        }
    }
    __syncthreads();
    if (wid == 0) TC_DEALLOC(tmem, 256);

#else  // ------- generic fallback (compile-only on this rig) -------
    extern __shared__ float sm[];
    float* Qs = sm;
    float* Ks = sm + 64 * 68;
    float* Vs = sm + 2 * 64 * 68;
    float* Ps = sm + 3 * 64 * 68;

    const int tid = threadIdx.x;
    const int tx  = tid & 15, ty = tid >> 4;
    const int h = blockIdx.y, b = blockIdx.z;

    const size_t hbase = (size_t)b * SEQ * QLD + h * (3 * HD);

    for (int sub = 0; sub < 2; sub++) {
        const int q0 = (blockIdx.x << 7) + (sub << 6);
        __syncthreads();
        for (int idx = tid; idx < 64 * 64; idx += 256) {
            int rr = idx >> 6, d = idx & 63;
            size_t o = hbase + (size_t)(q0 + rr) * QLD + d;
            Qs[d * 68 + rr] = (__bfloat162float(g_qkv_hi[o]) + __bfloat162float(g_qkv_lo[o])) * 0.125f;
        }

        float m_i[4] = {-3e38f, -3e38f, -3e38f, -3e38f};
        float l_i[4] = {};
        float acc[4][4] = {};
        const int nkb = (q0 >> 6) + 1;

        for (int kb = 0; kb < nkb; kb++) {
            const int k0 = kb << 6;
            __syncthreads();
            for (int idx = tid; idx < 64 * 64; idx += 256) {
                int c = idx >> 6, d = idx & 63;
                size_t ko = hbase + (size_t)(k0 + c) * QLD + HD + d;
                size_t vo = ko + HD;
                Ks[d * 68 + c] = __bfloat162float(g_qkv_hi[ko]) + __bfloat162float(g_qkv_lo[ko]);
                Vs[c * 68 + d] = __bfloat162float(g_qkv_hi[vo]) + __bfloat162float(g_qkv_lo[vo]);
            }
            __syncthreads();

            float s[4][4] = {};
            for (int d = 0; d < 64; d++) {
                float a0 = Qs[d*68+(ty<<2)], a1 = Qs[d*68+(ty<<2)+1];
                float a2 = Qs[d*68+(ty<<2)+2], a3 = Qs[d*68+(ty<<2)+3];
                float b0 = Ks[d*68+(tx<<2)], b1 = Ks[d*68+(tx<<2)+1];
                float b2 = Ks[d*68+(tx<<2)+2], b3 = Ks[d*68+(tx<<2)+3];
                s[0][0]+=a0*b0; s[0][1]+=a0*b1; s[0][2]+=a0*b2; s[0][3]+=a0*b3;
                s[1][0]+=a1*b0; s[1][1]+=a1*b1; s[1][2]+=a1*b2; s[1][3]+=a1*b3;
                s[2][0]+=a2*b0; s[2][1]+=a2*b1; s[2][2]+=a2*b2; s[2][3]+=a2*b3;
                s[3][0]+=a3*b0; s[3][1]+=a3*b1; s[3][2]+=a3*b2; s[3][3]+=a3*b3;
            }
            if (kb == nkb - 1)
                for (int i = 0; i < 4; i++)
                    for (int j = 0; j < 4; j++)
                        if ((tx<<2)+j > (ty<<2)+i) s[i][j] = -1e9f;
            for (int i = 0; i < 4; i++) {
                float mx = fmaxf(fmaxf(s[i][0], s[i][1]), fmaxf(s[i][2], s[i][3]));
                for (int off = 8; off > 0; off >>= 1)
                    mx = fmaxf(mx, __shfl_xor_sync(0xffffffffu, mx, off, 16));
                float mnew = fmaxf(m_i[i], mx);
                float p0 = __expf(s[i][0]-mnew), p1 = __expf(s[i][1]-mnew);
                float p2 = __expf(s[i][2]-mnew), p3 = __expf(s[i][3]-mnew);
                float ls = p0+p1+p2+p3;
                for (int off = 8; off > 0; off >>= 1)
                    ls += __shfl_xor_sync(0xffffffffu, ls, off, 16);
                float alpha = __expf(m_i[i] - mnew);
                l_i[i] = l_i[i]*alpha + ls;
                m_i[i] = mnew;
                acc[i][0]*=alpha; acc[i][1]*=alpha; acc[i][2]*=alpha; acc[i][3]*=alpha;
                s[i][0]=p0; s[i][1]=p1; s[i][2]=p2; s[i][3]=p3;
            }
            for (int i = 0; i < 4; i++)
                for (int j = 0; j < 4; j++)
                    Ps[((tx<<2)+j)*68 + (ty<<2)+i] = s[i][j];
            __syncthreads();
            for (int c = 0; c < 64; c++) {
                float a0 = Ps[c*68+(ty<<2)], a1 = Ps[c*68+(ty<<2)+1];
                float a2 = Ps[c*68+(ty<<2)+2], a3 = Ps[c*68+(ty<<2)+3];
                float b0 = Vs[c*68+(tx<<2)], b1 = Vs[c*68+(tx<<2)+1];
                float b2 = Vs[c*68+(tx<<2)+2], b3 = Vs[c*68+(tx<<2)+3];
                acc[0][0]+=a0*b0; acc[0][1]+=a0*b1; acc[0][2]+=a0*b2; acc[0][3]+=a0*b3;
                acc[1][0]+=a1*b0; acc[1][1]+=a1*b1; acc[1][2]+=a1*b2; acc[1][3]+=a1*b3;
                acc[2][0]+=a2*b0; acc[2][1]+=a2*b1; acc[2][2]+=a2*b2; acc[2][3]+=a2*b3;
                acc[3][0]+=a3*b0; acc[3][1]+=a3*b1; acc[3][2]+=a3*b2; acc[3][3]+=a3*b3;
            }
        }
        for (int i = 0; i < 4; i++) {
            float inv = 1.0f / l_i[i];
            for (int j = 0; j < 4; j++) {
                float v = acc[i][j] * inv;
                size_t o = ((size_t)b * SEQ + q0 + (ty<<2)+i) * DM + h * HD + (tx<<2)+j;
                __nv_bfloat16 hb = __float2bfloat16_rn(v);
                g_val_hi[o] = hb;
                g_val_lo[o] = __float2bfloat16_rn(v - __bfloat162float(hb));
            }
        }
        __syncthreads();
    }
#endif
}

// ---------------------------------------------------------------------------
// Launch
// ---------------------------------------------------------------------------
extern "C" void kernel_launch(void* const* d_in, const int* in_sizes, int n_in,
                              void* d_out, int out_size)
{
    const float* x    = (const float*)d_in[0];
    const float* Wqkv = (const float*)d_in[1];
    const float* bqkv = (const float*)d_in[2];
    const float* Wout = (const float*)d_in[3];
    const float* bout = (const float*)d_in[4];
    float* out = (float*)d_out;

    __nv_bfloat16 *x_hi, *x_lo, *qkv_hi, *qkv_lo, *val_hi, *val_lo;
    __nv_bfloat16 *wq_hi, *wq_lo, *wo_hi, *wo_lo;
    cudaGetSymbolAddress((void**)&x_hi,   g_x_hi);
    cudaGetSymbolAddress((void**)&x_lo,   g_x_lo);
    cudaGetSymbolAddress((void**)&qkv_hi, g_qkv_hi);
    cudaGetSymbolAddress((void**)&qkv_lo, g_qkv_lo);
    cudaGetSymbolAddress((void**)&val_hi, g_val_hi);
    cudaGetSymbolAddress((void**)&val_lo, g_val_lo);
    cudaGetSymbolAddress((void**)&wq_hi,  g_wqkvT_hi);
    cudaGetSymbolAddress((void**)&wq_lo,  g_wqkvT_lo);
    cudaGetSymbolAddress((void**)&wo_hi,  g_woutT_hi);
    cudaGetSymbolAddress((void**)&wo_lo,  g_woutT_lo);

    const int gemm_smem = 1024 + 196608 + 512 + 64;
    const int attn_smem = ATTN_SMEM_BYTES;
    cudaFuncSetAttribute(gemm_bf16pre_kernel,
                         cudaFuncAttributeMaxDynamicSharedMemorySize, gemm_smem);
    cudaFuncSetAttribute(attn_tc_kernel,
                         cudaFuncAttributeMaxDynamicSharedMemorySize, attn_smem);

    // Preludes
    split_f32_kernel<<<(BSROWS * DM) / (256 * 8), 256>>>(x, x_hi, x_lo);
    transpose_split_kernel<<<dim3(QLD / 32, DM / 32), dim3(32, 8)>>>(Wqkv, wq_hi, wq_lo, DM, QLD);
    transpose_split_kernel<<<dim3(DM / 32, DM / 32), dim3(32, 8)>>>(Wout, wo_hi, wo_lo, DM, DM);

    // QKV projection -> bf16 hi/lo qkv
    gemm_bf16pre_kernel<<<dim3(QLD / 128, BSROWS / 128), 256, gemm_smem>>>(
        x_hi, x_lo, wq_hi, wq_lo, bqkv, nullptr, qkv_hi, qkv_lo, BSROWS, QLD, DM);

    // Attention -> bf16 hi/lo val
    attn_tc_kernel<<<dim3(SEQ / 128, NH, BATCH), 256, attn_smem>>>();

    // Output projection -> fp32 out
    gemm_bf16pre_kernel<<<dim3(DM / 128, BSROWS / 128), 256, gemm_smem>>>(
        val_hi, val_lo, wo_hi, wo_lo, bout, out, nullptr, nullptr, BSROWS, DM, DM);
}

// round 14
// speedup vs baseline: 1.0765x; 1.0001x over previous
#include <cuda_runtime.h>
#include <cuda_bf16.h>
#include <cstdint>
#include <math.h>

#define SEQ   2048
#define BATCH 2
#define DM    1024
#define NH    16
#define HD    64
#define BSROWS (BATCH*SEQ)   // 4096
#define QLD   (3*DM)         // 3072

#if defined(__CUDA_ARCH_FEAT_SM103_ALL) || defined(__CUDA_ARCH_FEAT_SM100_ALL) || \
    (defined(__CUDA_ARCH_SPECIFIC__) && (__CUDA_ARCH_SPECIFIC__ >= 1000))
#define HAS_TCGEN05 1
#else
#define HAS_TCGEN05 0
#endif

// ---------------------------------------------------------------------------
// Scratch: everything mid-pipeline is bf16 hi/lo
// ---------------------------------------------------------------------------
__device__ __nv_bfloat16 g_x_hi[(size_t)BSROWS * DM];
__device__ __nv_bfloat16 g_x_lo[(size_t)BSROWS * DM];
__device__ __nv_bfloat16 g_qkv_hi[(size_t)BSROWS * QLD];
__device__ __nv_bfloat16 g_qkv_lo[(size_t)BSROWS * QLD];
__device__ __nv_bfloat16 g_val_hi[(size_t)BSROWS * DM];
__device__ __nv_bfloat16 g_val_lo[(size_t)BSROWS * DM];
__device__ __nv_bfloat16 g_wqkvT_hi[(size_t)QLD * DM];
__device__ __nv_bfloat16 g_wqkvT_lo[(size_t)QLD * DM];
__device__ __nv_bfloat16 g_woutT_hi[(size_t)DM * DM];
__device__ __nv_bfloat16 g_woutT_lo[(size_t)DM * DM];

// ---------------------------------------------------------------------------
// Generic helpers
// ---------------------------------------------------------------------------
__device__ __forceinline__ uint32_t su32(const void* p) {
    return (uint32_t)__cvta_generic_to_shared(p);
}
__device__ __forceinline__ uint32_t pk_hi(float a, float b) {
    __nv_bfloat162 t = __floats2bfloat162_rn(a, b);
    return *(uint32_t*)&t;
}
__device__ __forceinline__ uint32_t pk_lo(float a, float b) {
    float ah = __bfloat162float(__float2bfloat16_rn(a));
    float bh = __bfloat162float(__float2bfloat16_rn(b));
    __nv_bfloat162 t = __floats2bfloat162_rn(a - ah, b - bh);
    return *(uint32_t*)&t;
}
#define SMEM_SWZ(off)   ((off) ^ (((off) >> 3) & 0x70))   // SW128 (128B rows)
#define SMEM_SWZ64(off) ((off) ^ (((off) >> 3) & 0x30))   // SW64  (64B rows)

// cp.async (sm_80+)
__device__ __forceinline__ void cp16(uint32_t dst, const void* src) {
    asm volatile("cp.async.cg.shared.global [%0], [%1], 16;" :: "r"(dst), "l"(src) : "memory");
}
#define CP_COMMIT() asm volatile("cp.async.commit_group;" ::: "memory")
#define CP_WAIT0()  asm volatile("cp.async.wait_group 0;" ::: "memory")
#define CP_WAIT1()  asm volatile("cp.async.wait_group 1;" ::: "memory")

#if HAS_TCGEN05
__device__ __forceinline__ bool elect1() {
    uint32_t r;
    asm volatile("{\n\t.reg .pred p;\n\telect.sync _|p, 0xFFFFFFFF;\n\tselp.b32 %0, 1, 0, p;\n\t}" : "=r"(r));
    return r != 0;
}
#define MBAR_INIT(addr, cnt) \
    asm volatile("mbarrier.init.shared.b64 [%0], %1;" :: "r"(addr), "r"(cnt) : "memory")
#define MBAR_WAIT(addr, ph) do {                                              \
    uint32_t _m = (addr), _p = (ph), _d;                                      \
    asm volatile("{\n\t.reg .pred p;\n\t"                                     \
        "mbarrier.try_wait.parity.acquire.cta.shared::cta.b64 p, [%1], %2;\n\t" \
        "selp.b32 %0, 1, 0, p;\n\t}" : "=r"(_d) : "r"(_m), "r"(_p) : "memory"); \
    if (!_d) {                                                                \
        asm volatile("{\n\t.reg .pred P1;\n\t"                                \
            "WL_%=:\n\t"                                                      \
            "mbarrier.try_wait.parity.acquire.cta.shared::cta.b64 P1, [%0], %1, 0x989680;\n\t" \
            "@P1 bra.uni WD_%=;\n\tbra.uni WL_%=;\n\tWD_%=:\n\t}"             \
            :: "r"(_m), "r"(_p) : "memory");                                  \
    }                                                                         \
} while (0)
#define TC_ALLOC(smem_addr, ncols) \
    asm volatile("tcgen05.alloc.cta_group::1.sync.aligned.shared::cta.b32 [%0], %1;" \
                 :: "r"(smem_addr), "r"(ncols) : "memory")
#define TC_RELINQ() \
    asm volatile("tcgen05.relinquish_alloc_permit.cta_group::1.sync.aligned;")
#define TC_DEALLOC(tmem, ncols) \
    asm volatile("tcgen05.dealloc.cta_group::1.sync.aligned.b32 %0, %1;" :: "r"(tmem), "r"(ncols))
#define TC_COMMIT(mbar) \
    asm volatile("tcgen05.commit.cta_group::1.mbarrier::arrive::one.shared::cluster.b64 [%0];" \
                 :: "r"(mbar) : "memory")
#define TC_FENCE_AFTER()  asm volatile("tcgen05.fence::after_thread_sync;" ::: "memory")
#define TC_FENCE_BEFORE() asm volatile("tcgen05.fence::before_thread_sync;" ::: "memory")
#define TC_WAIT_LD()      asm volatile("tcgen05.wait::ld.sync.aligned;" ::: "memory")
#define TC_WAIT_ST()      asm volatile("tcgen05.wait::st.sync.aligned;" ::: "memory")
#define FENCE_ASYNC()     asm volatile("fence.proxy.async.shared::cta;" ::: "memory")

#define LDTM_X32(r, a) \
    asm volatile("tcgen05.ld.sync.aligned.32x32b.x32.b32 "                    \
        "{%0, %1, %2, %3, %4, %5, %6, %7, %8, %9, %10, %11, %12, %13, %14, %15, " \
        " %16, %17, %18, %19, %20, %21, %22, %23, %24, %25, %26, %27, %28, %29, %30, %31}, [%32];" \
        : "=r"((r)[0]),  "=r"((r)[1]),  "=r"((r)[2]),  "=r"((r)[3]),          \
          "=r"((r)[4]),  "=r"((r)[5]),  "=r"((r)[6]),  "=r"((r)[7]),          \
          "=r"((r)[8]),  "=r"((r)[9]),  "=r"((r)[10]), "=r"((r)[11]),         \
          "=r"((r)[12]), "=r"((r)[13]), "=r"((r)[14]), "=r"((r)[15]),         \
          "=r"((r)[16]), "=r"((r)[17]), "=r"((r)[18]), "=r"((r)[19]),         \
          "=r"((r)[20]), "=r"((r)[21]), "=r"((r)[22]), "=r"((r)[23]),         \
          "=r"((r)[24]), "=r"((r)[25]), "=r"((r)[26]), "=r"((r)[27]),         \
          "=r"((r)[28]), "=r"((r)[29]), "=r"((r)[30]), "=r"((r)[31])          \
        : "r"(a))

#define STTM_X16(a, r) \
    asm volatile("tcgen05.st.sync.aligned.32x32b.x16.b32 [%0], "              \
        "{%1, %2, %3, %4, %5, %6, %7, %8, %9, %10, %11, %12, %13, %14, %15, %16};" \
        :: "r"(a),                                                            \
           "r"((r)[0]),  "r"((r)[1]),  "r"((r)[2]),  "r"((r)[3]),             \
           "r"((r)[4]),  "r"((r)[5]),  "r"((r)[6]),  "r"((r)[7]),             \
           "r"((r)[8]),  "r"((r)[9]),  "r"((r)[10]), "r"((r)[11]),            \
           "r"((r)[12]), "r"((r)[13]), "r"((r)[14]), "r"((r)[15])             \
        : "memory")

// K-major SW128 desc (128B rows): SBO=64, LBO=1
static __device__ __forceinline__ uint64_t make_desc(uint32_t addr) {
    const uint64_t base = (uint64_t(2) << 61) | (uint64_t(1) << 46)
                        | (uint64_t(64) << 32) | (uint64_t(1) << 16);
    return base | ((uint64_t)(addr >> 4) & 0x3FFF);
}
// K-major SW64 desc (64B rows): layout=4, SBO=32, LBO=1 (per ptx_helpers)
static __device__ __forceinline__ uint64_t make_desc_sw64(uint32_t addr) {
    const uint64_t base = (uint64_t(4) << 61) | (uint64_t(1) << 46)
                        | (uint64_t(32) << 32) | (uint64_t(1) << 16);
    return base | ((uint64_t)(addr >> 4) & 0x3FFF);
}
__device__ __forceinline__ void mma_bf16_ss(uint32_t d, uint64_t ad, uint64_t bd,
                                            uint32_t idesc, bool acc) {
    uint32_t en = acc ? 1u : 0u;
    asm volatile(
        "{\n\t.reg .pred p;\n\tsetp.ne.u32 p, %4, 0;\n\t"
        "tcgen05.mma.cta_group::1.kind::f16 [%0], %1, %2, %3, {%5, %5, %5, %5}, p;\n\t}"
        :: "r"(d), "l"(ad), "l"(bd), "r"(idesc), "r"(en), "r"(0u) : "memory");
}
__device__ __forceinline__ void mma_bf16_ts(uint32_t d, uint32_t a, uint64_t bd,
                                            uint32_t idesc, bool acc) {
    uint32_t en = acc ? 1u : 0u;
    asm volatile(
        "{\n\t.reg .pred p;\n\tsetp.ne.u32 p, %4, 0;\n\t"
        "tcgen05.mma.cta_group::1.kind::f16 [%0], [%1], %2, %3, {%5, %5, %5, %5}, p;\n\t}"
        :: "r"(d), "r"(a), "l"(bd), "r"(idesc), "r"(en), "r"(0u) : "memory");
}
#define GEMM_IDESC  ((1u << 4) | (1u << 7) | (1u << 10) | (16u << 17) | (8u << 24))  // M128 N128
#define ATTN_IDESC1 ((1u << 4) | (1u << 7) | (1u << 10) | (16u << 17) | (8u << 24))  // M128 N128
#define ATTN_IDESC2 ((1u << 4) | (1u << 7) | (1u << 10) | (8u  << 17) | (8u << 24))  // M128 N64
#endif  // HAS_TCGEN05

// ---------------------------------------------------------------------------
// Elementwise split: fp32 -> bf16 hi/lo (8 elems/thread)
// ---------------------------------------------------------------------------
__global__ __launch_bounds__(256) void split_f32_kernel(
    const float* __restrict__ X, __nv_bfloat16* __restrict__ Xhi,
    __nv_bfloat16* __restrict__ Xlo)
{
    const size_t i = ((size_t)blockIdx.x * 256 + threadIdx.x) * 8;
    float4 a = *(const float4*)(X + i);
    float4 b = *(const float4*)(X + i + 4);
    uint4 h, l;
    h.x = pk_hi(a.x, a.y); h.y = pk_hi(a.z, a.w);
    h.z = pk_hi(b.x, b.y); h.w = pk_hi(b.z, b.w);
    l.x = pk_lo(a.x, a.y); l.y = pk_lo(a.z, a.w);
    l.z = pk_lo(b.x, b.y); l.w = pk_lo(b.z, b.w);
    *(uint4*)(Xhi + i) = h;
    *(uint4*)(Xlo + i) = l;
}

// ---------------------------------------------------------------------------
// Transpose + bf16 hi/lo split: W[K,N] -> Thi/Tlo[N,K]
// ---------------------------------------------------------------------------
__global__ __launch_bounds__(256) void transpose_split_kernel(
    const float* __restrict__ W, __nv_bfloat16* __restrict__ Thi,
    __nv_bfloat16* __restrict__ Tlo, int K, int N)
{
    __shared__ float t[32][33];
    const int n0 = blockIdx.x << 5, k0 = blockIdx.y << 5;
    const int x = threadIdx.x, y = threadIdx.y;
    #pragma unroll
    for (int i = y; i < 32; i += 8)
        t[i][x] = W[(size_t)(k0 + i) * N + n0 + x];
    __syncthreads();
    #pragma unroll
    for (int i = y; i < 32; i += 8) {
        float v  = t[x][i];
        __nv_bfloat16 hb = __float2bfloat16_rn(v);
        size_t o = (size_t)(n0 + i) * K + k0 + x;
        Thi[o] = hb;
        Tlo[o] = __float2bfloat16_rn(v - __bfloat162float(hb));
    }
}

// ---------------------------------------------------------------------------
// GEMM: cp.async (depth-2, safe tail) + bf16x2 MMA. 128x128 tile, BK=32,
// SW64 panels, 3x32KB buffers -> 2 CTAs/SM.
// ---------------------------------------------------------------------------
#define GSTG 32768
__global__ __launch_bounds__(256, 2)
void gemm_bf16pre_kernel(const __nv_bfloat16* __restrict__ Ahi,
                         const __nv_bfloat16* __restrict__ Alo,
                         const __nv_bfloat16* __restrict__ Bhi,
                         const __nv_bfloat16* __restrict__ Blo,
                         const float* __restrict__ bias,
                         float* __restrict__ Cf,
                         __nv_bfloat16* __restrict__ Chi,
                         __nv_bfloat16* __restrict__ Clo,
                         int M, int N, int K)
{
#if HAS_TCGEN05
    extern __shared__ char dyn[];
    char* tiles = (char*)(((uintptr_t)dyn + 1023) & ~(uintptr_t)1023);
    float*    biass = (float*)(tiles + 3 * GSTG);
    uint64_t* mbar  = (uint64_t*)(tiles + 3 * GSTG + 512);
    uint32_t* tptr  = (uint32_t*)(tiles + 3 * GSTG + 512 + 24);

    const int tid  = threadIdx.x;
    const int wid  = tid >> 5;
    const int lane = tid & 31;
    const int row0 = blockIdx.y << 7, col0 = blockIdx.x << 7;

    const uint32_t tiles_u = su32(tiles);
    const uint32_t mbar_u  = su32(mbar);

    if (tid == 0) { MBAR_INIT(mbar_u, 1); MBAR_INIT(mbar_u + 8, 1); MBAR_INIT(mbar_u + 16, 1); }
    if (wid == 0) { TC_ALLOC(su32(tptr), 128); TC_RELINQ(); }
    if (tid < 128) biass[tid] = bias[col0 + tid];
    __syncthreads();
    const uint32_t tmem = *tptr;

    const int NS = K >> 5;   // BK=32 stages

    // 8 cp16/thread: per operand 512 chunks (128 rows x 4 x 16B), 64B rows SW64
    auto load_stage = [&](int s, int b) {
        uint32_t base = tiles_u + b * GSTG;
        const int koff = s << 5;
        #pragma unroll
        for (int i = 0; i < 2; i++) {
            int cg  = tid + (i << 8);          // 0..511
            int row = cg >> 2, ch = cg & 3;
            uint32_t sw = SMEM_SWZ64((uint32_t)(row * 64 + ch * 16));
            size_t aoff = (size_t)(row0 + row) * K + koff + (ch << 3);
            size_t boff = (size_t)(col0 + row) * K + koff + (ch << 3);
            cp16(base + sw,         Ahi + aoff);
            cp16(base + 8192 + sw,  Alo + aoff);
            cp16(base + 16384 + sw, Bhi + boff);
            cp16(base + 24576 + sw, Blo + boff);
        }
        CP_COMMIT();
    };

    auto issue_stage = [&](int s, int b, bool first) {
        uint32_t a0 = tiles_u + b * GSTG;
        uint64_t dAh = make_desc_sw64(a0);
        uint64_t dAl = make_desc_sw64(a0 + 8192);
        uint64_t dBh = make_desc_sw64(a0 + 16384);
        uint64_t dBl = make_desc_sw64(a0 + 24576);
        #pragma unroll
        for (int j = 0; j < 2; j++) {      // K=16 per MMA, 32B = 2 desc units
            mma_bf16_ss(tmem, dAh + j * 2, dBh + j * 2, GEMM_IDESC, !(first && j == 0));
            mma_bf16_ss(tmem, dAh + j * 2, dBl + j * 2, GEMM_IDESC, true);
            mma_bf16_ss(tmem, dAl + j * 2, dBh + j * 2, GEMM_IDESC, true);
        }
        TC_COMMIT(mbar_u + (uint32_t)(s % 3) * 8);
    };

    load_stage(0, 0);
    load_stage(1, 1);
    CP_WAIT1();
    FENCE_ASYNC();
    __syncthreads();
    if (wid == 0 && elect1()) issue_stage(0, 0, true);

    for (int s = 0; s < NS; s++) {
        if (s >= 1) { int w = s - 1; MBAR_WAIT(mbar_u + (w % 3) * 8, (w / 3) & 1); }
        const bool loaded = (s + 2 < NS);
        if (loaded) load_stage(s + 2, (s + 2) % 3);
        if (s + 1 < NS) {
            if (loaded) CP_WAIT1(); else CP_WAIT0();
            FENCE_ASYNC();
            __syncthreads();
            if (wid == 0 && elect1()) issue_stage(s + 1, (s + 1) % 3, false);
        }
    }
    { int w = NS - 1; MBAR_WAIT(mbar_u + (w % 3) * 8, (w / 3) & 1); }
    CP_WAIT0();

    TC_FENCE_AFTER();
    if (tid < 128) {
        const int er = row0 + wid * 32 + lane;
        #pragma unroll
        for (int c0 = 0; c0 < 128; c0 += 32) {
            uint32_t rg[32];
            LDTM_X32(rg, tmem + c0);
            TC_WAIT_LD();
            float v[32];
            #pragma unroll
            for (int j = 0; j < 32; j++)
                v[j] = __uint_as_float(rg[j]) + biass[c0 + j];
            if (Chi) {
                __nv_bfloat16* ph = Chi + (size_t)er * N + col0 + c0;
                __nv_bfloat16* pl = Clo + (size_t)er * N + col0 + c0;
                #pragma unroll
                for (int q = 0; q < 4; q++) {
                    uint4 hh, ll;
                    hh.x = pk_hi(v[8*q+0], v[8*q+1]); ll.x = pk_lo(v[8*q+0], v[8*q+1]);
                    hh.y = pk_hi(v[8*q+2], v[8*q+3]); ll.y = pk_lo(v[8*q+2], v[8*q+3]);
                    hh.z = pk_hi(v[8*q+4], v[8*q+5]); ll.z = pk_lo(v[8*q+4], v[8*q+5]);
                    hh.w = pk_hi(v[8*q+6], v[8*q+7]); ll.w = pk_lo(v[8*q+6], v[8*q+7]);
                    *(uint4*)(ph + 8*q) = hh;
                    *(uint4*)(pl + 8*q) = ll;
                }
            } else {
                float* cp = Cf + (size_t)er * N + col0 + c0;
                #pragma unroll
                for (int j = 0; j < 8; j++) {
                    float4 o;
                    o.x = v[4*j+0]; o.y = v[4*j+1]; o.z = v[4*j+2]; o.w = v[4*j+3];
                    *(float4*)(cp + 4 * j) = o;
                }
            }
        }
    }
    __syncthreads();
    if (wid == 0) TC_DEALLOC(tmem, 128);

#else  // ------- generic fallback (compile-only on this rig) -------
    extern __shared__ char dyn[];
    float* As = (float*)dyn;
    float* Bs = As + 16 * 132;

    const int tid = threadIdx.x;
    const int tx  = tid & 15, ty = tid >> 4;
    const int row0 = blockIdx.y << 7, col0 = blockIdx.x << 7;

    float acc[8][8] = {};
    for (int k0 = 0; k0 < K; k0 += 16) {
        __syncthreads();
        #pragma unroll
        for (int t = 0; t < 2; t++) {
            int ch = tid + (t << 8);
            int rr = ch >> 2, c4 = (ch & 3) << 2;
            size_t ao = (size_t)(row0 + rr) * K + k0 + c4;
            size_t bo = (size_t)(col0 + rr) * K + k0 + c4;
            #pragma unroll
            for (int q = 0; q < 4; q++) {
                As[(c4 + q) * 132 + rr] = __bfloat162float(Ahi[ao + q]) + __bfloat162float(Alo[ao + q]);
                Bs[(c4 + q) * 132 + rr] = __bfloat162float(Bhi[bo + q]) + __bfloat162float(Blo[bo + q]);
            }
        }
        __syncthreads();
        #pragma unroll
        for (int kk = 0; kk < 16; kk++) {
            float a[8], b[8];
            #pragma unroll
            for (int i = 0; i < 8; i++) a[i] = As[kk * 132 + ty * 8 + i];
            #pragma unroll
            for (int j = 0; j < 8; j++) b[j] = Bs[kk * 132 + tx * 8 + j];
            #pragma unroll
            for (int i = 0; i < 8; i++)
                #pragma unroll
                for (int j = 0; j < 8; j++) acc[i][j] += a[i] * b[j];
        }
    }
    #pragma unroll
    for (int i = 0; i < 8; i++)
        #pragma unroll
        for (int j = 0; j < 8; j++) {
            float v = acc[i][j] + bias[col0 + tx * 8 + j];
            size_t o = (size_t)(row0 + ty * 8 + i) * N + col0 + tx * 8 + j;
            if (Chi) {
                __nv_bfloat16 hb = __float2bfloat16_rn(v);
                Chi[o] = hb;
                Clo[o] = __float2bfloat16_rn(v - __bfloat162float(hb));
            } else {
                Cf[o] = v;
            }
        }
#endif
}

// ---------------------------------------------------------------------------
// Attention (unchanged from R13): bf16x2 tcgen05, m=0 softmax, pipelined loads
// ---------------------------------------------------------------------------
#define AS_QHI  0
#define AS_QLO  16384
#define AS_KHI  32768
#define AS_KLO  49152
#define AS_VHI  65536
#define AS_VLO  81920
#define AS_PSUM 98304
#define AS_RED  99328
#define AS_MBAR 99840
#define AS_TPTR 99856
#define ATTN_SMEM_BYTES (1024 + 99872)

#define TM_S    0
#define TM_PHI  128
#define TM_PLO  192

__global__ __launch_bounds__(256, 2) void attn_tc_kernel()
{
#if HAS_TCGEN05
    extern __shared__ char dyn[];
    char* smc = (char*)(((uintptr_t)dyn + 1023) & ~(uintptr_t)1023);
    const uint32_t smu = su32(smc);

    const int tid  = threadIdx.x;
    const int wid  = tid >> 5;
    const int lane = tid & 31;
    const int sp   = wid & 3;
    const int half = wid >> 2;
    const int qb   = (gridDim.x - 1) - blockIdx.x;   // big tiles first
    const int h = blockIdx.y, b = blockIdx.z;
    const int q0   = qb << 7;
    const int r    = sp * 32 + lane;

    const size_t hbase = (size_t)b * SEQ * QLD + h * (3 * HD);
    const __nv_bfloat16* qh = g_qkv_hi + hbase;
    const __nv_bfloat16* ql = g_qkv_lo + hbase;
    const __nv_bfloat16* kh = qh + HD;
    const __nv_bfloat16* kl = ql + HD;
    const __nv_bfloat16* vh = qh + 2 * HD;
    const __nv_bfloat16* vl = ql + 2 * HD;

    float* psums = (float*)(smc + AS_PSUM);
    float* red   = (float*)(smc + AS_RED);
    const uint32_t mb1 = smu + AS_MBAR;
    const uint32_t mb2 = smu + AS_MBAR + 8;

    if (tid == 0) { MBAR_INIT(mb1, 1); MBAR_INIT(mb2, 1); }
    if (wid == 0) { TC_ALLOC(smu + AS_TPTR, 256); TC_RELINQ(); }
    __syncthreads();
    const uint32_t tmem = *(uint32_t*)(smc + AS_TPTR);
    const uint32_t warpoff = (uint32_t)sp << 21;

    const float C = 0.125f * 1.44269504f;

    auto load_k_tile = [&](int k0) {
        #pragma unroll
        for (int i = 0; i < 4; i++) {
            int cg  = tid + (i << 8);
            int row = cg >> 3, ch = cg & 7;
            uint32_t sw = SMEM_SWZ((uint32_t)(row * 128 + ch * 16));
            size_t off = (size_t)(k0 + row) * QLD + (ch << 3);
            cp16(smu + AS_KHI + sw, kh + off);
            cp16(smu + AS_KLO + sw, kl + off);
        }
        CP_COMMIT();
    };

    const int vp_p  = tid & 63;
    const int vp_dh = tid >> 6;
    const int vp_panel = vp_p >> 5;
    const int vp_pc    = vp_p & 31;

    uint32_t E[8], Od[8], El[8], Ol[8];
    auto load_v_regs = [&](int k0) {
        const size_t e_off = (size_t)(k0 + 2 * vp_p) * QLD + (vp_dh << 4);
        const size_t o_off = e_off + QLD;
        *(uint4*)&E[0]  = *(const uint4*)(vh + e_off);
        *(uint4*)&E[4]  = *(const uint4*)(vh + e_off + 8);
        *(uint4*)&Od[0] = *(const uint4*)(vh + o_off);
        *(uint4*)&Od[4] = *(const uint4*)(vh + o_off + 8);
        *(uint4*)&El[0] = *(const uint4*)(vl + e_off);
        *(uint4*)&El[4] = *(const uint4*)(vl + e_off + 8);
        *(uint4*)&Ol[0] = *(const uint4*)(vl + o_off);
        *(uint4*)&Ol[4] = *(const uint4*)(vl + o_off + 8);
    };
    auto store_v_smem = [&]() {
        #pragma unroll
        for (int j = 0; j < 8; j++) {
            int d = (vp_dh << 4) + 2 * j;
            uint32_t w0h = __byte_perm(E[j],  Od[j], 0x5410);
            uint32_t w1h = __byte_perm(E[j],  Od[j], 0x7632);
            uint32_t w0l = __byte_perm(El[j], Ol[j], 0x5410);
            uint32_t w1l = __byte_perm(El[j], Ol[j], 0x7632);
            uint32_t off0 = SMEM_SWZ((uint32_t)(d * 128 + vp_pc * 4));
            uint32_t off1 = SMEM_SWZ((uint32_t)((d + 1) * 128 + vp_pc * 4));
            *(uint32_t*)(smc + AS_VHI + vp_panel * 8192 + off0) = w0h;
            *(uint32_t*)(smc + AS_VHI + vp_panel * 8192 + off1) = w1h;
            *(uint32_t*)(smc + AS_VLO + vp_panel * 8192 + off0) = w0l;
            *(uint32_t*)(smc + AS_VLO + vp_panel * 8192 + off1) = w1l;
        }
    };

    // ---- Prologue: Q copy, K(0) copy, V(0) -> regs ----
    #pragma unroll
    for (int i = 0; i < 4; i++) {
        int cg  = tid + (i << 8);
        int row = cg >> 3, ch = cg & 7;
        uint32_t sw = SMEM_SWZ((uint32_t)(row * 128 + ch * 16));
        size_t off = (size_t)(q0 + row) * QLD + (ch << 3);
        cp16(smu + AS_QHI + sw, qh + off);
        cp16(smu + AS_QLO + sw, ql + off);
    }
    CP_COMMIT();
    load_k_tile(0);
    load_v_regs(0);

    float O[32];
    #pragma unroll
    for (int i = 0; i < 32; i++) O[i] = 0.0f;
    float l_run = 0.0f;
    int pt1 = 0, pt2 = 0;

    for (int kb = 0; kb <= qb; kb++) {
        const int k0 = kb << 7;

        store_v_smem();
        CP_WAIT0();
        FENCE_ASYNC();
        __syncthreads();

        // ---- MMA1: S = Q @ K^T ----
        if (wid == 0) {
            TC_FENCE_AFTER();
            if (elect1()) {
                uint64_t dQh = make_desc(smu + AS_QHI);
                uint64_t dQl = make_desc(smu + AS_QLO);
                uint64_t dKh = make_desc(smu + AS_KHI);
                uint64_t dKl = make_desc(smu + AS_KLO);
                bool first = true;
                #pragma unroll
                for (int j = 0; j < 4; j++) {
                    mma_bf16_ss(tmem + TM_S, dQh + j * 2, dKh + j * 2, ATTN_IDESC1, !first);
                    first = false;
                    mma_bf16_ss(tmem + TM_S, dQh + j * 2, dKl + j * 2, ATTN_IDESC1, true);
                    mma_bf16_ss(tmem + TM_S, dQl + j * 2, dKh + j * 2, ATTN_IDESC1, true);
                }
                TC_COMMIT(mb1);
            }
        }
        MBAR_WAIT(mb1, pt1); pt1 ^= 1;
        TC_FENCE_AFTER();

        // ---- Softmax (single pass, m=0) ----
        const int qg = q0 + r;
        float ps = 0.0f;
        #pragma unroll
        for (int c = 0; c < 2; c++) {
            uint32_t u[32];
            LDTM_X32(u, tmem + TM_S + half * 64 + c * 32);
            TC_WAIT_LD();
            const int cb = k0 + half * 64 + c * 32;
            float p[32];
            #pragma unroll
            for (int j = 0; j < 32; j++) {
                float e = exp2f(__uint_as_float(u[j]) * C);
                if (kb == qb && cb + j > qg) e = 0.0f;
                p[j] = e;
                ps += e;
            }
            uint32_t hw[16], lw[16];
            #pragma unroll
            for (int j = 0; j < 16; j++) {
                hw[j] = pk_hi(p[2 * j], p[2 * j + 1]);
                lw[j] = pk_lo(p[2 * j], p[2 * j + 1]);
            }
            STTM_X16(tmem + TM_PHI + half * 32 + c * 16 + warpoff, hw);
            STTM_X16(tmem + TM_PLO + half * 32 + c * 16 + warpoff, lw);
        }
        psums[r * 2 + half] = ps;
        TC_WAIT_ST();
        TC_FENCE_BEFORE();
        __syncthreads();

        if (half == 0)
            l_run += psums[r * 2] + psums[r * 2 + 1];

        if (kb < qb) load_k_tile(k0 + 128);

        // ---- MMA2: U = P @ Vt^T ----
        if (wid == 0) {
            TC_FENCE_AFTER();
            if (elect1()) {
                bool first = true;
                #pragma unroll
                for (int panel = 0; panel < 2; panel++) {
                    uint64_t dVh = make_desc(smu + AS_VHI + panel * 8192);
                    uint64_t dVl = make_desc(smu + AS_VLO + panel * 8192);
                    #pragma unroll
                    for (int j = 0; j < 4; j++) {
                        uint32_t acol = panel * 32 + j * 8;
                        mma_bf16_ts(tmem + TM_S, tmem + TM_PHI + acol, dVh + j * 2, ATTN_IDESC2, !first);
                        first = false;
                        mma_bf16_ts(tmem + TM_S, tmem + TM_PHI + acol, dVl + j * 2, ATTN_IDESC2, true);
                        mma_bf16_ts(tmem + TM_S, tmem + TM_PLO + acol, dVh + j * 2, ATTN_IDESC2, true);
                    }
                }
                TC_COMMIT(mb2);
            }
        }

        if (kb < qb) load_v_regs(k0 + 128);

        MBAR_WAIT(mb2, pt2); pt2 ^= 1;
        TC_FENCE_AFTER();

        // ---- O += U ----
        {
            uint32_t u[32];
            LDTM_X32(u, tmem + TM_S + half * 32);
            TC_WAIT_LD();
            #pragma unroll
            for (int j = 0; j < 32; j++)
                O[j] += __uint_as_float(u[j]);
        }
        TC_FENCE_BEFORE();
        __syncthreads();
    }

    // ---- Epilogue: write val bf16 hi/lo ----
    if (half == 0) red[r] = 1.0f / l_run;
    __syncthreads();
    {
        const float inv = red[r];
        const size_t vo = ((size_t)b * SEQ + q0 + r) * DM + h * HD + half * 32;
        float v[32];
        #pragma unroll
        for (int c = 0; c < 32; c++) v[c] = O[c] * inv;
        uint4 hh, ll;
        #pragma unroll
        for (int q = 0; q < 4; q++) {
            hh.x = pk_hi(v[8*q+0], v[8*q+1]); ll.x = pk_lo(v[8*q+0], v[8*q+1]);
            hh.y = pk_hi(v[8*q+2], v[8*q+3]); ll.y = pk_lo(v[8*q+2], v[8*q+3]);
            hh.z = pk_hi(v[8*q+4], v[8*q+5]); ll.z = pk_lo(v[8*q+4], v[8*q+5]);
            hh.w = pk_hi(v[8*q+6], v[8*q+7]); ll.w = pk_lo(v[8*q+6], v[8*q+7]);
            *(uint4*)(g_val_hi + vo + 8*q) = hh;
            *(uint4*)(g_val_lo + vo + 8*q) = ll;
        }
    }
    __syncthreads();
    if (wid == 0) TC_DEALLOC(tmem, 256);

#else  // ------- generic fallback (compile-only on this rig) -------
    extern __shared__ float sm[];
    float* Qs = sm;
    float* Ks = sm + 64 * 68;
    float* Vs = sm + 2 * 64 * 68;
    float* Ps = sm + 3 * 64 * 68;

    const int tid = threadIdx.x;
    const int tx  = tid & 15, ty = tid >> 4;
    const int h = blockIdx.y, b = blockIdx.z;

    const size_t hbase = (size_t)b * SEQ * QLD + h * (3 * HD);

    for (int sub = 0; sub < 2; sub++) {
        const int q0 = (blockIdx.x << 7) + (sub << 6);
        __syncthreads();
        for (int idx = tid; idx < 64 * 64; idx += 256) {
            int rr = idx >> 6, d = idx & 63;
            size_t o = hbase + (size_t)(q0 + rr) * QLD + d;
            Qs[d * 68 + rr] = (__bfloat162float(g_qkv_hi[o]) + __bfloat162float(g_qkv_lo[o])) * 0.125f;
        }

        float m_i[4] = {-3e38f, -3e38f, -3e38f, -3e38f};
        float l_i[4] = {};
        float acc[4][4] = {};
        const int nkb = (q0 >> 6) + 1;

        for (int kb = 0; kb < nkb; kb++) {
            const int k0 = kb << 6;
            __syncthreads();
            for (int idx = tid; idx < 64 * 64; idx += 256) {
                int c = idx >> 6, d = idx & 63;
                size_t ko = hbase + (size_t)(k0 + c) * QLD + HD + d;
                size_t vo = ko + HD;
                Ks[d * 68 + c] = __bfloat162float(g_qkv_hi[ko]) + __bfloat162float(g_qkv_lo[ko]);
                Vs[c * 68 + d] = __bfloat162float(g_qkv_hi[vo]) + __bfloat162float(g_qkv_lo[vo]);
            }
            __syncthreads();

            float s[4][4] = {};
            for (int d = 0; d < 64; d++) {
                float a0 = Qs[d*68+(ty<<2)], a1 = Qs[d*68+(ty<<2)+1];
                float a2 = Qs[d*68+(ty<<2)+2], a3 = Qs[d*68+(ty<<2)+3];
                float b0 = Ks[d*68+(tx<<2)], b1 = Ks[d*68+(tx<<2)+1];
                float b2 = Ks[d*68+(tx<<2)+2], b3 = Ks[d*68+(tx<<2)+3];
                s[0][0]+=a0*b0; s[0][1]+=a0*b1; s[0][2]+=a0*b2; s[0][3]+=a0*b3;
                s[1][0]+=a1*b0; s[1][1]+=a1*b1; s[1][2]+=a1*b2; s[1][3]+=a1*b3;
                s[2][0]+=a2*b0; s[2][1]+=a2*b1; s[2][2]+=a2*b2; s[2][3]+=a2*b3;
                s[3][0]+=a3*b0; s[3][1]+=a3*b1; s[3][2]+=a3*b2; s[3][3]+=a3*b3;
            }
            if (kb == nkb - 1)
                for (int i = 0; i < 4; i++)
                    for (int j = 0; j < 4; j++)
                        if ((tx<<2)+j > (ty<<2)+i) s[i][j] = -1e9f;
            for (int i = 0; i < 4; i++) {
                float mx = fmaxf(fmaxf(s[i][0], s[i][1]), fmaxf(s[i][2], s[i][3]));
                for (int off = 8; off > 0; off >>= 1)
                    mx = fmaxf(mx, __shfl_xor_sync(0xffffffffu, mx, off, 16));
                float mnew = fmaxf(m_i[i], mx);
                float p0 = __expf(s[i][0]-mnew), p1 = __expf(s[i][1]-mnew);
                float p2 = __expf(s[i][2]-mnew), p3 = __expf(s[i][3]-mnew);
                float ls = p0+p1+p2+p3;
                for (int off = 8; off > 0; off >>= 1)
                    ls += __shfl_xor_sync(0xffffffffu, ls, off, 16);
                float alpha = __expf(m_i[i] - mnew);
                l_i[i] = l_i[i]*alpha + ls;
                m_i[i] = mnew;
                acc[i][0]*=alpha; acc[i][1]*=alpha; acc[i][2]*=alpha; acc[i][3]*=alpha;
                s[i][0]=p0; s[i][1]=p1; s[i][2]=p2; s[i][3]=p3;
            }
            for (int i = 0; i < 4; i++)
                for (int j = 0; j < 4; j++)
                    Ps[((tx<<2)+j)*68 + (ty<<2)+i] = s[i][j];
            __syncthreads();
            for (int c = 0; c < 64; c++) {
                float a0 = Ps[c*68+(ty<<2)], a1 = Ps[c*68+(ty<<2)+1];
                float a2 = Ps[c*68+(ty<<2)+2], a3 = Ps[c*68+(ty<<2)+3];
                float b0 = Vs[c*68+(tx<<2)], b1 = Vs[c*68+(tx<<2)+1];
                float b2 = Vs[c*68+(tx<<2)+2], b3 = Vs[c*68+(tx<<2)+3];
                acc[0][0]+=a0*b0; acc[0][1]+=a0*b1; acc[0][2]+=a0*b2; acc[0][3]+=a0*b3;
                acc[1][0]+=a1*b0; acc[1][1]+=a1*b1; acc[1][2]+=a1*b2; acc[1][3]+=a1*b3;
                acc[2][0]+=a2*b0; acc[2][1]+=a2*b1; acc[2][2]+=a2*b2; acc[2][3]+=a2*b3;
                acc[3][0]+=a3*b0; acc[3][1]+=a3*b1; acc[3][2]+=a3*b2; acc[3][3]+=a3*b3;
            }
        }
        for (int i = 0; i < 4; i++) {
            float inv = 1.0f / l_i[i];
            for (int j = 0; j < 4; j++) {
                float v = acc[i][j] * inv;
                size_t o = ((size_t)b * SEQ + q0 + (ty<<2)+i) * DM + h * HD + (tx<<2)+j;
                __nv_bfloat16 hb = __float2bfloat16_rn(v);
                g_val_hi[o] = hb;
                g_val_lo[o] = __float2bfloat16_rn(v - __bfloat162float(hb));
            }
        }
        __syncthreads();
    }
#endif
}

// ---------------------------------------------------------------------------
// Launch
// ---------------------------------------------------------------------------
extern "C" void kernel_launch(void* const* d_in, const int* in_sizes, int n_in,
                              void* d_out, int out_size)
{
    const float* x    = (const float*)d_in[0];
    const float* Wqkv = (const float*)d_in[1];
    const float* bqkv = (const float*)d_in[2];
    const float* Wout = (const float*)d_in[3];
    const float* bout = (const float*)d_in[4];
    float* out = (float*)d_out;

    __nv_bfloat16 *x_hi, *x_lo, *qkv_hi, *qkv_lo, *val_hi, *val_lo;
    __nv_bfloat16 *wq_hi, *wq_lo, *wo_hi, *wo_lo;
    cudaGetSymbolAddress((void**)&x_hi,   g_x_hi);
    cudaGetSymbolAddress((void**)&x_lo,   g_x_lo);
    cudaGetSymbolAddress((void**)&qkv_hi, g_qkv_hi);
    cudaGetSymbolAddress((void**)&qkv_lo, g_qkv_lo);
    cudaGetSymbolAddress((void**)&val_hi, g_val_hi);
    cudaGetSymbolAddress((void**)&val_lo, g_val_lo);
    cudaGetSymbolAddress((void**)&wq_hi,  g_wqkvT_hi);
    cudaGetSymbolAddress((void**)&wq_lo,  g_wqkvT_lo);
    cudaGetSymbolAddress((void**)&wo_hi,  g_woutT_hi);
    cudaGetSymbolAddress((void**)&wo_lo,  g_woutT_lo);

    const int gemm_smem = 1024 + 3 * GSTG + 512 + 64;   // ~100 KB -> 2 CTAs/SM
    const int attn_smem = ATTN_SMEM_BYTES;
    cudaFuncSetAttribute(gemm_bf16pre_kernel,
                         cudaFuncAttributeMaxDynamicSharedMemorySize, gemm_smem);
    cudaFuncSetAttribute(attn_tc_kernel,
                         cudaFuncAttributeMaxDynamicSharedMemorySize, attn_smem);

    // Preludes
    split_f32_kernel<<<(BSROWS * DM) / (256 * 8), 256>>>(x, x_hi, x_lo);
    transpose_split_kernel<<<dim3(QLD / 32, DM / 32), dim3(32, 8)>>>(Wqkv, wq_hi, wq_lo, DM, QLD);
    transpose_split_kernel<<<dim3(DM / 32, DM / 32), dim3(32, 8)>>>(Wout, wo_hi, wo_lo, DM, DM);

    // QKV projection -> bf16 hi/lo qkv
    gemm_bf16pre_kernel<<<dim3(QLD / 128, BSROWS / 128), 256, gemm_smem>>>(
        x_hi, x_lo, wq_hi, wq_lo, bqkv, nullptr, qkv_hi, qkv_lo, BSROWS, QLD, DM);

    // Attention -> bf16 hi/lo val
    attn_tc_kernel<<<dim3(SEQ / 128, NH, BATCH), 256, attn_smem>>>();

    // Output projection -> fp32 out
    gemm_bf16pre_kernel<<<dim3(DM / 128, BSROWS / 128), 256, gemm_smem>>>(
        val_hi, val_lo, wo_hi, wo_lo, bout, out, nullptr, nullptr, BSROWS, DM, DM);
}

// round 15
// speedup vs baseline: 1.1113x; 1.0324x over previous
#include <cuda_runtime.h>
#include <cuda_bf16.h>
#include <cstdint>
#include <math.h>

#define SEQ   2048
#define BATCH 2
#define DM    1024
#define NH    16
#define HD    64
#define BSROWS (BATCH*SEQ)   // 4096
#define QLD   (3*DM)         // 3072

#if defined(__CUDA_ARCH_FEAT_SM103_ALL) || defined(__CUDA_ARCH_FEAT_SM100_ALL) || \
    (defined(__CUDA_ARCH_SPECIFIC__) && (__CUDA_ARCH_SPECIFIC__ >= 1000))
#define HAS_TCGEN05 1
#else
#define HAS_TCGEN05 0
#endif

// ---------------------------------------------------------------------------
// Scratch: everything mid-pipeline is bf16 hi/lo
// ---------------------------------------------------------------------------
__device__ __nv_bfloat16 g_x_hi[(size_t)BSROWS * DM];
__device__ __nv_bfloat16 g_x_lo[(size_t)BSROWS * DM];
__device__ __nv_bfloat16 g_qkv_hi[(size_t)BSROWS * QLD];
__device__ __nv_bfloat16 g_qkv_lo[(size_t)BSROWS * QLD];
__device__ __nv_bfloat16 g_val_hi[(size_t)BSROWS * DM];
__device__ __nv_bfloat16 g_val_lo[(size_t)BSROWS * DM];
__device__ __nv_bfloat16 g_wqkvT_hi[(size_t)QLD * DM];
__device__ __nv_bfloat16 g_wqkvT_lo[(size_t)QLD * DM];
__device__ __nv_bfloat16 g_woutT_hi[(size_t)DM * DM];
__device__ __nv_bfloat16 g_woutT_lo[(size_t)DM * DM];

// ---------------------------------------------------------------------------
// Generic helpers
// ---------------------------------------------------------------------------
__device__ __forceinline__ uint32_t su32(const void* p) {
    return (uint32_t)__cvta_generic_to_shared(p);
}
__device__ __forceinline__ uint32_t pk_hi(float a, float b) {
    __nv_bfloat162 t = __floats2bfloat162_rn(a, b);
    return *(uint32_t*)&t;
}
__device__ __forceinline__ uint32_t pk_lo(float a, float b) {
    float ah = __bfloat162float(__float2bfloat16_rn(a));
    float bh = __bfloat162float(__float2bfloat16_rn(b));
    __nv_bfloat162 t = __floats2bfloat162_rn(a - ah, b - bh);
    return *(uint32_t*)&t;
}
#define SMEM_SWZ(off)   ((off) ^ (((off) >> 3) & 0x70))   // SW128 (128B rows)
#define SMEM_SWZ64(off) ((off) ^ (((off) >> 3) & 0x30))   // SW64  (64B rows)

// cp.async (sm_80+)
__device__ __forceinline__ void cp16(uint32_t dst, const void* src) {
    asm volatile("cp.async.cg.shared.global [%0], [%1], 16;" :: "r"(dst), "l"(src) : "memory");
}
#define CP_COMMIT() asm volatile("cp.async.commit_group;" ::: "memory")
#define CP_WAIT0()  asm volatile("cp.async.wait_group 0;" ::: "memory")
#define CP_WAIT1()  asm volatile("cp.async.wait_group 1;" ::: "memory")

#if HAS_TCGEN05
__device__ __forceinline__ bool elect1() {
    uint32_t r;
    asm volatile("{\n\t.reg .pred p;\n\telect.sync _|p, 0xFFFFFFFF;\n\tselp.b32 %0, 1, 0, p;\n\t}" : "=r"(r));
    return r != 0;
}
#define MBAR_INIT(addr, cnt) \
    asm volatile("mbarrier.init.shared.b64 [%0], %1;" :: "r"(addr), "r"(cnt) : "memory")
#define MBAR_WAIT(addr, ph) do {                                              \
    uint32_t _m = (addr), _p = (ph), _d;                                      \
    asm volatile("{\n\t.reg .pred p;\n\t"                                     \
        "mbarrier.try_wait.parity.acquire.cta.shared::cta.b64 p, [%1], %2;\n\t" \
        "selp.b32 %0, 1, 0, p;\n\t}" : "=r"(_d) : "r"(_m), "r"(_p) : "memory"); \
    if (!_d) {                                                                \
        asm volatile("{\n\t.reg .pred P1;\n\t"                                \
            "WL_%=:\n\t"                                                      \
            "mbarrier.try_wait.parity.acquire.cta.shared::cta.b64 P1, [%0], %1, 0x989680;\n\t" \
            "@P1 bra.uni WD_%=;\n\tbra.uni WL_%=;\n\tWD_%=:\n\t}"             \
            :: "r"(_m), "r"(_p) : "memory");                                  \
    }                                                                         \
} while (0)
#define TC_ALLOC(smem_addr, ncols) \
    asm volatile("tcgen05.alloc.cta_group::1.sync.aligned.shared::cta.b32 [%0], %1;" \
                 :: "r"(smem_addr), "r"(ncols) : "memory")
#define TC_RELINQ() \
    asm volatile("tcgen05.relinquish_alloc_permit.cta_group::1.sync.aligned;")
#define TC_DEALLOC(tmem, ncols) \
    asm volatile("tcgen05.dealloc.cta_group::1.sync.aligned.b32 %0, %1;" :: "r"(tmem), "r"(ncols))
#define TC_COMMIT(mbar) \
    asm volatile("tcgen05.commit.cta_group::1.mbarrier::arrive::one.shared::cluster.b64 [%0];" \
                 :: "r"(mbar) : "memory")
#define TC_FENCE_AFTER()  asm volatile("tcgen05.fence::after_thread_sync;" ::: "memory")
#define TC_FENCE_BEFORE() asm volatile("tcgen05.fence::before_thread_sync;" ::: "memory")
#define TC_WAIT_LD()      asm volatile("tcgen05.wait::ld.sync.aligned;" ::: "memory")
#define TC_WAIT_ST()      asm volatile("tcgen05.wait::st.sync.aligned;" ::: "memory")
#define FENCE_ASYNC()     asm volatile("fence.proxy.async.shared::cta;" ::: "memory")

#define LDTM_X32(r, a) \
    asm volatile("tcgen05.ld.sync.aligned.32x32b.x32.b32 "                    \
        "{%0, %1, %2, %3, %4, %5, %6, %7, %8, %9, %10, %11, %12, %13, %14, %15, " \
        " %16, %17, %18, %19, %20, %21, %22, %23, %24, %25, %26, %27, %28, %29, %30, %31}, [%32];" \
        : "=r"((r)[0]),  "=r"((r)[1]),  "=r"((r)[2]),  "=r"((r)[3]),          \
          "=r"((r)[4]),  "=r"((r)[5]),  "=r"((r)[6]),  "=r"((r)[7]),          \
          "=r"((r)[8]),  "=r"((r)[9]),  "=r"((r)[10]), "=r"((r)[11]),         \
          "=r"((r)[12]), "=r"((r)[13]), "=r"((r)[14]), "=r"((r)[15]),         \
          "=r"((r)[16]), "=r"((r)[17]), "=r"((r)[18]), "=r"((r)[19]),         \
          "=r"((r)[20]), "=r"((r)[21]), "=r"((r)[22]), "=r"((r)[23]),         \
          "=r"((r)[24]), "=r"((r)[25]), "=r"((r)[26]), "=r"((r)[27]),         \
          "=r"((r)[28]), "=r"((r)[29]), "=r"((r)[30]), "=r"((r)[31])          \
        : "r"(a))

#define STTM_X16(a, r) \
    asm volatile("tcgen05.st.sync.aligned.32x32b.x16.b32 [%0], "              \
        "{%1, %2, %3, %4, %5, %6, %7, %8, %9, %10, %11, %12, %13, %14, %15, %16};" \
        :: "r"(a),                                                            \
           "r"((r)[0]),  "r"((r)[1]),  "r"((r)[2]),  "r"((r)[3]),             \
           "r"((r)[4]),  "r"((r)[5]),  "r"((r)[6]),  "r"((r)[7]),             \
           "r"((r)[8]),  "r"((r)[9]),  "r"((r)[10]), "r"((r)[11]),            \
           "r"((r)[12]), "r"((r)[13]), "r"((r)[14]), "r"((r)[15])             \
        : "memory")

// K-major SW128 desc (128B rows): SBO=64, LBO=1
static __device__ __forceinline__ uint64_t make_desc(uint32_t addr) {
    const uint64_t base = (uint64_t(2) << 61) | (uint64_t(1) << 46)
                        | (uint64_t(64) << 32) | (uint64_t(1) << 16);
    return base | ((uint64_t)(addr >> 4) & 0x3FFF);
}
// K-major SW64 desc (64B rows): layout=4, SBO=32, LBO=1
static __device__ __forceinline__ uint64_t make_desc_sw64(uint32_t addr) {
    const uint64_t base = (uint64_t(4) << 61) | (uint64_t(1) << 46)
                        | (uint64_t(32) << 32) | (uint64_t(1) << 16);
    return base | ((uint64_t)(addr >> 4) & 0x3FFF);
}
__device__ __forceinline__ void mma_bf16_ss(uint32_t d, uint64_t ad, uint64_t bd,
                                            uint32_t idesc, bool acc) {
    uint32_t en = acc ? 1u : 0u;
    asm volatile(
        "{\n\t.reg .pred p;\n\tsetp.ne.u32 p, %4, 0;\n\t"
        "tcgen05.mma.cta_group::1.kind::f16 [%0], %1, %2, %3, {%5, %5, %5, %5}, p;\n\t}"
        :: "r"(d), "l"(ad), "l"(bd), "r"(idesc), "r"(en), "r"(0u) : "memory");
}
__device__ __forceinline__ void mma_bf16_ts(uint32_t d, uint32_t a, uint64_t bd,
                                            uint32_t idesc, bool acc) {
    uint32_t en = acc ? 1u : 0u;
    asm volatile(
        "{\n\t.reg .pred p;\n\tsetp.ne.u32 p, %4, 0;\n\t"
        "tcgen05.mma.cta_group::1.kind::f16 [%0], [%1], %2, %3, {%5, %5, %5, %5}, p;\n\t}"
        :: "r"(d), "r"(a), "l"(bd), "r"(idesc), "r"(en), "r"(0u) : "memory");
}
#define GEMM_IDESC  ((1u << 4) | (1u << 7) | (1u << 10) | (16u << 17) | (8u << 24))  // M128 N128
#define ATTN_IDESC1 ((1u << 4) | (1u << 7) | (1u << 10) | (16u << 17) | (8u << 24))  // M128 N128
#define ATTN_IDESC2 ((1u << 4) | (1u << 7) | (1u << 10) | (8u  << 17) | (8u << 24))  // M128 N64
#endif  // HAS_TCGEN05

// ---------------------------------------------------------------------------
// Elementwise split: fp32 -> bf16 hi/lo (8 elems/thread)
// ---------------------------------------------------------------------------
__global__ __launch_bounds__(256) void split_f32_kernel(
    const float* __restrict__ X, __nv_bfloat16* __restrict__ Xhi,
    __nv_bfloat16* __restrict__ Xlo)
{
    const size_t i = ((size_t)blockIdx.x * 256 + threadIdx.x) * 8;
    float4 a = *(const float4*)(X + i);
    float4 b = *(const float4*)(X + i + 4);
    uint4 h, l;
    h.x = pk_hi(a.x, a.y); h.y = pk_hi(a.z, a.w);
    h.z = pk_hi(b.x, b.y); h.w = pk_hi(b.z, b.w);
    l.x = pk_lo(a.x, a.y); l.y = pk_lo(a.z, a.w);
    l.z = pk_lo(b.x, b.y); l.w = pk_lo(b.z, b.w);
    *(uint4*)(Xhi + i) = h;
    *(uint4*)(Xlo + i) = l;
}

// ---------------------------------------------------------------------------
// Transpose + bf16 hi/lo split: W[K,N] -> Thi/Tlo[N,K]
// ---------------------------------------------------------------------------
__global__ __launch_bounds__(256) void transpose_split_kernel(
    const float* __restrict__ W, __nv_bfloat16* __restrict__ Thi,
    __nv_bfloat16* __restrict__ Tlo, int K, int N)
{
    __shared__ float t[32][33];
    const int n0 = blockIdx.x << 5, k0 = blockIdx.y << 5;
    const int x = threadIdx.x, y = threadIdx.y;
    #pragma unroll
    for (int i = y; i < 32; i += 8)
        t[i][x] = W[(size_t)(k0 + i) * N + n0 + x];
    __syncthreads();
    #pragma unroll
    for (int i = y; i < 32; i += 8) {
        float v  = t[x][i];
        __nv_bfloat16 hb = __float2bfloat16_rn(v);
        size_t o = (size_t)(n0 + i) * K + k0 + x;
        Thi[o] = hb;
        Tlo[o] = __float2bfloat16_rn(v - __bfloat162float(hb));
    }
}

// ---------------------------------------------------------------------------
// GEMM (unchanged from R14): cp.async, BK=32, SW64, 3x32KB, 2 CTAs/SM
// ---------------------------------------------------------------------------
#define GSTG 32768
__global__ __launch_bounds__(256, 2)
void gemm_bf16pre_kernel(const __nv_bfloat16* __restrict__ Ahi,
                         const __nv_bfloat16* __restrict__ Alo,
                         const __nv_bfloat16* __restrict__ Bhi,
                         const __nv_bfloat16* __restrict__ Blo,
                         const float* __restrict__ bias,
                         float* __restrict__ Cf,
                         __nv_bfloat16* __restrict__ Chi,
                         __nv_bfloat16* __restrict__ Clo,
                         int M, int N, int K)
{
#if HAS_TCGEN05
    extern __shared__ char dyn[];
    char* tiles = (char*)(((uintptr_t)dyn + 1023) & ~(uintptr_t)1023);
    float*    biass = (float*)(tiles + 3 * GSTG);
    uint64_t* mbar  = (uint64_t*)(tiles + 3 * GSTG + 512);
    uint32_t* tptr  = (uint32_t*)(tiles + 3 * GSTG + 512 + 24);

    const int tid  = threadIdx.x;
    const int wid  = tid >> 5;
    const int lane = tid & 31;
    const int row0 = blockIdx.y << 7, col0 = blockIdx.x << 7;

    const uint32_t tiles_u = su32(tiles);
    const uint32_t mbar_u  = su32(mbar);

    if (tid == 0) { MBAR_INIT(mbar_u, 1); MBAR_INIT(mbar_u + 8, 1); MBAR_INIT(mbar_u + 16, 1); }
    if (wid == 0) { TC_ALLOC(su32(tptr), 128); TC_RELINQ(); }
    if (tid < 128) biass[tid] = bias[col0 + tid];
    __syncthreads();
    const uint32_t tmem = *tptr;

    const int NS = K >> 5;

    auto load_stage = [&](int s, int b) {
        uint32_t base = tiles_u + b * GSTG;
        const int koff = s << 5;
        #pragma unroll
        for (int i = 0; i < 2; i++) {
            int cg  = tid + (i << 8);
            int row = cg >> 2, ch = cg & 3;
            uint32_t sw = SMEM_SWZ64((uint32_t)(row * 64 + ch * 16));
            size_t aoff = (size_t)(row0 + row) * K + koff + (ch << 3);
            size_t boff = (size_t)(col0 + row) * K + koff + (ch << 3);
            cp16(base + sw,         Ahi + aoff);
            cp16(base + 8192 + sw,  Alo + aoff);
            cp16(base + 16384 + sw, Bhi + boff);
            cp16(base + 24576 + sw, Blo + boff);
        }
        CP_COMMIT();
    };

    auto issue_stage = [&](int s, int b, bool first) {
        uint32_t a0 = tiles_u + b * GSTG;
        uint64_t dAh = make_desc_sw64(a0);
        uint64_t dAl = make_desc_sw64(a0 + 8192);
        uint64_t dBh = make_desc_sw64(a0 + 16384);
        uint64_t dBl = make_desc_sw64(a0 + 24576);
        #pragma unroll
        for (int j = 0; j < 2; j++) {
            mma_bf16_ss(tmem, dAh + j * 2, dBh + j * 2, GEMM_IDESC, !(first && j == 0));
            mma_bf16_ss(tmem, dAh + j * 2, dBl + j * 2, GEMM_IDESC, true);
            mma_bf16_ss(tmem, dAl + j * 2, dBh + j * 2, GEMM_IDESC, true);
        }
        TC_COMMIT(mbar_u + (uint32_t)(s % 3) * 8);
    };

    load_stage(0, 0);
    load_stage(1, 1);
    CP_WAIT1();
    FENCE_ASYNC();
    __syncthreads();
    if (wid == 0 && elect1()) issue_stage(0, 0, true);

    for (int s = 0; s < NS; s++) {
        if (s >= 1) { int w = s - 1; MBAR_WAIT(mbar_u + (w % 3) * 8, (w / 3) & 1); }
        const bool loaded = (s + 2 < NS);
        if (loaded) load_stage(s + 2, (s + 2) % 3);
        if (s + 1 < NS) {
            if (loaded) CP_WAIT1(); else CP_WAIT0();
            FENCE_ASYNC();
            __syncthreads();
            if (wid == 0 && elect1()) issue_stage(s + 1, (s + 1) % 3, false);
        }
    }
    { int w = NS - 1; MBAR_WAIT(mbar_u + (w % 3) * 8, (w / 3) & 1); }
    CP_WAIT0();

    TC_FENCE_AFTER();
    if (tid < 128) {
        const int er = row0 + wid * 32 + lane;
        #pragma unroll
        for (int c0 = 0; c0 < 128; c0 += 32) {
            uint32_t rg[32];
            LDTM_X32(rg, tmem + c0);
            TC_WAIT_LD();
            float v[32];
            #pragma unroll
            for (int j = 0; j < 32; j++)
                v[j] = __uint_as_float(rg[j]) + biass[c0 + j];
            if (Chi) {
                __nv_bfloat16* ph = Chi + (size_t)er * N + col0 + c0;
                __nv_bfloat16* pl = Clo + (size_t)er * N + col0 + c0;
                #pragma unroll
                for (int q = 0; q < 4; q++) {
                    uint4 hh, ll;
                    hh.x = pk_hi(v[8*q+0], v[8*q+1]); ll.x = pk_lo(v[8*q+0], v[8*q+1]);
                    hh.y = pk_hi(v[8*q+2], v[8*q+3]); ll.y = pk_lo(v[8*q+2], v[8*q+3]);
                    hh.z = pk_hi(v[8*q+4], v[8*q+5]); ll.z = pk_lo(v[8*q+4], v[8*q+5]);
                    hh.w = pk_hi(v[8*q+6], v[8*q+7]); ll.w = pk_lo(v[8*q+6], v[8*q+7]);
                    *(uint4*)(ph + 8*q) = hh;
                    *(uint4*)(pl + 8*q) = ll;
                }
            } else {
                float* cp = Cf + (size_t)er * N + col0 + c0;
                #pragma unroll
                for (int j = 0; j < 8; j++) {
                    float4 o;
                    o.x = v[4*j+0]; o.y = v[4*j+1]; o.z = v[4*j+2]; o.w = v[4*j+3];
                    *(float4*)(cp + 4 * j) = o;
                }
            }
        }
    }
    __syncthreads();
    if (wid == 0) TC_DEALLOC(tmem, 128);

#else  // ------- generic fallback (compile-only on this rig) -------
    extern __shared__ char dyn[];
    float* As = (float*)dyn;
    float* Bs = As + 16 * 132;

    const int tid = threadIdx.x;
    const int tx  = tid & 15, ty = tid >> 4;
    const int row0 = blockIdx.y << 7, col0 = blockIdx.x << 7;

    float acc[8][8] = {};
    for (int k0 = 0; k0 < K; k0 += 16) {
        __syncthreads();
        #pragma unroll
        for (int t = 0; t < 2; t++) {
            int ch = tid + (t << 8);
            int rr = ch >> 2, c4 = (ch & 3) << 2;
            size_t ao = (size_t)(row0 + rr) * K + k0 + c4;
            size_t bo = (size_t)(col0 + rr) * K + k0 + c4;
            #pragma unroll
            for (int q = 0; q < 4; q++) {
                As[(c4 + q) * 132 + rr] = __bfloat162float(Ahi[ao + q]) + __bfloat162float(Alo[ao + q]);
                Bs[(c4 + q) * 132 + rr] = __bfloat162float(Bhi[bo + q]) + __bfloat162float(Blo[bo + q]);
            }
        }
        __syncthreads();
        #pragma unroll
        for (int kk = 0; kk < 16; kk++) {
            float a[8], b[8];
            #pragma unroll
            for (int i = 0; i < 8; i++) a[i] = As[kk * 132 + ty * 8 + i];
            #pragma unroll
            for (int j = 0; j < 8; j++) b[j] = Bs[kk * 132 + tx * 8 + j];
            #pragma unroll
            for (int i = 0; i < 8; i++)
                #pragma unroll
                for (int j = 0; j < 8; j++) acc[i][j] += a[i] * b[j];
        }
    }
    #pragma unroll
    for (int i = 0; i < 8; i++)
        #pragma unroll
        for (int j = 0; j < 8; j++) {
            float v = acc[i][j] + bias[col0 + tx * 8 + j];
            size_t o = (size_t)(row0 + ty * 8 + i) * N + col0 + tx * 8 + j;
            if (Chi) {
                __nv_bfloat16 hb = __float2bfloat16_rn(v);
                Chi[o] = hb;
                Clo[o] = __float2bfloat16_rn(v - __bfloat162float(hb));
            } else {
                Cf[o] = v;
            }
        }
#endif
}

// ---------------------------------------------------------------------------
// Attention: TMEM-resident O accumulator (no per-tile readback), MMA1(kb+1)
// pre-issued after draining S(kb) -> tensor pipe overlaps softmax.
// TMEM (alloc 512): S @0(128), PHI @128(64), PLO @192(64), U @256(64)
// SMEM: Q 32K, K double-buffered 2x32K, V 32K.
// ---------------------------------------------------------------------------
#define AS_QHI   0
#define AS_QLO   16384
#define AS_KB(b) (32768 + (b) * 32768)       // KHI at +0, KLO at +16384
#define AS_VHI   98304
#define AS_VLO   114688
#define AS_PSUM  131072
#define AS_RED   132096
#define AS_MBAR  132608
#define AS_TPTR  132624
#define ATTN_SMEM_BYTES (1024 + 132640)

#define TM_S    0
#define TM_PHI  128
#define TM_PLO  192
#define TM_U    256

__global__ __launch_bounds__(256) void attn_tc_kernel()
{
#if HAS_TCGEN05
    extern __shared__ char dyn[];
    char* smc = (char*)(((uintptr_t)dyn + 1023) & ~(uintptr_t)1023);
    const uint32_t smu = su32(smc);

    const int tid  = threadIdx.x;
    const int wid  = tid >> 5;
    const int lane = tid & 31;
    const int sp   = wid & 3;
    const int half = wid >> 2;
    const int qb   = (gridDim.x - 1) - blockIdx.x;   // big tiles first
    const int h = blockIdx.y, b = blockIdx.z;
    const int q0   = qb << 7;
    const int r    = sp * 32 + lane;

    const size_t hbase = (size_t)b * SEQ * QLD + h * (3 * HD);
    const __nv_bfloat16* qh = g_qkv_hi + hbase;
    const __nv_bfloat16* ql = g_qkv_lo + hbase;
    const __nv_bfloat16* kh = qh + HD;
    const __nv_bfloat16* kl = ql + HD;
    const __nv_bfloat16* vh = qh + 2 * HD;
    const __nv_bfloat16* vl = ql + 2 * HD;

    float* psums = (float*)(smc + AS_PSUM);
    float* red   = (float*)(smc + AS_RED);
    const uint32_t mb = smu + AS_MBAR;

    if (tid == 0) MBAR_INIT(mb, 1);
    if (wid == 0) { TC_ALLOC(smu + AS_TPTR, 512); TC_RELINQ(); }
    __syncthreads();
    const uint32_t tmem = *(uint32_t*)(smc + AS_TPTR);
    const uint32_t warpoff = (uint32_t)sp << 21;

    const float C = 0.125f * 1.44269504f;

    auto load_k_tile = [&](int k0, int buf) {
        uint32_t base = smu + AS_KB(buf);
        #pragma unroll
        for (int i = 0; i < 4; i++) {
            int cg  = tid + (i << 8);
            int row = cg >> 3, ch = cg & 7;
            uint32_t sw = SMEM_SWZ((uint32_t)(row * 128 + ch * 16));
            size_t off = (size_t)(k0 + row) * QLD + (ch << 3);
            cp16(base + sw,         kh + off);
            cp16(base + 16384 + sw, kl + off);
        }
        CP_COMMIT();
    };

    const int vp_p  = tid & 63;
    const int vp_dh = tid >> 6;
    const int vp_panel = vp_p >> 5;
    const int vp_pc    = vp_p & 31;

    uint32_t E[8], Od[8], El[8], Ol[8];
    auto load_v_regs = [&](int k0) {
        const size_t e_off = (size_t)(k0 + 2 * vp_p) * QLD + (vp_dh << 4);
        const size_t o_off = e_off + QLD;
        *(uint4*)&E[0]  = *(const uint4*)(vh + e_off);
        *(uint4*)&E[4]  = *(const uint4*)(vh + e_off + 8);
        *(uint4*)&Od[0] = *(const uint4*)(vh + o_off);
        *(uint4*)&Od[4] = *(const uint4*)(vh + o_off + 8);
        *(uint4*)&El[0] = *(const uint4*)(vl + e_off);
        *(uint4*)&El[4] = *(const uint4*)(vl + e_off + 8);
        *(uint4*)&Ol[0] = *(const uint4*)(vl + o_off);
        *(uint4*)&Ol[4] = *(const uint4*)(vl + o_off + 8);
    };
    auto store_v_smem = [&]() {
        #pragma unroll
        for (int j = 0; j < 8; j++) {
            int d = (vp_dh << 4) + 2 * j;
            uint32_t w0h = __byte_perm(E[j],  Od[j], 0x5410);
            uint32_t w1h = __byte_perm(E[j],  Od[j], 0x7632);
            uint32_t w0l = __byte_perm(El[j], Ol[j], 0x5410);
            uint32_t w1l = __byte_perm(El[j], Ol[j], 0x7632);
            uint32_t off0 = SMEM_SWZ((uint32_t)(d * 128 + vp_pc * 4));
            uint32_t off1 = SMEM_SWZ((uint32_t)((d + 1) * 128 + vp_pc * 4));
            *(uint32_t*)(smc + AS_VHI + vp_panel * 8192 + off0) = w0h;
            *(uint32_t*)(smc + AS_VHI + vp_panel * 8192 + off1) = w1h;
            *(uint32_t*)(smc + AS_VLO + vp_panel * 8192 + off0) = w0l;
            *(uint32_t*)(smc + AS_VLO + vp_panel * 8192 + off1) = w1l;
        }
    };

    auto issue_mma1 = [&](int buf) {
        uint64_t dQh = make_desc(smu + AS_QHI);
        uint64_t dQl = make_desc(smu + AS_QLO);
        uint64_t dKh = make_desc(smu + AS_KB(buf));
        uint64_t dKl = make_desc(smu + AS_KB(buf) + 16384);
        bool first = true;
        #pragma unroll
        for (int j = 0; j < 4; j++) {
            mma_bf16_ss(tmem + TM_S, dQh + j * 2, dKh + j * 2, ATTN_IDESC1, !first);
            first = false;
            mma_bf16_ss(tmem + TM_S, dQh + j * 2, dKl + j * 2, ATTN_IDESC1, true);
            mma_bf16_ss(tmem + TM_S, dQl + j * 2, dKh + j * 2, ATTN_IDESC1, true);
        }
    };

    // ---- Prologue: Q copy, K(0) copy, V(0)->regs; issue MMA1(0)+commit ----
    #pragma unroll
    for (int i = 0; i < 4; i++) {
        int cg  = tid + (i << 8);
        int row = cg >> 3, ch = cg & 7;
        uint32_t sw = SMEM_SWZ((uint32_t)(row * 128 + ch * 16));
        size_t off = (size_t)(q0 + row) * QLD + (ch << 3);
        cp16(smu + AS_QHI + sw, qh + off);
        cp16(smu + AS_QLO + sw, ql + off);
    }
    CP_COMMIT();
    load_k_tile(0, 0);
    load_v_regs(0);
    CP_WAIT0();
    FENCE_ASYNC();
    __syncthreads();
    if (wid == 0) {
        TC_FENCE_AFTER();
        if (elect1()) { issue_mma1(0); TC_COMMIT(mb); }
    }

    float l_run = 0.0f;
    int pt = 0;

    for (int kb = 0; kb <= qb; kb++) {
        const int k0 = kb << 7;

        // wait: MMA1(kb) done (and MMA2(kb-1) done — same commit chain)
        MBAR_WAIT(mb, pt); pt ^= 1;
        TC_FENCE_AFTER();

        // V(kb) regs -> smem (safe: MMA2(kb-1) completed)
        store_v_smem();

        // prefetch K(kb+1) into buf (kb+1)&1 (freed: MMA1(kb-1) done long ago)
        if (kb < qb) load_k_tile(k0 + 128, (kb + 1) & 1);

        // drain S(kb) fully into registers
        uint32_t u0[32], u1[32];
        LDTM_X32(u0, tmem + TM_S + half * 64);
        LDTM_X32(u1, tmem + TM_S + half * 64 + 32);
        TC_WAIT_LD();
        TC_FENCE_BEFORE();
        CP_WAIT0();              // K(kb+1) complete (all threads)
        FENCE_ASYNC();
        __syncthreads();

        // pre-issue MMA1(kb+1): S region free, K(kb+1) loaded
        if (kb < qb && wid == 0) {
            TC_FENCE_AFTER();
            if (elect1()) issue_mma1((kb + 1) & 1);
        }

        // softmax (m=0) from registers; overlaps MMA1(kb+1) in tensor pipe
        const int qg = q0 + r;
        float ps = 0.0f;
        {
            float p[32];
            const int cb0 = k0 + half * 64;
            #pragma unroll
            for (int j = 0; j < 32; j++) {
                float e = exp2f(__uint_as_float(u0[j]) * C);
                if (kb == qb && cb0 + j > qg) e = 0.0f;
                p[j] = e; ps += e;
            }
            uint32_t hw[16], lw[16];
            #pragma unroll
            for (int j = 0; j < 16; j++) {
                hw[j] = pk_hi(p[2*j], p[2*j+1]);
                lw[j] = pk_lo(p[2*j], p[2*j+1]);
            }
            STTM_X16(tmem + TM_PHI + half * 32 + warpoff, hw);
            STTM_X16(tmem + TM_PLO + half * 32 + warpoff, lw);
            const int cb1 = cb0 + 32;
            #pragma unroll
            for (int j = 0; j < 32; j++) {
                float e = exp2f(__uint_as_float(u1[j]) * C);
                if (kb == qb && cb1 + j > qg) e = 0.0f;
                p[j] = e; ps += e;
            }
            #pragma unroll
            for (int j = 0; j < 16; j++) {
                hw[j] = pk_hi(p[2*j], p[2*j+1]);
                lw[j] = pk_lo(p[2*j], p[2*j+1]);
            }
            STTM_X16(tmem + TM_PHI + half * 32 + 16 + warpoff, hw);
            STTM_X16(tmem + TM_PLO + half * 32 + 16 + warpoff, lw);
        }
        psums[r * 2 + half] = ps;
        TC_WAIT_ST();
        TC_FENCE_BEFORE();
        __syncthreads();

        if (half == 0)
            l_run += psums[r * 2] + psums[r * 2 + 1];

        // MMA2(kb): U += P @ Vt^T (TMEM accumulate), then commit (covers MMA1(kb+1) too)
        if (wid == 0) {
            TC_FENCE_AFTER();
            if (elect1()) {
                bool first = (kb == 0);
                #pragma unroll
                for (int panel = 0; panel < 2; panel++) {
                    uint64_t dVh = make_desc(smu + AS_VHI + panel * 8192);
                    uint64_t dVl = make_desc(smu + AS_VLO + panel * 8192);
                    #pragma unroll
                    for (int j = 0; j < 4; j++) {
                        uint32_t acol = panel * 32 + j * 8;
                        mma_bf16_ts(tmem + TM_U, tmem + TM_PHI + acol, dVh + j * 2, ATTN_IDESC2, !first);
                        first = false;
                        mma_bf16_ts(tmem + TM_U, tmem + TM_PHI + acol, dVl + j * 2, ATTN_IDESC2, true);
                        mma_bf16_ts(tmem + TM_U, tmem + TM_PLO + acol, dVh + j * 2, ATTN_IDESC2, true);
                    }
                }
                TC_COMMIT(mb);
            }
        }

        // prefetch V(kb+1) into regs (hides under MMA2)
        if (kb < qb) load_v_regs(k0 + 128);
    }

    // ---- Epilogue: final MMA2 done -> read U once, normalize, write ----
    MBAR_WAIT(mb, pt);
    TC_FENCE_AFTER();
    if (half == 0) red[r] = 1.0f / l_run;
    __syncthreads();
    {
        uint32_t u[32];
        LDTM_X32(u, tmem + TM_U + half * 32);
        TC_WAIT_LD();
        TC_FENCE_BEFORE();
        const float inv = red[r];
        const size_t vo = ((size_t)b * SEQ + q0 + r) * DM + h * HD + half * 32;
        float v[32];
        #pragma unroll
        for (int c = 0; c < 32; c++) v[c] = __uint_as_float(u[c]) * inv;
        uint4 hh, ll;
        #pragma unroll
        for (int q = 0; q < 4; q++) {
            hh.x = pk_hi(v[8*q+0], v[8*q+1]); ll.x = pk_lo(v[8*q+0], v[8*q+1]);
            hh.y = pk_hi(v[8*q+2], v[8*q+3]); ll.y = pk_lo(v[8*q+2], v[8*q+3]);
            hh.z = pk_hi(v[8*q+4], v[8*q+5]); ll.z = pk_lo(v[8*q+4], v[8*q+5]);
            hh.w = pk_hi(v[8*q+6], v[8*q+7]); ll.w = pk_lo(v[8*q+6], v[8*q+7]);
            *(uint4*)(g_val_hi + vo + 8*q) = hh;
            *(uint4*)(g_val_lo + vo + 8*q) = ll;
        }
    }
    __syncthreads();
    if (wid == 0) TC_DEALLOC(tmem, 512);

#else  // ------- generic fallback (compile-only on this rig) -------
    extern __shared__ float sm[];
    float* Qs = sm;
    float* Ks = sm + 64 * 68;
    float* Vs = sm + 2 * 64 * 68;
    float* Ps = sm + 3 * 64 * 68;

    const int tid = threadIdx.x;
    const int tx  = tid & 15, ty = tid >> 4;
    const int h = blockIdx.y, b = blockIdx.z;

    const size_t hbase = (size_t)b * SEQ * QLD + h * (3 * HD);

    for (int sub = 0; sub < 2; sub++) {
        const int q0 = (blockIdx.x << 7) + (sub << 6);
        __syncthreads();
        for (int idx = tid; idx < 64 * 64; idx += 256) {
            int rr = idx >> 6, d = idx & 63;
            size_t o = hbase + (size_t)(q0 + rr) * QLD + d;
            Qs[d * 68 + rr] = (__bfloat162float(g_qkv_hi[o]) + __bfloat162float(g_qkv_lo[o])) * 0.125f;
        }

        float m_i[4] = {-3e38f, -3e38f, -3e38f, -3e38f};
        float l_i[4] = {};
        float acc[4][4] = {};
        const int nkb = (q0 >> 6) + 1;

        for (int kb = 0; kb < nkb; kb++) {
            const int k0 = kb << 6;
            __syncthreads();
            for (int idx = tid; idx < 64 * 64; idx += 256) {
                int c = idx >> 6, d = idx & 63;
                size_t ko = hbase + (size_t)(k0 + c) * QLD + HD + d;
                size_t vo = ko + HD;
                Ks[d * 68 + c] = __bfloat162float(g_qkv_hi[ko]) + __bfloat162float(g_qkv_lo[ko]);
                Vs[c * 68 + d] = __bfloat162float(g_qkv_hi[vo]) + __bfloat162float(g_qkv_lo[vo]);
            }
            __syncthreads();

            float s[4][4] = {};
            for (int d = 0; d < 64; d++) {
                float a0 = Qs[d*68+(ty<<2)], a1 = Qs[d*68+(ty<<2)+1];
                float a2 = Qs[d*68+(ty<<2)+2], a3 = Qs[d*68+(ty<<2)+3];
                float b0 = Ks[d*68+(tx<<2)], b1 = Ks[d*68+(tx<<2)+1];
                float b2 = Ks[d*68+(tx<<2)+2], b3 = Ks[d*68+(tx<<2)+3];
                s[0][0]+=a0*b0; s[0][1]+=a0*b1; s[0][2]+=a0*b2; s[0][3]+=a0*b3;
                s[1][0]+=a1*b0; s[1][1]+=a1*b1; s[1][2]+=a1*b2; s[1][3]+=a1*b3;
                s[2][0]+=a2*b0; s[2][1]+=a2*b1; s[2][2]+=a2*b2; s[2][3]+=a2*b3;
                s[3][0]+=a3*b0; s[3][1]+=a3*b1; s[3][2]+=a3*b2; s[3][3]+=a3*b3;
            }
            if (kb == nkb - 1)
                for (int i = 0; i < 4; i++)
                    for (int j = 0; j < 4; j++)
                        if ((tx<<2)+j > (ty<<2)+i) s[i][j] = -1e9f;
            for (int i = 0; i < 4; i++) {
                float mx = fmaxf(fmaxf(s[i][0], s[i][1]), fmaxf(s[i][2], s[i][3]));
                for (int off = 8; off > 0; off >>= 1)
                    mx = fmaxf(mx, __shfl_xor_sync(0xffffffffu, mx, off, 16));
                float mnew = fmaxf(m_i[i], mx);
                float p0 = __expf(s[i][0]-mnew), p1 = __expf(s[i][1]-mnew);
                float p2 = __expf(s[i][2]-mnew), p3 = __expf(s[i][3]-mnew);
                float ls = p0+p1+p2+p3;
                for (int off = 8; off > 0; off >>= 1)
                    ls += __shfl_xor_sync(0xffffffffu, ls, off, 16);
                float alpha = __expf(m_i[i] - mnew);
                l_i[i] = l_i[i]*alpha + ls;
                m_i[i] = mnew;
                acc[i][0]*=alpha; acc[i][1]*=alpha; acc[i][2]*=alpha; acc[i][3]*=alpha;
                s[i][0]=p0; s[i][1]=p1; s[i][2]=p2; s[i][3]=p3;
            }
            for (int i = 0; i < 4; i++)
                for (int j = 0; j < 4; j++)
                    Ps[((tx<<2)+j)*68 + (ty<<2)+i] = s[i][j];
            __syncthreads();
            for (int c = 0; c < 64; c++) {
                float a0 = Ps[c*68+(ty<<2)], a1 = Ps[c*68+(ty<<2)+1];
                float a2 = Ps[c*68+(ty<<2)+2], a3 = Ps[c*68+(ty<<2)+3];
                float b0 = Vs[c*68+(tx<<2)], b1 = Vs[c*68+(tx<<2)+1];
                float b2 = Vs[c*68+(tx<<2)+2], b3 = Vs[c*68+(tx<<2)+3];
                acc[0][0]+=a0*b0; acc[0][1]+=a0*b1; acc[0][2]+=a0*b2; acc[0][3]+=a0*b3;
                acc[1][0]+=a1*b0; acc[1][1]+=a1*b1; acc[1][2]+=a1*b2; acc[1][3]+=a1*b3;
                acc[2][0]+=a2*b0; acc[2][1]+=a2*b1; acc[2][2]+=a2*b2; acc[2][3]+=a2*b3;
                acc[3][0]+=a3*b0; acc[3][1]+=a3*b1; acc[3][2]+=a3*b2; acc[3][3]+=a3*b3;
            }
        }
        for (int i = 0; i < 4; i++) {
            float inv = 1.0f / l_i[i];
            for (int j = 0; j < 4; j++) {
                float v = acc[i][j] * inv;
                size_t o = ((size_t)b * SEQ + q0 + (ty<<2)+i) * DM + h * HD + (tx<<2)+j;
                __nv_bfloat16 hb = __float2bfloat16_rn(v);
                g_val_hi[o] = hb;
                g_val_lo[o] = __float2bfloat16_rn(v - __bfloat162float(hb));
            }
        }
        __syncthreads();
    }
#endif
}

// ---------------------------------------------------------------------------
// Launch
// ---------------------------------------------------------------------------
extern "C" void kernel_launch(void* const* d_in, const int* in_sizes, int n_in,
                              void* d_out, int out_size)
{
    const float* x    = (const float*)d_in[0];
    const float* Wqkv = (const float*)d_in[1];
    const float* bqkv = (const float*)d_in[2];
    const float* Wout = (const float*)d_in[3];
    const float* bout = (const float*)d_in[4];
    float* out = (float*)d_out;

    __nv_bfloat16 *x_hi, *x_lo, *qkv_hi, *qkv_lo, *val_hi, *val_lo;
    __nv_bfloat16 *wq_hi, *wq_lo, *wo_hi, *wo_lo;
    cudaGetSymbolAddress((void**)&x_hi,   g_x_hi);
    cudaGetSymbolAddress((void**)&x_lo,   g_x_lo);
    cudaGetSymbolAddress((void**)&qkv_hi, g_qkv_hi);
    cudaGetSymbolAddress((void**)&qkv_lo, g_qkv_lo);
    cudaGetSymbolAddress((void**)&val_hi, g_val_hi);
    cudaGetSymbolAddress((void**)&val_lo, g_val_lo);
    cudaGetSymbolAddress((void**)&wq_hi,  g_wqkvT_hi);
    cudaGetSymbolAddress((void**)&wq_lo,  g_wqkvT_lo);
    cudaGetSymbolAddress((void**)&wo_hi,  g_woutT_hi);
    cudaGetSymbolAddress((void**)&wo_lo,  g_woutT_lo);

    const int gemm_smem = 1024 + 3 * GSTG + 512 + 64;
    const int attn_smem = ATTN_SMEM_BYTES;
    cudaFuncSetAttribute(gemm_bf16pre_kernel,
                         cudaFuncAttributeMaxDynamicSharedMemorySize, gemm_smem);
    cudaFuncSetAttribute(attn_tc_kernel,
                         cudaFuncAttributeMaxDynamicSharedMemorySize, attn_smem);

    // Preludes
    split_f32_kernel<<<(BSROWS * DM) / (256 * 8), 256>>>(x, x_hi, x_lo);
    transpose_split_kernel<<<dim3(QLD / 32, DM / 32), dim3(32, 8)>>>(Wqkv, wq_hi, wq_lo, DM, QLD);
    transpose_split_kernel<<<dim3(DM / 32, DM / 32), dim3(32, 8)>>>(Wout, wo_hi, wo_lo, DM, DM);

    // QKV projection -> bf16 hi/lo qkv
    gemm_bf16pre_kernel<<<dim3(QLD / 128, BSROWS / 128), 256, gemm_smem>>>(
        x_hi, x_lo, wq_hi, wq_lo, bqkv, nullptr, qkv_hi, qkv_lo, BSROWS, QLD, DM);

    // Attention -> bf16 hi/lo val
    attn_tc_kernel<<<dim3(SEQ / 128, NH, BATCH), 256, attn_smem>>>();

    // Output projection -> fp32 out
    gemm_bf16pre_kernel<<<dim3(DM / 128, BSROWS / 128), 256, gemm_smem>>>(
        val_hi, val_lo, wo_hi, wo_lo, bout, out, nullptr, nullptr, BSROWS, DM, DM);
}

// round 16
// speedup vs baseline: 1.1436x; 1.0291x over previous
#include <cuda_runtime.h>
#include <cuda_bf16.h>
#include <cstdint>
#include <math.h>

#define SEQ   2048
#define BATCH 2
#define DM    1024
#define NH    16
#define HD    64
#define BSROWS (BATCH*SEQ)   // 4096
#define QLD   (3*DM)         // 3072

#if defined(__CUDA_ARCH_FEAT_SM103_ALL) || defined(__CUDA_ARCH_FEAT_SM100_ALL) || \
    (defined(__CUDA_ARCH_SPECIFIC__) && (__CUDA_ARCH_SPECIFIC__ >= 1000))
#define HAS_TCGEN05 1
#else
#define HAS_TCGEN05 0
#endif

// ---------------------------------------------------------------------------
// Scratch: everything mid-pipeline is bf16 hi/lo
// ---------------------------------------------------------------------------
__device__ __nv_bfloat16 g_x_hi[(size_t)BSROWS * DM];
__device__ __nv_bfloat16 g_x_lo[(size_t)BSROWS * DM];
__device__ __nv_bfloat16 g_qkv_hi[(size_t)BSROWS * QLD];
__device__ __nv_bfloat16 g_qkv_lo[(size_t)BSROWS * QLD];
__device__ __nv_bfloat16 g_val_hi[(size_t)BSROWS * DM];
__device__ __nv_bfloat16 g_val_lo[(size_t)BSROWS * DM];
__device__ __nv_bfloat16 g_wqkvT_hi[(size_t)QLD * DM];
__device__ __nv_bfloat16 g_wqkvT_lo[(size_t)QLD * DM];
__device__ __nv_bfloat16 g_woutT_hi[(size_t)DM * DM];
__device__ __nv_bfloat16 g_woutT_lo[(size_t)DM * DM];

// ---------------------------------------------------------------------------
// Generic helpers
// ---------------------------------------------------------------------------
__device__ __forceinline__ uint32_t su32(const void* p) {
    return (uint32_t)__cvta_generic_to_shared(p);
}
__device__ __forceinline__ uint32_t pk_hi(float a, float b) {
    __nv_bfloat162 t = __floats2bfloat162_rn(a, b);
    return *(uint32_t*)&t;
}
__device__ __forceinline__ uint32_t pk_lo(float a, float b) {
    float ah = __bfloat162float(__float2bfloat16_rn(a));
    float bh = __bfloat162float(__float2bfloat16_rn(b));
    __nv_bfloat162 t = __floats2bfloat162_rn(a - ah, b - bh);
    return *(uint32_t*)&t;
}
#define SMEM_SWZ(off)   ((off) ^ (((off) >> 3) & 0x70))   // SW128 (128B rows)
#define SMEM_SWZ64(off) ((off) ^ (((off) >> 3) & 0x30))   // SW64  (64B rows)

// cp.async (sm_80+)
__device__ __forceinline__ void cp16(uint32_t dst, const void* src) {
    asm volatile("cp.async.cg.shared.global [%0], [%1], 16;" :: "r"(dst), "l"(src) : "memory");
}
#define CP_COMMIT() asm volatile("cp.async.commit_group;" ::: "memory")
#define CP_WAIT0()  asm volatile("cp.async.wait_group 0;" ::: "memory")
#define CP_WAIT1()  asm volatile("cp.async.wait_group 1;" ::: "memory")

#if HAS_TCGEN05
__device__ __forceinline__ bool elect1() {
    uint32_t r;
    asm volatile("{\n\t.reg .pred p;\n\telect.sync _|p, 0xFFFFFFFF;\n\tselp.b32 %0, 1, 0, p;\n\t}" : "=r"(r));
    return r != 0;
}
#define MBAR_INIT(addr, cnt) \
    asm volatile("mbarrier.init.shared.b64 [%0], %1;" :: "r"(addr), "r"(cnt) : "memory")
#define MBAR_WAIT(addr, ph) do {                                              \
    uint32_t _m = (addr), _p = (ph), _d;                                      \
    asm volatile("{\n\t.reg .pred p;\n\t"                                     \
        "mbarrier.try_wait.parity.acquire.cta.shared::cta.b64 p, [%1], %2;\n\t" \
        "selp.b32 %0, 1, 0, p;\n\t}" : "=r"(_d) : "r"(_m), "r"(_p) : "memory"); \
    if (!_d) {                                                                \
        asm volatile("{\n\t.reg .pred P1;\n\t"                                \
            "WL_%=:\n\t"                                                      \
            "mbarrier.try_wait.parity.acquire.cta.shared::cta.b64 P1, [%0], %1, 0x989680;\n\t" \
            "@P1 bra.uni WD_%=;\n\tbra.uni WL_%=;\n\tWD_%=:\n\t}"             \
            :: "r"(_m), "r"(_p) : "memory");                                  \
    }                                                                         \
} while (0)
#define TC_ALLOC(smem_addr, ncols) \
    asm volatile("tcgen05.alloc.cta_group::1.sync.aligned.shared::cta.b32 [%0], %1;" \
                 :: "r"(smem_addr), "r"(ncols) : "memory")
#define TC_RELINQ() \
    asm volatile("tcgen05.relinquish_alloc_permit.cta_group::1.sync.aligned;")
#define TC_DEALLOC(tmem, ncols) \
    asm volatile("tcgen05.dealloc.cta_group::1.sync.aligned.b32 %0, %1;" :: "r"(tmem), "r"(ncols))
#define TC_COMMIT(mbar) \
    asm volatile("tcgen05.commit.cta_group::1.mbarrier::arrive::one.shared::cluster.b64 [%0];" \
                 :: "r"(mbar) : "memory")
#define TC_FENCE_AFTER()  asm volatile("tcgen05.fence::after_thread_sync;" ::: "memory")
#define TC_FENCE_BEFORE() asm volatile("tcgen05.fence::before_thread_sync;" ::: "memory")
#define TC_WAIT_LD()      asm volatile("tcgen05.wait::ld.sync.aligned;" ::: "memory")
#define TC_WAIT_ST()      asm volatile("tcgen05.wait::st.sync.aligned;" ::: "memory")
#define FENCE_ASYNC()     asm volatile("fence.proxy.async.shared::cta;" ::: "memory")

#define LDTM_X32(r, a) \
    asm volatile("tcgen05.ld.sync.aligned.32x32b.x32.b32 "                    \
        "{%0, %1, %2, %3, %4, %5, %6, %7, %8, %9, %10, %11, %12, %13, %14, %15, " \
        " %16, %17, %18, %19, %20, %21, %22, %23, %24, %25, %26, %27, %28, %29, %30, %31}, [%32];" \
        : "=r"((r)[0]),  "=r"((r)[1]),  "=r"((r)[2]),  "=r"((r)[3]),          \
          "=r"((r)[4]),  "=r"((r)[5]),  "=r"((r)[6]),  "=r"((r)[7]),          \
          "=r"((r)[8]),  "=r"((r)[9]),  "=r"((r)[10]), "=r"((r)[11]),         \
          "=r"((r)[12]), "=r"((r)[13]), "=r"((r)[14]), "=r"((r)[15]),         \
          "=r"((r)[16]), "=r"((r)[17]), "=r"((r)[18]), "=r"((r)[19]),         \
          "=r"((r)[20]), "=r"((r)[21]), "=r"((r)[22]), "=r"((r)[23]),         \
          "=r"((r)[24]), "=r"((r)[25]), "=r"((r)[26]), "=r"((r)[27]),         \
          "=r"((r)[28]), "=r"((r)[29]), "=r"((r)[30]), "=r"((r)[31])          \
        : "r"(a))

#define STTM_X16(a, r) \
    asm volatile("tcgen05.st.sync.aligned.32x32b.x16.b32 [%0], "              \
        "{%1, %2, %3, %4, %5, %6, %7, %8, %9, %10, %11, %12, %13, %14, %15, %16};" \
        :: "r"(a),                                                            \
           "r"((r)[0]),  "r"((r)[1]),  "r"((r)[2]),  "r"((r)[3]),             \
           "r"((r)[4]),  "r"((r)[5]),  "r"((r)[6]),  "r"((r)[7]),             \
           "r"((r)[8]),  "r"((r)[9]),  "r"((r)[10]), "r"((r)[11]),            \
           "r"((r)[12]), "r"((r)[13]), "r"((r)[14]), "r"((r)[15])             \
        : "memory")

// K-major SW128 desc (128B rows): SBO=64, LBO=1
static __device__ __forceinline__ uint64_t make_desc(uint32_t addr) {
    const uint64_t base = (uint64_t(2) << 61) | (uint64_t(1) << 46)
                        | (uint64_t(64) << 32) | (uint64_t(1) << 16);
    return base | ((uint64_t)(addr >> 4) & 0x3FFF);
}
// K-major SW64 desc (64B rows): layout=4, SBO=32, LBO=1
static __device__ __forceinline__ uint64_t make_desc_sw64(uint32_t addr) {
    const uint64_t base = (uint64_t(4) << 61) | (uint64_t(1) << 46)
                        | (uint64_t(32) << 32) | (uint64_t(1) << 16);
    return base | ((uint64_t)(addr >> 4) & 0x3FFF);
}
__device__ __forceinline__ void mma_bf16_ss(uint32_t d, uint64_t ad, uint64_t bd,
                                            uint32_t idesc, bool acc) {
    uint32_t en = acc ? 1u : 0u;
    asm volatile(
        "{\n\t.reg .pred p;\n\tsetp.ne.u32 p, %4, 0;\n\t"
        "tcgen05.mma.cta_group::1.kind::f16 [%0], %1, %2, %3, {%5, %5, %5, %5}, p;\n\t}"
        :: "r"(d), "l"(ad), "l"(bd), "r"(idesc), "r"(en), "r"(0u) : "memory");
}
__device__ __forceinline__ void mma_bf16_ts(uint32_t d, uint32_t a, uint64_t bd,
                                            uint32_t idesc, bool acc) {
    uint32_t en = acc ? 1u : 0u;
    asm volatile(
        "{\n\t.reg .pred p;\n\tsetp.ne.u32 p, %4, 0;\n\t"
        "tcgen05.mma.cta_group::1.kind::f16 [%0], [%1], %2, %3, {%5, %5, %5, %5}, p;\n\t}"
        :: "r"(d), "r"(a), "l"(bd), "r"(idesc), "r"(en), "r"(0u) : "memory");
}
#define GEMM_IDESC  ((1u << 4) | (1u << 7) | (1u << 10) | (16u << 17) | (8u << 24))  // M128 N128
#define ATTN_IDESC1 ((1u << 4) | (1u << 7) | (1u << 10) | (16u << 17) | (8u << 24))  // M128 N128
#define ATTN_IDESC2 ((1u << 4) | (1u << 7) | (1u << 10) | (8u  << 17) | (8u << 24))  // M128 N64
#endif  // HAS_TCGEN05

// ---------------------------------------------------------------------------
// Elementwise split: fp32 -> bf16 hi/lo (8 elems/thread)
// ---------------------------------------------------------------------------
__global__ __launch_bounds__(256) void split_f32_kernel(
    const float* __restrict__ X, __nv_bfloat16* __restrict__ Xhi,
    __nv_bfloat16* __restrict__ Xlo)
{
    const size_t i = ((size_t)blockIdx.x * 256 + threadIdx.x) * 8;
    float4 a = *(const float4*)(X + i);
    float4 b = *(const float4*)(X + i + 4);
    uint4 h, l;
    h.x = pk_hi(a.x, a.y); h.y = pk_hi(a.z, a.w);
    h.z = pk_hi(b.x, b.y); h.w = pk_hi(b.z, b.w);
    l.x = pk_lo(a.x, a.y); l.y = pk_lo(a.z, a.w);
    l.z = pk_lo(b.x, b.y); l.w = pk_lo(b.z, b.w);
    *(uint4*)(Xhi + i) = h;
    *(uint4*)(Xlo + i) = l;
}

// ---------------------------------------------------------------------------
// Transpose + bf16 hi/lo split: W[K,N] -> Thi/Tlo[N,K]
// ---------------------------------------------------------------------------
__global__ __launch_bounds__(256) void transpose_split_kernel(
    const float* __restrict__ W, __nv_bfloat16* __restrict__ Thi,
    __nv_bfloat16* __restrict__ Tlo, int K, int N)
{
    __shared__ float t[32][33];
    const int n0 = blockIdx.x << 5, k0 = blockIdx.y << 5;
    const int x = threadIdx.x, y = threadIdx.y;
    #pragma unroll
    for (int i = y; i < 32; i += 8)
        t[i][x] = W[(size_t)(k0 + i) * N + n0 + x];
    __syncthreads();
    #pragma unroll
    for (int i = y; i < 32; i += 8) {
        float v  = t[x][i];
        __nv_bfloat16 hb = __float2bfloat16_rn(v);
        size_t o = (size_t)(n0 + i) * K + k0 + x;
        Thi[o] = hb;
        Tlo[o] = __float2bfloat16_rn(v - __bfloat162float(hb));
    }
}

// ---------------------------------------------------------------------------
// GEMM (unchanged from R14): cp.async, BK=32, SW64, 3x32KB, 2 CTAs/SM
// ---------------------------------------------------------------------------
#define GSTG 32768
__global__ __launch_bounds__(256, 2)
void gemm_bf16pre_kernel(const __nv_bfloat16* __restrict__ Ahi,
                         const __nv_bfloat16* __restrict__ Alo,
                         const __nv_bfloat16* __restrict__ Bhi,
                         const __nv_bfloat16* __restrict__ Blo,
                         const float* __restrict__ bias,
                         float* __restrict__ Cf,
                         __nv_bfloat16* __restrict__ Chi,
                         __nv_bfloat16* __restrict__ Clo,
                         int M, int N, int K)
{
#if HAS_TCGEN05
    extern __shared__ char dyn[];
    char* tiles = (char*)(((uintptr_t)dyn + 1023) & ~(uintptr_t)1023);
    float*    biass = (float*)(tiles + 3 * GSTG);
    uint64_t* mbar  = (uint64_t*)(tiles + 3 * GSTG + 512);
    uint32_t* tptr  = (uint32_t*)(tiles + 3 * GSTG + 512 + 24);

    const int tid  = threadIdx.x;
    const int wid  = tid >> 5;
    const int lane = tid & 31;
    const int row0 = blockIdx.y << 7, col0 = blockIdx.x << 7;

    const uint32_t tiles_u = su32(tiles);
    const uint32_t mbar_u  = su32(mbar);

    if (tid == 0) { MBAR_INIT(mbar_u, 1); MBAR_INIT(mbar_u + 8, 1); MBAR_INIT(mbar_u + 16, 1); }
    if (wid == 0) { TC_ALLOC(su32(tptr), 128); TC_RELINQ(); }
    if (tid < 128) biass[tid] = bias[col0 + tid];
    __syncthreads();
    const uint32_t tmem = *tptr;

    const int NS = K >> 5;

    auto load_stage = [&](int s, int b) {
        uint32_t base = tiles_u + b * GSTG;
        const int koff = s << 5;
        #pragma unroll
        for (int i = 0; i < 2; i++) {
            int cg  = tid + (i << 8);
            int row = cg >> 2, ch = cg & 3;
            uint32_t sw = SMEM_SWZ64((uint32_t)(row * 64 + ch * 16));
            size_t aoff = (size_t)(row0 + row) * K + koff + (ch << 3);
            size_t boff = (size_t)(col0 + row) * K + koff + (ch << 3);
            cp16(base + sw,         Ahi + aoff);
            cp16(base + 8192 + sw,  Alo + aoff);
            cp16(base + 16384 + sw, Bhi + boff);
            cp16(base + 24576 + sw, Blo + boff);
        }
        CP_COMMIT();
    };

    auto issue_stage = [&](int s, int b, bool first) {
        uint32_t a0 = tiles_u + b * GSTG;
        uint64_t dAh = make_desc_sw64(a0);
        uint64_t dAl = make_desc_sw64(a0 + 8192);
        uint64_t dBh = make_desc_sw64(a0 + 16384);
        uint64_t dBl = make_desc_sw64(a0 + 24576);
        #pragma unroll
        for (int j = 0; j < 2; j++) {
            mma_bf16_ss(tmem, dAh + j * 2, dBh + j * 2, GEMM_IDESC, !(first && j == 0));
            mma_bf16_ss(tmem, dAh + j * 2, dBl + j * 2, GEMM_IDESC, true);
            mma_bf16_ss(tmem, dAl + j * 2, dBh + j * 2, GEMM_IDESC, true);
        }
        TC_COMMIT(mbar_u + (uint32_t)(s % 3) * 8);
    };

    load_stage(0, 0);
    load_stage(1, 1);
    CP_WAIT1();
    FENCE_ASYNC();
    __syncthreads();
    if (wid == 0 && elect1()) issue_stage(0, 0, true);

    for (int s = 0; s < NS; s++) {
        if (s >= 1) { int w = s - 1; MBAR_WAIT(mbar_u + (w % 3) * 8, (w / 3) & 1); }
        const bool loaded = (s + 2 < NS);
        if (loaded) load_stage(s + 2, (s + 2) % 3);
        if (s + 1 < NS) {
            if (loaded) CP_WAIT1(); else CP_WAIT0();
            FENCE_ASYNC();
            __syncthreads();
            if (wid == 0 && elect1()) issue_stage(s + 1, (s + 1) % 3, false);
        }
    }
    { int w = NS - 1; MBAR_WAIT(mbar_u + (w % 3) * 8, (w / 3) & 1); }
    CP_WAIT0();

    TC_FENCE_AFTER();
    if (tid < 128) {
        const int er = row0 + wid * 32 + lane;
        #pragma unroll
        for (int c0 = 0; c0 < 128; c0 += 32) {
            uint32_t rg[32];
            LDTM_X32(rg, tmem + c0);
            TC_WAIT_LD();
            float v[32];
            #pragma unroll
            for (int j = 0; j < 32; j++)
                v[j] = __uint_as_float(rg[j]) + biass[c0 + j];
            if (Chi) {
                __nv_bfloat16* ph = Chi + (size_t)er * N + col0 + c0;
                __nv_bfloat16* pl = Clo + (size_t)er * N + col0 + c0;
                #pragma unroll
                for (int q = 0; q < 4; q++) {
                    uint4 hh, ll;
                    hh.x = pk_hi(v[8*q+0], v[8*q+1]); ll.x = pk_lo(v[8*q+0], v[8*q+1]);
                    hh.y = pk_hi(v[8*q+2], v[8*q+3]); ll.y = pk_lo(v[8*q+2], v[8*q+3]);
                    hh.z = pk_hi(v[8*q+4], v[8*q+5]); ll.z = pk_lo(v[8*q+4], v[8*q+5]);
                    hh.w = pk_hi(v[8*q+6], v[8*q+7]); ll.w = pk_lo(v[8*q+6], v[8*q+7]);
                    *(uint4*)(ph + 8*q) = hh;
                    *(uint4*)(pl + 8*q) = ll;
                }
            } else {
                float* cp = Cf + (size_t)er * N + col0 + c0;
                #pragma unroll
                for (int j = 0; j < 8; j++) {
                    float4 o;
                    o.x = v[4*j+0]; o.y = v[4*j+1]; o.z = v[4*j+2]; o.w = v[4*j+3];
                    *(float4*)(cp + 4 * j) = o;
                }
            }
        }
    }
    __syncthreads();
    if (wid == 0) TC_DEALLOC(tmem, 128);

#else  // ------- generic fallback (compile-only on this rig) -------
    extern __shared__ char dyn[];
    float* As = (float*)dyn;
    float* Bs = As + 16 * 132;

    const int tid = threadIdx.x;
    const int tx  = tid & 15, ty = tid >> 4;
    const int row0 = blockIdx.y << 7, col0 = blockIdx.x << 7;

    float acc[8][8] = {};
    for (int k0 = 0; k0 < K; k0 += 16) {
        __syncthreads();
        #pragma unroll
        for (int t = 0; t < 2; t++) {
            int ch = tid + (t << 8);
            int rr = ch >> 2, c4 = (ch & 3) << 2;
            size_t ao = (size_t)(row0 + rr) * K + k0 + c4;
            size_t bo = (size_t)(col0 + rr) * K + k0 + c4;
            #pragma unroll
            for (int q = 0; q < 4; q++) {
                As[(c4 + q) * 132 + rr] = __bfloat162float(Ahi[ao + q]) + __bfloat162float(Alo[ao + q]);
                Bs[(c4 + q) * 132 + rr] = __bfloat162float(Bhi[bo + q]) + __bfloat162float(Blo[bo + q]);
            }
        }
        __syncthreads();
        #pragma unroll
        for (int kk = 0; kk < 16; kk++) {
            float a[8], b[8];
            #pragma unroll
            for (int i = 0; i < 8; i++) a[i] = As[kk * 132 + ty * 8 + i];
            #pragma unroll
            for (int j = 0; j < 8; j++) b[j] = Bs[kk * 132 + tx * 8 + j];
            #pragma unroll
            for (int i = 0; i < 8; i++)
                #pragma unroll
                for (int j = 0; j < 8; j++) acc[i][j] += a[i] * b[j];
        }
    }
    #pragma unroll
    for (int i = 0; i < 8; i++)
        #pragma unroll
        for (int j = 0; j < 8; j++) {
            float v = acc[i][j] + bias[col0 + tx * 8 + j];
            size_t o = (size_t)(row0 + ty * 8 + i) * N + col0 + tx * 8 + j;
            if (Chi) {
                __nv_bfloat16 hb = __float2bfloat16_rn(v);
                Chi[o] = hb;
                Clo[o] = __float2bfloat16_rn(v - __bfloat162float(hb));
            } else {
                Cf[o] = v;
            }
        }
#endif
}

// ---------------------------------------------------------------------------
// Attention: TMEM-resident O, MMA1(kb+1) overlapped with softmax(kb), and
// K prefetched at DISTANCE 2 (K(kb+2) issued at iter kb) so K(kb+1)'s global
// latency is fully hidden (R15 fix).
// TMEM (alloc 512): S @0(128), PHI @128(64), PLO @192(64), U @256(64)
// SMEM: Q 32K, K double-buffered 2x32K, V 32K.
// ---------------------------------------------------------------------------
#define AS_QHI   0
#define AS_QLO   16384
#define AS_KB(b) (32768 + (b) * 32768)       // KHI at +0, KLO at +16384
#define AS_VHI   98304
#define AS_VLO   114688
#define AS_PSUM  131072
#define AS_RED   132096
#define AS_MBAR  132608
#define AS_TPTR  132624
#define ATTN_SMEM_BYTES (1024 + 132640)

#define TM_S    0
#define TM_PHI  128
#define TM_PLO  192
#define TM_U    256

__global__ __launch_bounds__(256) void attn_tc_kernel()
{
#if HAS_TCGEN05
    extern __shared__ char dyn[];
    char* smc = (char*)(((uintptr_t)dyn + 1023) & ~(uintptr_t)1023);
    const uint32_t smu = su32(smc);

    const int tid  = threadIdx.x;
    const int wid  = tid >> 5;
    const int lane = tid & 31;
    const int sp   = wid & 3;
    const int half = wid >> 2;
    const int qb   = (gridDim.x - 1) - blockIdx.x;   // big tiles first
    const int h = blockIdx.y, b = blockIdx.z;
    const int q0   = qb << 7;
    const int r    = sp * 32 + lane;

    const size_t hbase = (size_t)b * SEQ * QLD + h * (3 * HD);
    const __nv_bfloat16* qh = g_qkv_hi + hbase;
    const __nv_bfloat16* ql = g_qkv_lo + hbase;
    const __nv_bfloat16* kh = qh + HD;
    const __nv_bfloat16* kl = ql + HD;
    const __nv_bfloat16* vh = qh + 2 * HD;
    const __nv_bfloat16* vl = ql + 2 * HD;

    float* psums = (float*)(smc + AS_PSUM);
    float* red   = (float*)(smc + AS_RED);
    const uint32_t mb = smu + AS_MBAR;

    if (tid == 0) MBAR_INIT(mb, 1);
    if (wid == 0) { TC_ALLOC(smu + AS_TPTR, 512); TC_RELINQ(); }
    __syncthreads();
    const uint32_t tmem = *(uint32_t*)(smc + AS_TPTR);
    const uint32_t warpoff = (uint32_t)sp << 21;

    const float C = 0.125f * 1.44269504f;

    auto load_k_tile = [&](int k0, int buf) {
        uint32_t base = smu + AS_KB(buf);
        #pragma unroll
        for (int i = 0; i < 4; i++) {
            int cg  = tid + (i << 8);
            int row = cg >> 3, ch = cg & 7;
            uint32_t sw = SMEM_SWZ((uint32_t)(row * 128 + ch * 16));
            size_t off = (size_t)(k0 + row) * QLD + (ch << 3);
            cp16(base + sw,         kh + off);
            cp16(base + 16384 + sw, kl + off);
        }
        CP_COMMIT();
    };

    const int vp_p  = tid & 63;
    const int vp_dh = tid >> 6;
    const int vp_panel = vp_p >> 5;
    const int vp_pc    = vp_p & 31;

    uint32_t E[8], Od[8], El[8], Ol[8];
    auto load_v_regs = [&](int k0) {
        const size_t e_off = (size_t)(k0 + 2 * vp_p) * QLD + (vp_dh << 4);
        const size_t o_off = e_off + QLD;
        *(uint4*)&E[0]  = *(const uint4*)(vh + e_off);
        *(uint4*)&E[4]  = *(const uint4*)(vh + e_off + 8);
        *(uint4*)&Od[0] = *(const uint4*)(vh + o_off);
        *(uint4*)&Od[4] = *(const uint4*)(vh + o_off + 8);
        *(uint4*)&El[0] = *(const uint4*)(vl + e_off);
        *(uint4*)&El[4] = *(const uint4*)(vl + e_off + 8);
        *(uint4*)&Ol[0] = *(const uint4*)(vl + o_off);
        *(uint4*)&Ol[4] = *(const uint4*)(vl + o_off + 8);
    };
    auto store_v_smem = [&]() {
        #pragma unroll
        for (int j = 0; j < 8; j++) {
            int d = (vp_dh << 4) + 2 * j;
            uint32_t w0h = __byte_perm(E[j],  Od[j], 0x5410);
            uint32_t w1h = __byte_perm(E[j],  Od[j], 0x7632);
            uint32_t w0l = __byte_perm(El[j], Ol[j], 0x5410);
            uint32_t w1l = __byte_perm(El[j], Ol[j], 0x7632);
            uint32_t off0 = SMEM_SWZ((uint32_t)(d * 128 + vp_pc * 4));
            uint32_t off1 = SMEM_SWZ((uint32_t)((d + 1) * 128 + vp_pc * 4));
            *(uint32_t*)(smc + AS_VHI + vp_panel * 8192 + off0) = w0h;
            *(uint32_t*)(smc + AS_VHI + vp_panel * 8192 + off1) = w1h;
            *(uint32_t*)(smc + AS_VLO + vp_panel * 8192 + off0) = w0l;
            *(uint32_t*)(smc + AS_VLO + vp_panel * 8192 + off1) = w1l;
        }
    };

    auto issue_mma1 = [&](int buf) {
        uint64_t dQh = make_desc(smu + AS_QHI);
        uint64_t dQl = make_desc(smu + AS_QLO);
        uint64_t dKh = make_desc(smu + AS_KB(buf));
        uint64_t dKl = make_desc(smu + AS_KB(buf) + 16384);
        bool first = true;
        #pragma unroll
        for (int j = 0; j < 4; j++) {
            mma_bf16_ss(tmem + TM_S, dQh + j * 2, dKh + j * 2, ATTN_IDESC1, !first);
            first = false;
            mma_bf16_ss(tmem + TM_S, dQh + j * 2, dKl + j * 2, ATTN_IDESC1, true);
            mma_bf16_ss(tmem + TM_S, dQl + j * 2, dKh + j * 2, ATTN_IDESC1, true);
        }
    };

    // ---- Prologue: Q copy, K(0)+K(1) copies, V(0)->regs; issue MMA1(0) ----
    #pragma unroll
    for (int i = 0; i < 4; i++) {
        int cg  = tid + (i << 8);
        int row = cg >> 3, ch = cg & 7;
        uint32_t sw = SMEM_SWZ((uint32_t)(row * 128 + ch * 16));
        size_t off = (size_t)(q0 + row) * QLD + (ch << 3);
        cp16(smu + AS_QHI + sw, qh + off);
        cp16(smu + AS_QLO + sw, ql + off);
    }
    CP_COMMIT();
    load_k_tile(0, 0);
    if (qb >= 1) load_k_tile(128, 1);
    load_v_regs(0);
    CP_WAIT0();
    FENCE_ASYNC();
    __syncthreads();
    if (wid == 0) {
        TC_FENCE_AFTER();
        if (elect1()) { issue_mma1(0); TC_COMMIT(mb); }
    }

    float l_run = 0.0f;
    int pt = 0;

    for (int kb = 0; kb <= qb; kb++) {
        const int k0 = kb << 7;

        // wait: MMA1(kb) done (and MMA2(kb-1) done — same commit chain)
        MBAR_WAIT(mb, pt); pt ^= 1;
        TC_FENCE_AFTER();

        // V(kb) regs -> smem (safe: MMA2(kb-1) completed)
        store_v_smem();

        // distance-2 K prefetch: buffer kb&1 just freed by MMA1(kb)
        const bool lk = (kb + 2 <= qb);
        if (lk) load_k_tile(k0 + 256, kb & 1);

        // drain S(kb) fully into registers
        uint32_t u0[32], u1[32];
        LDTM_X32(u0, tmem + TM_S + half * 64);
        LDTM_X32(u1, tmem + TM_S + half * 64 + 32);
        TC_WAIT_LD();
        TC_FENCE_BEFORE();
        // K(kb+1) must be complete before MMA1(kb+1); it was issued a full
        // iteration ago. If a new load is in flight keep it pending (depth-2),
        // else drain all (tail).
        if (kb < qb) { if (lk) CP_WAIT1(); else CP_WAIT0(); }
        FENCE_ASYNC();
        __syncthreads();

        // pre-issue MMA1(kb+1): S region free, K(kb+1) loaded
        if (kb < qb && wid == 0) {
            TC_FENCE_AFTER();
            if (elect1()) issue_mma1((kb + 1) & 1);
        }

        // softmax (m=0) from registers; overlaps MMA1(kb+1) in tensor pipe
        const int qg = q0 + r;
        float ps = 0.0f;
        {
            float p[32];
            const int cb0 = k0 + half * 64;
            #pragma unroll
            for (int j = 0; j < 32; j++) {
                float e = exp2f(__uint_as_float(u0[j]) * C);
                if (kb == qb && cb0 + j > qg) e = 0.0f;
                p[j] = e; ps += e;
            }
            uint32_t hw[16], lw[16];
            #pragma unroll
            for (int j = 0; j < 16; j++) {
                hw[j] = pk_hi(p[2*j], p[2*j+1]);
                lw[j] = pk_lo(p[2*j], p[2*j+1]);
            }
            STTM_X16(tmem + TM_PHI + half * 32 + warpoff, hw);
            STTM_X16(tmem + TM_PLO + half * 32 + warpoff, lw);
            const int cb1 = cb0 + 32;
            #pragma unroll
            for (int j = 0; j < 32; j++) {
                float e = exp2f(__uint_as_float(u1[j]) * C);
                if (kb == qb && cb1 + j > qg) e = 0.0f;
                p[j] = e; ps += e;
            }
            #pragma unroll
            for (int j = 0; j < 16; j++) {
                hw[j] = pk_hi(p[2*j], p[2*j+1]);
                lw[j] = pk_lo(p[2*j], p[2*j+1]);
            }
            STTM_X16(tmem + TM_PHI + half * 32 + 16 + warpoff, hw);
            STTM_X16(tmem + TM_PLO + half * 32 + 16 + warpoff, lw);
        }
        psums[r * 2 + half] = ps;
        TC_WAIT_ST();
        TC_FENCE_BEFORE();
        __syncthreads();

        if (half == 0)
            l_run += psums[r * 2] + psums[r * 2 + 1];

        // MMA2(kb): U += P @ Vt^T (TMEM accumulate); commit covers MMA1(kb+1) too
        if (wid == 0) {
            TC_FENCE_AFTER();
            if (elect1()) {
                bool first = (kb == 0);
                #pragma unroll
                for (int panel = 0; panel < 2; panel++) {
                    uint64_t dVh = make_desc(smu + AS_VHI + panel * 8192);
                    uint64_t dVl = make_desc(smu + AS_VLO + panel * 8192);
                    #pragma unroll
                    for (int j = 0; j < 4; j++) {
                        uint32_t acol = panel * 32 + j * 8;
                        mma_bf16_ts(tmem + TM_U, tmem + TM_PHI + acol, dVh + j * 2, ATTN_IDESC2, !first);
                        first = false;
                        mma_bf16_ts(tmem + TM_U, tmem + TM_PHI + acol, dVl + j * 2, ATTN_IDESC2, true);
                        mma_bf16_ts(tmem + TM_U, tmem + TM_PLO + acol, dVh + j * 2, ATTN_IDESC2, true);
                    }
                }
                TC_COMMIT(mb);
            }
        }

        // prefetch V(kb+1) into regs (hides under MMA2)
        if (kb < qb) load_v_regs(k0 + 128);
    }

    // ---- Epilogue: final MMA2 done -> read U once, normalize, write ----
    MBAR_WAIT(mb, pt);
    TC_FENCE_AFTER();
    if (half == 0) red[r] = 1.0f / l_run;
    __syncthreads();
    {
        uint32_t u[32];
        LDTM_X32(u, tmem + TM_U + half * 32);
        TC_WAIT_LD();
        TC_FENCE_BEFORE();
        const float inv = red[r];
        const size_t vo = ((size_t)b * SEQ + q0 + r) * DM + h * HD + half * 32;
        float v[32];
        #pragma unroll
        for (int c = 0; c < 32; c++) v[c] = __uint_as_float(u[c]) * inv;
        uint4 hh, ll;
        #pragma unroll
        for (int q = 0; q < 4; q++) {
            hh.x = pk_hi(v[8*q+0], v[8*q+1]); ll.x = pk_lo(v[8*q+0], v[8*q+1]);
            hh.y = pk_hi(v[8*q+2], v[8*q+3]); ll.y = pk_lo(v[8*q+2], v[8*q+3]);
            hh.z = pk_hi(v[8*q+4], v[8*q+5]); ll.z = pk_lo(v[8*q+4], v[8*q+5]);
            hh.w = pk_hi(v[8*q+6], v[8*q+7]); ll.w = pk_lo(v[8*q+6], v[8*q+7]);
            *(uint4*)(g_val_hi + vo + 8*q) = hh;
            *(uint4*)(g_val_lo + vo + 8*q) = ll;
        }
    }
    __syncthreads();
    if (wid == 0) TC_DEALLOC(tmem, 512);

#else  // ------- generic fallback (compile-only on this rig) -------
    extern __shared__ float sm[];
    float* Qs = sm;
    float* Ks = sm + 64 * 68;
    float* Vs = sm + 2 * 64 * 68;
    float* Ps = sm + 3 * 64 * 68;

    const int tid = threadIdx.x;
    const int tx  = tid & 15, ty = tid >> 4;
    const int h = blockIdx.y, b = blockIdx.z;

    const size_t hbase = (size_t)b * SEQ * QLD + h * (3 * HD);

    for (int sub = 0; sub < 2; sub++) {
        const int q0 = (blockIdx.x << 7) + (sub << 6);
        __syncthreads();
        for (int idx = tid; idx < 64 * 64; idx += 256) {
            int rr = idx >> 6, d = idx & 63;
            size_t o = hbase + (size_t)(q0 + rr) * QLD + d;
            Qs[d * 68 + rr] = (__bfloat162float(g_qkv_hi[o]) + __bfloat162float(g_qkv_lo[o])) * 0.125f;
        }

        float m_i[4] = {-3e38f, -3e38f, -3e38f, -3e38f};
        float l_i[4] = {};
        float acc[4][4] = {};
        const int nkb = (q0 >> 6) + 1;

        for (int kb = 0; kb < nkb; kb++) {
            const int k0 = kb << 6;
            __syncthreads();
            for (int idx = tid; idx < 64 * 64; idx += 256) {
                int c = idx >> 6, d = idx & 63;
                size_t ko = hbase + (size_t)(k0 + c) * QLD + HD + d;
                size_t vo = ko + HD;
                Ks[d * 68 + c] = __bfloat162float(g_qkv_hi[ko]) + __bfloat162float(g_qkv_lo[ko]);
                Vs[c * 68 + d] = __bfloat162float(g_qkv_hi[vo]) + __bfloat162float(g_qkv_lo[vo]);
            }
            __syncthreads();

            float s[4][4] = {};
            for (int d = 0; d < 64; d++) {
                float a0 = Qs[d*68+(ty<<2)], a1 = Qs[d*68+(ty<<2)+1];
                float a2 = Qs[d*68+(ty<<2)+2], a3 = Qs[d*68+(ty<<2)+3];
                float b0 = Ks[d*68+(tx<<2)], b1 = Ks[d*68+(tx<<2)+1];
                float b2 = Ks[d*68+(tx<<2)+2], b3 = Ks[d*68+(tx<<2)+3];
                s[0][0]+=a0*b0; s[0][1]+=a0*b1; s[0][2]+=a0*b2; s[0][3]+=a0*b3;
                s[1][0]+=a1*b0; s[1][1]+=a1*b1; s[1][2]+=a1*b2; s[1][3]+=a1*b3;
                s[2][0]+=a2*b0; s[2][1]+=a2*b1; s[2][2]+=a2*b2; s[2][3]+=a2*b3;
                s[3][0]+=a3*b0; s[3][1]+=a3*b1; s[3][2]+=a3*b2; s[3][3]+=a3*b3;
            }
            if (kb == nkb - 1)
                for (int i = 0; i < 4; i++)
                    for (int j = 0; j < 4; j++)
                        if ((tx<<2)+j > (ty<<2)+i) s[i][j] = -1e9f;
            for (int i = 0; i < 4; i++) {
                float mx = fmaxf(fmaxf(s[i][0], s[i][1]), fmaxf(s[i][2], s[i][3]));
                for (int off = 8; off > 0; off >>= 1)
                    mx = fmaxf(mx, __shfl_xor_sync(0xffffffffu, mx, off, 16));
                float mnew = fmaxf(m_i[i], mx);
                float p0 = __expf(s[i][0]-mnew), p1 = __expf(s[i][1]-mnew);
                float p2 = __expf(s[i][2]-mnew), p3 = __expf(s[i][3]-mnew);
                float ls = p0+p1+p2+p3;
                for (int off = 8; off > 0; off >>= 1)
                    ls += __shfl_xor_sync(0xffffffffu, ls, off, 16);
                float alpha = __expf(m_i[i] - mnew);
                l_i[i] = l_i[i]*alpha + ls;
                m_i[i] = mnew;
                acc[i][0]*=alpha; acc[i][1]*=alpha; acc[i][2]*=alpha; acc[i][3]*=alpha;
                s[i][0]=p0; s[i][1]=p1; s[i][2]=p2; s[i][3]=p3;
            }
            for (int i = 0; i < 4; i++)
                for (int j = 0; j < 4; j++)
                    Ps[((tx<<2)+j)*68 + (ty<<2)+i] = s[i][j];
            __syncthreads();
            for (int c = 0; c < 64; c++) {
                float a0 = Ps[c*68+(ty<<2)], a1 = Ps[c*68+(ty<<2)+1];
                float a2 = Ps[c*68+(ty<<2)+2], a3 = Ps[c*68+(ty<<2)+3];
                float b0 = Vs[c*68+(tx<<2)], b1 = Vs[c*68+(tx<<2)+1];
                float b2 = Vs[c*68+(tx<<2)+2], b3 = Vs[c*68+(tx<<2)+3];
                acc[0][0]+=a0*b0; acc[0][1]+=a0*b1; acc[0][2]+=a0*b2; acc[0][3]+=a0*b3;
                acc[1][0]+=a1*b0; acc[1][1]+=a1*b1; acc[1][2]+=a1*b2; acc[1][3]+=a1*b3;
                acc[2][0]+=a2*b0; acc[2][1]+=a2*b1; acc[2][2]+=a2*b2; acc[2][3]+=a2*b3;
                acc[3][0]+=a3*b0; acc[3][1]+=a3*b1; acc[3][2]+=a3*b2; acc[3][3]+=a3*b3;
            }
        }
        for (int i = 0; i < 4; i++) {
            float inv = 1.0f / l_i[i];
            for (int j = 0; j < 4; j++) {
                float v = acc[i][j] * inv;
                size_t o = ((size_t)b * SEQ + q0 + (ty<<2)+i) * DM + h * HD + (tx<<2)+j;
                __nv_bfloat16 hb = __float2bfloat16_rn(v);
                g_val_hi[o] = hb;
                g_val_lo[o] = __float2bfloat16_rn(v - __bfloat162float(hb));
            }
        }
        __syncthreads();
    }
#endif
}

// ---------------------------------------------------------------------------
// Launch
// ---------------------------------------------------------------------------
extern "C" void kernel_launch(void* const* d_in, const int* in_sizes, int n_in,
                              void* d_out, int out_size)
{
    const float* x    = (const float*)d_in[0];
    const float* Wqkv = (const float*)d_in[1];
    const float* bqkv = (const float*)d_in[2];
    const float* Wout = (const float*)d_in[3];
    const float* bout = (const float*)d_in[4];
    float* out = (float*)d_out;

    __nv_bfloat16 *x_hi, *x_lo, *qkv_hi, *qkv_lo, *val_hi, *val_lo;
    __nv_bfloat16 *wq_hi, *wq_lo, *wo_hi, *wo_lo;
    cudaGetSymbolAddress((void**)&x_hi,   g_x_hi);
    cudaGetSymbolAddress((void**)&x_lo,   g_x_lo);
    cudaGetSymbolAddress((void**)&qkv_hi, g_qkv_hi);
    cudaGetSymbolAddress((void**)&qkv_lo, g_qkv_lo);
    cudaGetSymbolAddress((void**)&val_hi, g_val_hi);
    cudaGetSymbolAddress((void**)&val_lo, g_val_lo);
    cudaGetSymbolAddress((void**)&wq_hi,  g_wqkvT_hi);
    cudaGetSymbolAddress((void**)&wq_lo,  g_wqkvT_lo);
    cudaGetSymbolAddress((void**)&wo_hi,  g_woutT_hi);
    cudaGetSymbolAddress((void**)&wo_lo,  g_woutT_lo);

    const int gemm_smem = 1024 + 3 * GSTG + 512 + 64;
    const int attn_smem = ATTN_SMEM_BYTES;
    cudaFuncSetAttribute(gemm_bf16pre_kernel,
                         cudaFuncAttributeMaxDynamicSharedMemorySize, gemm_smem);
    cudaFuncSetAttribute(attn_tc_kernel,
                         cudaFuncAttributeMaxDynamicSharedMemorySize, attn_smem);

    // Preludes
    split_f32_kernel<<<(BSROWS * DM) / (256 * 8), 256>>>(x, x_hi, x_lo);
    transpose_split_kernel<<<dim3(QLD / 32, DM / 32), dim3(32, 8)>>>(Wqkv, wq_hi, wq_lo, DM, QLD);
    transpose_split_kernel<<<dim3(DM / 32, DM / 32), dim3(32, 8)>>>(Wout, wo_hi, wo_lo, DM, DM);

    // QKV projection -> bf16 hi/lo qkv
    gemm_bf16pre_kernel<<<dim3(QLD / 128, BSROWS / 128), 256, gemm_smem>>>(
        x_hi, x_lo, wq_hi, wq_lo, bqkv, nullptr, qkv_hi, qkv_lo, BSROWS, QLD, DM);

    // Attention -> bf16 hi/lo val
    attn_tc_kernel<<<dim3(SEQ / 128, NH, BATCH), 256, attn_smem>>>();

    // Output projection -> fp32 out
    gemm_bf16pre_kernel<<<dim3(DM / 128, BSROWS / 128), 256, gemm_smem>>>(
        val_hi, val_lo, wo_hi, wo_lo, bout, out, nullptr, nullptr, BSROWS, DM, DM);
}

// round 17
// speedup vs baseline: 1.1688x; 1.0221x over previous
#include <cuda_runtime.h>
#include <cuda_bf16.h>
#include <cstdint>
#include <math.h>

#define SEQ   2048
#define BATCH 2
#define DM    1024
#define NH    16
#define HD    64
#define BSROWS (BATCH*SEQ)   // 4096
#define QLD   (3*DM)         // 3072

#if defined(__CUDA_ARCH_FEAT_SM103_ALL) || defined(__CUDA_ARCH_FEAT_SM100_ALL) || \
    (defined(__CUDA_ARCH_SPECIFIC__) && (__CUDA_ARCH_SPECIFIC__ >= 1000))
#define HAS_TCGEN05 1
#else
#define HAS_TCGEN05 0
#endif

// ---------------------------------------------------------------------------
// Scratch: everything mid-pipeline is bf16 hi/lo
// ---------------------------------------------------------------------------
__device__ __nv_bfloat16 g_x_hi[(size_t)BSROWS * DM];
__device__ __nv_bfloat16 g_x_lo[(size_t)BSROWS * DM];
__device__ __nv_bfloat16 g_qkv_hi[(size_t)BSROWS * QLD];
__device__ __nv_bfloat16 g_qkv_lo[(size_t)BSROWS * QLD];
__device__ __nv_bfloat16 g_val_hi[(size_t)BSROWS * DM];
__device__ __nv_bfloat16 g_val_lo[(size_t)BSROWS * DM];
__device__ __nv_bfloat16 g_wqkvT_hi[(size_t)QLD * DM];
__device__ __nv_bfloat16 g_wqkvT_lo[(size_t)QLD * DM];
__device__ __nv_bfloat16 g_woutT_hi[(size_t)DM * DM];
__device__ __nv_bfloat16 g_woutT_lo[(size_t)DM * DM];

// ---------------------------------------------------------------------------
// Generic helpers
// ---------------------------------------------------------------------------
__device__ __forceinline__ uint32_t su32(const void* p) {
    return (uint32_t)__cvta_generic_to_shared(p);
}
__device__ __forceinline__ uint32_t pk_hi(float a, float b) {
    __nv_bfloat162 t = __floats2bfloat162_rn(a, b);
    return *(uint32_t*)&t;
}
__device__ __forceinline__ uint32_t pk_lo(float a, float b) {
    float ah = __bfloat162float(__float2bfloat16_rn(a));
    float bh = __bfloat162float(__float2bfloat16_rn(b));
    __nv_bfloat162 t = __floats2bfloat162_rn(a - ah, b - bh);
    return *(uint32_t*)&t;
}
// pack hi pair and derive lo pair from it (same math, fewer instructions)
__device__ __forceinline__ uint32_t pk_pair(float a, float b, uint32_t& lo2) {
    __nv_bfloat162 t = __floats2bfloat162_rn(a, b);
    uint32_t hi2 = *(uint32_t*)&t;
    float hf0 = __uint_as_float(hi2 << 16);
    float hf1 = __uint_as_float(hi2 & 0xffff0000u);
    __nv_bfloat162 tl = __floats2bfloat162_rn(a - hf0, b - hf1);
    lo2 = *(uint32_t*)&tl;
    return hi2;
}
#define SMEM_SWZ(off)   ((off) ^ (((off) >> 3) & 0x70))   // SW128 (128B rows)
#define SMEM_SWZ64(off) ((off) ^ (((off) >> 3) & 0x30))   // SW64  (64B rows)

// cp.async (sm_80+)
__device__ __forceinline__ void cp16(uint32_t dst, const void* src) {
    asm volatile("cp.async.cg.shared.global [%0], [%1], 16;" :: "r"(dst), "l"(src) : "memory");
}
#define CP_COMMIT() asm volatile("cp.async.commit_group;" ::: "memory")
#define CP_WAIT0()  asm volatile("cp.async.wait_group 0;" ::: "memory")
#define CP_WAIT1()  asm volatile("cp.async.wait_group 1;" ::: "memory")

#if HAS_TCGEN05
__device__ __forceinline__ bool elect1() {
    uint32_t r;
    asm volatile("{\n\t.reg .pred p;\n\telect.sync _|p, 0xFFFFFFFF;\n\tselp.b32 %0, 1, 0, p;\n\t}" : "=r"(r));
    return r != 0;
}
#define MBAR_INIT(addr, cnt) \
    asm volatile("mbarrier.init.shared.b64 [%0], %1;" :: "r"(addr), "r"(cnt) : "memory")
#define MBAR_WAIT(addr, ph) do {                                              \
    uint32_t _m = (addr), _p = (ph), _d;                                      \
    asm volatile("{\n\t.reg .pred p;\n\t"                                     \
        "mbarrier.try_wait.parity.acquire.cta.shared::cta.b64 p, [%1], %2;\n\t" \
        "selp.b32 %0, 1, 0, p;\n\t}" : "=r"(_d) : "r"(_m), "r"(_p) : "memory"); \
    if (!_d) {                                                                \
        asm volatile("{\n\t.reg .pred P1;\n\t"                                \
            "WL_%=:\n\t"                                                      \
            "mbarrier.try_wait.parity.acquire.cta.shared::cta.b64 P1, [%0], %1, 0x989680;\n\t" \
            "@P1 bra.uni WD_%=;\n\tbra.uni WL_%=;\n\tWD_%=:\n\t}"             \
            :: "r"(_m), "r"(_p) : "memory");                                  \
    }                                                                         \
} while (0)
#define TC_ALLOC(smem_addr, ncols) \
    asm volatile("tcgen05.alloc.cta_group::1.sync.aligned.shared::cta.b32 [%0], %1;" \
                 :: "r"(smem_addr), "r"(ncols) : "memory")
#define TC_RELINQ() \
    asm volatile("tcgen05.relinquish_alloc_permit.cta_group::1.sync.aligned;")
#define TC_DEALLOC(tmem, ncols) \
    asm volatile("tcgen05.dealloc.cta_group::1.sync.aligned.b32 %0, %1;" :: "r"(tmem), "r"(ncols))
#define TC_COMMIT(mbar) \
    asm volatile("tcgen05.commit.cta_group::1.mbarrier::arrive::one.shared::cluster.b64 [%0];" \
                 :: "r"(mbar) : "memory")
#define TC_FENCE_AFTER()  asm volatile("tcgen05.fence::after_thread_sync;" ::: "memory")
#define TC_FENCE_BEFORE() asm volatile("tcgen05.fence::before_thread_sync;" ::: "memory")
#define TC_WAIT_LD()      asm volatile("tcgen05.wait::ld.sync.aligned;" ::: "memory")
#define TC_WAIT_ST()      asm volatile("tcgen05.wait::st.sync.aligned;" ::: "memory")
#define FENCE_ASYNC()     asm volatile("fence.proxy.async.shared::cta;" ::: "memory")

#define LDTM_X32(r, a) \
    asm volatile("tcgen05.ld.sync.aligned.32x32b.x32.b32 "                    \
        "{%0, %1, %2, %3, %4, %5, %6, %7, %8, %9, %10, %11, %12, %13, %14, %15, " \
        " %16, %17, %18, %19, %20, %21, %22, %23, %24, %25, %26, %27, %28, %29, %30, %31}, [%32];" \
        : "=r"((r)[0]),  "=r"((r)[1]),  "=r"((r)[2]),  "=r"((r)[3]),          \
          "=r"((r)[4]),  "=r"((r)[5]),  "=r"((r)[6]),  "=r"((r)[7]),          \
          "=r"((r)[8]),  "=r"((r)[9]),  "=r"((r)[10]), "=r"((r)[11]),         \
          "=r"((r)[12]), "=r"((r)[13]), "=r"((r)[14]), "=r"((r)[15]),         \
          "=r"((r)[16]), "=r"((r)[17]), "=r"((r)[18]), "=r"((r)[19]),         \
          "=r"((r)[20]), "=r"((r)[21]), "=r"((r)[22]), "=r"((r)[23]),         \
          "=r"((r)[24]), "=r"((r)[25]), "=r"((r)[26]), "=r"((r)[27]),         \
          "=r"((r)[28]), "=r"((r)[29]), "=r"((r)[30]), "=r"((r)[31])          \
        : "r"(a))

#define STTM_X16(a, r) \
    asm volatile("tcgen05.st.sync.aligned.32x32b.x16.b32 [%0], "              \
        "{%1, %2, %3, %4, %5, %6, %7, %8, %9, %10, %11, %12, %13, %14, %15, %16};" \
        :: "r"(a),                                                            \
           "r"((r)[0]),  "r"((r)[1]),  "r"((r)[2]),  "r"((r)[3]),             \
           "r"((r)[4]),  "r"((r)[5]),  "r"((r)[6]),  "r"((r)[7]),             \
           "r"((r)[8]),  "r"((r)[9]),  "r"((r)[10]), "r"((r)[11]),            \
           "r"((r)[12]), "r"((r)[13]), "r"((r)[14]), "r"((r)[15])             \
        : "memory")

// K-major SW128 desc (128B rows): SBO=64, LBO=1
static __device__ __forceinline__ uint64_t make_desc(uint32_t addr) {
    const uint64_t base = (uint64_t(2) << 61) | (uint64_t(1) << 46)
                        | (uint64_t(64) << 32) | (uint64_t(1) << 16);
    return base | ((uint64_t)(addr >> 4) & 0x3FFF);
}
// K-major SW64 desc (64B rows): layout=4, SBO=32, LBO=1
static __device__ __forceinline__ uint64_t make_desc_sw64(uint32_t addr) {
    const uint64_t base = (uint64_t(4) << 61) | (uint64_t(1) << 46)
                        | (uint64_t(32) << 32) | (uint64_t(1) << 16);
    return base | ((uint64_t)(addr >> 4) & 0x3FFF);
}
__device__ __forceinline__ void mma_bf16_ss(uint32_t d, uint64_t ad, uint64_t bd,
                                            uint32_t idesc, bool acc) {
    uint32_t en = acc ? 1u : 0u;
    asm volatile(
        "{\n\t.reg .pred p;\n\tsetp.ne.u32 p, %4, 0;\n\t"
        "tcgen05.mma.cta_group::1.kind::f16 [%0], %1, %2, %3, {%5, %5, %5, %5}, p;\n\t}"
        :: "r"(d), "l"(ad), "l"(bd), "r"(idesc), "r"(en), "r"(0u) : "memory");
}
__device__ __forceinline__ void mma_bf16_ts(uint32_t d, uint32_t a, uint64_t bd,
                                            uint32_t idesc, bool acc) {
    uint32_t en = acc ? 1u : 0u;
    asm volatile(
        "{\n\t.reg .pred p;\n\tsetp.ne.u32 p, %4, 0;\n\t"
        "tcgen05.mma.cta_group::1.kind::f16 [%0], [%1], %2, %3, {%5, %5, %5, %5}, p;\n\t}"
        :: "r"(d), "r"(a), "l"(bd), "r"(idesc), "r"(en), "r"(0u) : "memory");
}
#define GEMM_IDESC  ((1u << 4) | (1u << 7) | (1u << 10) | (16u << 17) | (8u << 24))  // M128 N128
#define ATTN_IDESC1 ((1u << 4) | (1u << 7) | (1u << 10) | (16u << 17) | (8u << 24))  // M128 N128
#define ATTN_IDESC2 ((1u << 4) | (1u << 7) | (1u << 10) | (8u  << 17) | (8u << 24))  // M128 N64
#endif  // HAS_TCGEN05

// ---------------------------------------------------------------------------
// Elementwise split: fp32 -> bf16 hi/lo (8 elems/thread)
// ---------------------------------------------------------------------------
__global__ __launch_bounds__(256) void split_f32_kernel(
    const float* __restrict__ X, __nv_bfloat16* __restrict__ Xhi,
    __nv_bfloat16* __restrict__ Xlo)
{
    const size_t i = ((size_t)blockIdx.x * 256 + threadIdx.x) * 8;
    float4 a = *(const float4*)(X + i);
    float4 b = *(const float4*)(X + i + 4);
    uint4 h, l;
    h.x = pk_hi(a.x, a.y); h.y = pk_hi(a.z, a.w);
    h.z = pk_hi(b.x, b.y); h.w = pk_hi(b.z, b.w);
    l.x = pk_lo(a.x, a.y); l.y = pk_lo(a.z, a.w);
    l.z = pk_lo(b.x, b.y); l.w = pk_lo(b.z, b.w);
    *(uint4*)(Xhi + i) = h;
    *(uint4*)(Xlo + i) = l;
}

// ---------------------------------------------------------------------------
// Transpose + bf16 hi/lo split: W[K,N] -> Thi/Tlo[N,K]
// ---------------------------------------------------------------------------
__global__ __launch_bounds__(256) void transpose_split_kernel(
    const float* __restrict__ W, __nv_bfloat16* __restrict__ Thi,
    __nv_bfloat16* __restrict__ Tlo, int K, int N)
{
    __shared__ float t[32][33];
    const int n0 = blockIdx.x << 5, k0 = blockIdx.y << 5;
    const int x = threadIdx.x, y = threadIdx.y;
    #pragma unroll
    for (int i = y; i < 32; i += 8)
        t[i][x] = W[(size_t)(k0 + i) * N + n0 + x];
    __syncthreads();
    #pragma unroll
    for (int i = y; i < 32; i += 8) {
        float v  = t[x][i];
        __nv_bfloat16 hb = __float2bfloat16_rn(v);
        size_t o = (size_t)(n0 + i) * K + k0 + x;
        Thi[o] = hb;
        Tlo[o] = __float2bfloat16_rn(v - __bfloat162float(hb));
    }
}

// ---------------------------------------------------------------------------
// GEMM (unchanged): cp.async, BK=32, SW64, 3x32KB, 2 CTAs/SM
// ---------------------------------------------------------------------------
#define GSTG 32768
__global__ __launch_bounds__(256, 2)
void gemm_bf16pre_kernel(const __nv_bfloat16* __restrict__ Ahi,
                         const __nv_bfloat16* __restrict__ Alo,
                         const __nv_bfloat16* __restrict__ Bhi,
                         const __nv_bfloat16* __restrict__ Blo,
                         const float* __restrict__ bias,
                         float* __restrict__ Cf,
                         __nv_bfloat16* __restrict__ Chi,
                         __nv_bfloat16* __restrict__ Clo,
                         int M, int N, int K)
{
#if HAS_TCGEN05
    extern __shared__ char dyn[];
    char* tiles = (char*)(((uintptr_t)dyn + 1023) & ~(uintptr_t)1023);
    float*    biass = (float*)(tiles + 3 * GSTG);
    uint64_t* mbar  = (uint64_t*)(tiles + 3 * GSTG + 512);
    uint32_t* tptr  = (uint32_t*)(tiles + 3 * GSTG + 512 + 24);

    const int tid  = threadIdx.x;
    const int wid  = tid >> 5;
    const int lane = tid & 31;
    const int row0 = blockIdx.y << 7, col0 = blockIdx.x << 7;

    const uint32_t tiles_u = su32(tiles);
    const uint32_t mbar_u  = su32(mbar);

    if (tid == 0) { MBAR_INIT(mbar_u, 1); MBAR_INIT(mbar_u + 8, 1); MBAR_INIT(mbar_u + 16, 1); }
    if (wid == 0) { TC_ALLOC(su32(tptr), 128); TC_RELINQ(); }
    if (tid < 128) biass[tid] = bias[col0 + tid];
    __syncthreads();
    const uint32_t tmem = *tptr;

    const int NS = K >> 5;

    auto load_stage = [&](int s, int b) {
        uint32_t base = tiles_u + b * GSTG;
        const int koff = s << 5;
        #pragma unroll
        for (int i = 0; i < 2; i++) {
            int cg  = tid + (i << 8);
            int row = cg >> 2, ch = cg & 3;
            uint32_t sw = SMEM_SWZ64((uint32_t)(row * 64 + ch * 16));
            size_t aoff = (size_t)(row0 + row) * K + koff + (ch << 3);
            size_t boff = (size_t)(col0 + row) * K + koff + (ch << 3);
            cp16(base + sw,         Ahi + aoff);
            cp16(base + 8192 + sw,  Alo + aoff);
            cp16(base + 16384 + sw, Bhi + boff);
            cp16(base + 24576 + sw, Blo + boff);
        }
        CP_COMMIT();
    };

    auto issue_stage = [&](int s, int b, bool first) {
        uint32_t a0 = tiles_u + b * GSTG;
        uint64_t dAh = make_desc_sw64(a0);
        uint64_t dAl = make_desc_sw64(a0 + 8192);
        uint64_t dBh = make_desc_sw64(a0 + 16384);
        uint64_t dBl = make_desc_sw64(a0 + 24576);
        #pragma unroll
        for (int j = 0; j < 2; j++) {
            mma_bf16_ss(tmem, dAh + j * 2, dBh + j * 2, GEMM_IDESC, !(first && j == 0));
            mma_bf16_ss(tmem, dAh + j * 2, dBl + j * 2, GEMM_IDESC, true);
            mma_bf16_ss(tmem, dAl + j * 2, dBh + j * 2, GEMM_IDESC, true);
        }
        TC_COMMIT(mbar_u + (uint32_t)(s % 3) * 8);
    };

    load_stage(0, 0);
    load_stage(1, 1);
    CP_WAIT1();
    FENCE_ASYNC();
    __syncthreads();
    if (wid == 0 && elect1()) issue_stage(0, 0, true);

    for (int s = 0; s < NS; s++) {
        if (s >= 1) { int w = s - 1; MBAR_WAIT(mbar_u + (w % 3) * 8, (w / 3) & 1); }
        const bool loaded = (s + 2 < NS);
        if (loaded) load_stage(s + 2, (s + 2) % 3);
        if (s + 1 < NS) {
            if (loaded) CP_WAIT1(); else CP_WAIT0();
            FENCE_ASYNC();
            __syncthreads();
            if (wid == 0 && elect1()) issue_stage(s + 1, (s + 1) % 3, false);
        }
    }
    { int w = NS - 1; MBAR_WAIT(mbar_u + (w % 3) * 8, (w / 3) & 1); }
    CP_WAIT0();

    TC_FENCE_AFTER();
    if (tid < 128) {
        const int er = row0 + wid * 32 + lane;
        #pragma unroll
        for (int c0 = 0; c0 < 128; c0 += 32) {
            uint32_t rg[32];
            LDTM_X32(rg, tmem + c0);
            TC_WAIT_LD();
            float v[32];
            #pragma unroll
            for (int j = 0; j < 32; j++)
                v[j] = __uint_as_float(rg[j]) + biass[c0 + j];
            if (Chi) {
                __nv_bfloat16* ph = Chi + (size_t)er * N + col0 + c0;
                __nv_bfloat16* pl = Clo + (size_t)er * N + col0 + c0;
                #pragma unroll
                for (int q = 0; q < 4; q++) {
                    uint4 hh, ll;
                    hh.x = pk_hi(v[8*q+0], v[8*q+1]); ll.x = pk_lo(v[8*q+0], v[8*q+1]);
                    hh.y = pk_hi(v[8*q+2], v[8*q+3]); ll.y = pk_lo(v[8*q+2], v[8*q+3]);
                    hh.z = pk_hi(v[8*q+4], v[8*q+5]); ll.z = pk_lo(v[8*q+4], v[8*q+5]);
                    hh.w = pk_hi(v[8*q+6], v[8*q+7]); ll.w = pk_lo(v[8*q+6], v[8*q+7]);
                    *(uint4*)(ph + 8*q) = hh;
                    *(uint4*)(pl + 8*q) = ll;
                }
            } else {
                float* cp = Cf + (size_t)er * N + col0 + c0;
                #pragma unroll
                for (int j = 0; j < 8; j++) {
                    float4 o;
                    o.x = v[4*j+0]; o.y = v[4*j+1]; o.z = v[4*j+2]; o.w = v[4*j+3];
                    *(float4*)(cp + 4 * j) = o;
                }
            }
        }
    }
    __syncthreads();
    if (wid == 0) TC_DEALLOC(tmem, 128);

#else  // ------- generic fallback (compile-only on this rig) -------
    extern __shared__ char dyn[];
    float* As = (float*)dyn;
    float* Bs = As + 16 * 132;

    const int tid = threadIdx.x;
    const int tx  = tid & 15, ty = tid >> 4;
    const int row0 = blockIdx.y << 7, col0 = blockIdx.x << 7;

    float acc[8][8] = {};
    for (int k0 = 0; k0 < K; k0 += 16) {
        __syncthreads();
        #pragma unroll
        for (int t = 0; t < 2; t++) {
            int ch = tid + (t << 8);
            int rr = ch >> 2, c4 = (ch & 3) << 2;
            size_t ao = (size_t)(row0 + rr) * K + k0 + c4;
            size_t bo = (size_t)(col0 + rr) * K + k0 + c4;
            #pragma unroll
            for (int q = 0; q < 4; q++) {
                As[(c4 + q) * 132 + rr] = __bfloat162float(Ahi[ao + q]) + __bfloat162float(Alo[ao + q]);
                Bs[(c4 + q) * 132 + rr] = __bfloat162float(Bhi[bo + q]) + __bfloat162float(Blo[bo + q]);
            }
        }
        __syncthreads();
        #pragma unroll
        for (int kk = 0; kk < 16; kk++) {
            float a[8], b[8];
            #pragma unroll
            for (int i = 0; i < 8; i++) a[i] = As[kk * 132 + ty * 8 + i];
            #pragma unroll
            for (int j = 0; j < 8; j++) b[j] = Bs[kk * 132 + tx * 8 + j];
            #pragma unroll
            for (int i = 0; i < 8; i++)
                #pragma unroll
                for (int j = 0; j < 8; j++) acc[i][j] += a[i] * b[j];
        }
    }
    #pragma unroll
    for (int i = 0; i < 8; i++)
        #pragma unroll
        for (int j = 0; j < 8; j++) {
            float v = acc[i][j] + bias[col0 + tx * 8 + j];
            size_t o = (size_t)(row0 + ty * 8 + i) * N + col0 + tx * 8 + j;
            if (Chi) {
                __nv_bfloat16 hb = __float2bfloat16_rn(v);
                Chi[o] = hb;
                Clo[o] = __float2bfloat16_rn(v - __bfloat162float(hb));
            } else {
                Cf[o] = v;
            }
        }
#endif
}

// ---------------------------------------------------------------------------
// Attention: TMEM-resident O, distance-2 K prefetch, and (R17) chunked
// LDTM/exp pipeline: LDTM(u1) hides under exp(u0); exp(u1) hides MMA1(kb+1).
// TMEM (alloc 512): S @0(128), PHI @128(64), PLO @192(64), U @256(64)
// ---------------------------------------------------------------------------
#define AS_QHI   0
#define AS_QLO   16384
#define AS_KB(b) (32768 + (b) * 32768)       // KHI at +0, KLO at +16384
#define AS_VHI   98304
#define AS_VLO   114688
#define AS_PSUM  131072
#define AS_RED   132096
#define AS_MBAR  132608
#define AS_TPTR  132624
#define ATTN_SMEM_BYTES (1024 + 132640)

#define TM_S    0
#define TM_PHI  128
#define TM_PLO  192
#define TM_U    256

__global__ __launch_bounds__(256) void attn_tc_kernel()
{
#if HAS_TCGEN05
    extern __shared__ char dyn[];
    char* smc = (char*)(((uintptr_t)dyn + 1023) & ~(uintptr_t)1023);
    const uint32_t smu = su32(smc);

    const int tid  = threadIdx.x;
    const int wid  = tid >> 5;
    const int lane = tid & 31;
    const int sp   = wid & 3;
    const int half = wid >> 2;
    const int qb   = (gridDim.x - 1) - blockIdx.x;   // big tiles first
    const int h = blockIdx.y, b = blockIdx.z;
    const int q0   = qb << 7;
    const int r    = sp * 32 + lane;

    const size_t hbase = (size_t)b * SEQ * QLD + h * (3 * HD);
    const __nv_bfloat16* qh = g_qkv_hi + hbase;
    const __nv_bfloat16* ql = g_qkv_lo + hbase;
    const __nv_bfloat16* kh = qh + HD;
    const __nv_bfloat16* kl = ql + HD;
    const __nv_bfloat16* vh = qh + 2 * HD;
    const __nv_bfloat16* vl = ql + 2 * HD;

    float* psums = (float*)(smc + AS_PSUM);
    float* red   = (float*)(smc + AS_RED);
    const uint32_t mb = smu + AS_MBAR;

    if (tid == 0) MBAR_INIT(mb, 1);
    if (wid == 0) { TC_ALLOC(smu + AS_TPTR, 512); TC_RELINQ(); }
    __syncthreads();
    const uint32_t tmem = *(uint32_t*)(smc + AS_TPTR);
    const uint32_t warpoff = (uint32_t)sp << 21;

    const float C = 0.125f * 1.44269504f;

    auto load_k_tile = [&](int k0, int buf) {
        uint32_t base = smu + AS_KB(buf);
        #pragma unroll
        for (int i = 0; i < 4; i++) {
            int cg  = tid + (i << 8);
            int row = cg >> 3, ch = cg & 7;
            uint32_t sw = SMEM_SWZ((uint32_t)(row * 128 + ch * 16));
            size_t off = (size_t)(k0 + row) * QLD + (ch << 3);
            cp16(base + sw,         kh + off);
            cp16(base + 16384 + sw, kl + off);
        }
        CP_COMMIT();
    };

    const int vp_p  = tid & 63;
    const int vp_dh = tid >> 6;
    const int vp_panel = vp_p >> 5;
    const int vp_pc    = vp_p & 31;

    uint32_t E[8], Od[8], El[8], Ol[8];
    auto load_v_regs = [&](int k0) {
        const size_t e_off = (size_t)(k0 + 2 * vp_p) * QLD + (vp_dh << 4);
        const size_t o_off = e_off + QLD;
        *(uint4*)&E[0]  = *(const uint4*)(vh + e_off);
        *(uint4*)&E[4]  = *(const uint4*)(vh + e_off + 8);
        *(uint4*)&Od[0] = *(const uint4*)(vh + o_off);
        *(uint4*)&Od[4] = *(const uint4*)(vh + o_off + 8);
        *(uint4*)&El[0] = *(const uint4*)(vl + e_off);
        *(uint4*)&El[4] = *(const uint4*)(vl + e_off + 8);
        *(uint4*)&Ol[0] = *(const uint4*)(vl + o_off);
        *(uint4*)&Ol[4] = *(const uint4*)(vl + o_off + 8);
    };
    auto store_v_smem = [&]() {
        #pragma unroll
        for (int j = 0; j < 8; j++) {
            int d = (vp_dh << 4) + 2 * j;
            uint32_t w0h = __byte_perm(E[j],  Od[j], 0x5410);
            uint32_t w1h = __byte_perm(E[j],  Od[j], 0x7632);
            uint32_t w0l = __byte_perm(El[j], Ol[j], 0x5410);
            uint32_t w1l = __byte_perm(El[j], Ol[j], 0x7632);
            uint32_t off0 = SMEM_SWZ((uint32_t)(d * 128 + vp_pc * 4));
            uint32_t off1 = SMEM_SWZ((uint32_t)((d + 1) * 128 + vp_pc * 4));
            *(uint32_t*)(smc + AS_VHI + vp_panel * 8192 + off0) = w0h;
            *(uint32_t*)(smc + AS_VHI + vp_panel * 8192 + off1) = w1h;
            *(uint32_t*)(smc + AS_VLO + vp_panel * 8192 + off0) = w0l;
            *(uint32_t*)(smc + AS_VLO + vp_panel * 8192 + off1) = w1l;
        }
    };

    auto issue_mma1 = [&](int buf) {
        uint64_t dQh = make_desc(smu + AS_QHI);
        uint64_t dQl = make_desc(smu + AS_QLO);
        uint64_t dKh = make_desc(smu + AS_KB(buf));
        uint64_t dKl = make_desc(smu + AS_KB(buf) + 16384);
        bool first = true;
        #pragma unroll
        for (int j = 0; j < 4; j++) {
            mma_bf16_ss(tmem + TM_S, dQh + j * 2, dKh + j * 2, ATTN_IDESC1, !first);
            first = false;
            mma_bf16_ss(tmem + TM_S, dQh + j * 2, dKl + j * 2, ATTN_IDESC1, true);
            mma_bf16_ss(tmem + TM_S, dQl + j * 2, dKh + j * 2, ATTN_IDESC1, true);
        }
    };

    // exp + pack + STTM for one 32-col chunk; returns partial row sum
    auto soft_chunk = [&](const uint32_t* u, int cb, bool diag, int qg, uint32_t col) {
        float p[32];
        float ps = 0.0f;
        #pragma unroll
        for (int j = 0; j < 32; j++) {
            float e = exp2f(__uint_as_float(u[j]) * C);
            if (diag && cb + j > qg) e = 0.0f;
            p[j] = e; ps += e;
        }
        uint32_t hw[16], lw[16];
        #pragma unroll
        for (int j = 0; j < 16; j++)
            hw[j] = pk_pair(p[2*j], p[2*j+1], lw[j]);
        STTM_X16(tmem + TM_PHI + col + warpoff, hw);
        STTM_X16(tmem + TM_PLO + col + warpoff, lw);
        return ps;
    };

    // ---- Prologue: Q copy, K(0)+K(1) copies, V(0)->regs; issue MMA1(0) ----
    #pragma unroll
    for (int i = 0; i < 4; i++) {
        int cg  = tid + (i << 8);
        int row = cg >> 3, ch = cg & 7;
        uint32_t sw = SMEM_SWZ((uint32_t)(row * 128 + ch * 16));
        size_t off = (size_t)(q0 + row) * QLD + (ch << 3);
        cp16(smu + AS_QHI + sw, qh + off);
        cp16(smu + AS_QLO + sw, ql + off);
    }
    CP_COMMIT();
    load_k_tile(0, 0);
    if (qb >= 1) load_k_tile(128, 1);
    load_v_regs(0);
    CP_WAIT0();
    FENCE_ASYNC();
    __syncthreads();
    if (wid == 0) {
        TC_FENCE_AFTER();
        if (elect1()) { issue_mma1(0); TC_COMMIT(mb); }
    }

    float l_run = 0.0f;
    int pt = 0;

    for (int kb = 0; kb <= qb; kb++) {
        const int k0 = kb << 7;

        // wait: MMA1(kb) done (and MMA2(kb-1) done — same commit chain)
        MBAR_WAIT(mb, pt); pt ^= 1;
        TC_FENCE_AFTER();

        // chunked S drain: u0 now; u1 in flight under exp(u0)
        uint32_t u0[32], u1[32];
        LDTM_X32(u0, tmem + TM_S + half * 64);
        TC_WAIT_LD();
        LDTM_X32(u1, tmem + TM_S + half * 64 + 32);

        // V(kb) regs -> smem + distance-2 K prefetch (overlap LDTM u1)
        store_v_smem();
        const bool lk = (kb + 2 <= qb);
        if (lk) load_k_tile(k0 + 256, kb & 1);

        const int qg = q0 + r;
        const bool diag = (kb == qb);
        float ps = soft_chunk(u0, k0 + half * 64, diag, qg, half * 32);

        TC_WAIT_LD();            // u1 ready (all S reads done in this warp)
        TC_FENCE_BEFORE();
        if (kb < qb) { if (lk) CP_WAIT1(); else CP_WAIT0(); }
        FENCE_ASYNC();
        __syncthreads();         // all warps drained S; V smem + K(kb+1) visible

        // pre-issue MMA1(kb+1); exp(u1) below overlaps it
        if (kb < qb && wid == 0) {
            TC_FENCE_AFTER();
            if (elect1()) issue_mma1((kb + 1) & 1);
        }

        ps += soft_chunk(u1, k0 + half * 64 + 32, diag, qg, half * 32 + 16);
        psums[r * 2 + half] = ps;
        TC_WAIT_ST();
        TC_FENCE_BEFORE();
        __syncthreads();

        if (half == 0)
            l_run += psums[r * 2] + psums[r * 2 + 1];

        // MMA2(kb): U += P @ Vt^T; commit covers MMA1(kb+1) too
        if (wid == 0) {
            TC_FENCE_AFTER();
            if (elect1()) {
                bool first = (kb == 0);
                #pragma unroll
                for (int panel = 0; panel < 2; panel++) {
                    uint64_t dVh = make_desc(smu + AS_VHI + panel * 8192);
                    uint64_t dVl = make_desc(smu + AS_VLO + panel * 8192);
                    #pragma unroll
                    for (int j = 0; j < 4; j++) {
                        uint32_t acol = panel * 32 + j * 8;
                        mma_bf16_ts(tmem + TM_U, tmem + TM_PHI + acol, dVh + j * 2, ATTN_IDESC2, !first);
                        first = false;
                        mma_bf16_ts(tmem + TM_U, tmem + TM_PHI + acol, dVl + j * 2, ATTN_IDESC2, true);
                        mma_bf16_ts(tmem + TM_U, tmem + TM_PLO + acol, dVh + j * 2, ATTN_IDESC2, true);
                    }
                }
                TC_COMMIT(mb);
            }
        }

        // prefetch V(kb+1) into regs (hides under MMA2)
        if (kb < qb) load_v_regs(k0 + 128);
    }

    // ---- Epilogue: final MMA2 done -> read U once, normalize, write ----
    MBAR_WAIT(mb, pt);
    TC_FENCE_AFTER();
    if (half == 0) red[r] = 1.0f / l_run;
    __syncthreads();
    {
        uint32_t u[32];
        LDTM_X32(u, tmem + TM_U + half * 32);
        TC_WAIT_LD();
        TC_FENCE_BEFORE();
        const float inv = red[r];
        const size_t vo = ((size_t)b * SEQ + q0 + r) * DM + h * HD + half * 32;
        float v[32];
        #pragma unroll
        for (int c = 0; c < 32; c++) v[c] = __uint_as_float(u[c]) * inv;
        uint4 hh, ll;
        #pragma unroll
        for (int q = 0; q < 4; q++) {
            hh.x = pk_hi(v[8*q+0], v[8*q+1]); ll.x = pk_lo(v[8*q+0], v[8*q+1]);
            hh.y = pk_hi(v[8*q+2], v[8*q+3]); ll.y = pk_lo(v[8*q+2], v[8*q+3]);
            hh.z = pk_hi(v[8*q+4], v[8*q+5]); ll.z = pk_lo(v[8*q+4], v[8*q+5]);
            hh.w = pk_hi(v[8*q+6], v[8*q+7]); ll.w = pk_lo(v[8*q+6], v[8*q+7]);
            *(uint4*)(g_val_hi + vo + 8*q) = hh;
            *(uint4*)(g_val_lo + vo + 8*q) = ll;
        }
    }
    __syncthreads();
    if (wid == 0) TC_DEALLOC(tmem, 512);

#else  // ------- generic fallback (compile-only on this rig) -------
    extern __shared__ float sm[];
    float* Qs = sm;
    float* Ks = sm + 64 * 68;
    float* Vs = sm + 2 * 64 * 68;
    float* Ps = sm + 3 * 64 * 68;

    const int tid = threadIdx.x;
    const int tx  = tid & 15, ty = tid >> 4;
    const int h = blockIdx.y, b = blockIdx.z;

    const size_t hbase = (size_t)b * SEQ * QLD + h * (3 * HD);

    for (int sub = 0; sub < 2; sub++) {
        const int q0 = (blockIdx.x << 7) + (sub << 6);
        __syncthreads();
        for (int idx = tid; idx < 64 * 64; idx += 256) {
            int rr = idx >> 6, d = idx & 63;
            size_t o = hbase + (size_t)(q0 + rr) * QLD + d;
            Qs[d * 68 + rr] = (__bfloat162float(g_qkv_hi[o]) + __bfloat162float(g_qkv_lo[o])) * 0.125f;
        }

        float m_i[4] = {-3e38f, -3e38f, -3e38f, -3e38f};
        float l_i[4] = {};
        float acc[4][4] = {};
        const int nkb = (q0 >> 6) + 1;

        for (int kb = 0; kb < nkb; kb++) {
            const int k0 = kb << 6;
            __syncthreads();
            for (int idx = tid; idx < 64 * 64; idx += 256) {
                int c = idx >> 6, d = idx & 63;
                size_t ko = hbase + (size_t)(k0 + c) * QLD + HD + d;
                size_t vo = ko + HD;
                Ks[d * 68 + c] = __bfloat162float(g_qkv_hi[ko]) + __bfloat162float(g_qkv_lo[ko]);
                Vs[c * 68 + d] = __bfloat162float(g_qkv_hi[vo]) + __bfloat162float(g_qkv_lo[vo]);
            }
            __syncthreads();

            float s[4][4] = {};
            for (int d = 0; d < 64; d++) {
                float a0 = Qs[d*68+(ty<<2)], a1 = Qs[d*68+(ty<<2)+1];
                float a2 = Qs[d*68+(ty<<2)+2], a3 = Qs[d*68+(ty<<2)+3];
                float b0 = Ks[d*68+(tx<<2)], b1 = Ks[d*68+(tx<<2)+1];
                float b2 = Ks[d*68+(tx<<2)+2], b3 = Ks[d*68+(tx<<2)+3];
                s[0][0]+=a0*b0; s[0][1]+=a0*b1; s[0][2]+=a0*b2; s[0][3]+=a0*b3;
                s[1][0]+=a1*b0; s[1][1]+=a1*b1; s[1][2]+=a1*b2; s[1][3]+=a1*b3;
                s[2][0]+=a2*b0; s[2][1]+=a2*b1; s[2][2]+=a2*b2; s[2][3]+=a2*b3;
                s[3][0]+=a3*b0; s[3][1]+=a3*b1; s[3][2]+=a3*b2; s[3][3]+=a3*b3;
            }
            if (kb == nkb - 1)
                for (int i = 0; i < 4; i++)
                    for (int j = 0; j < 4; j++)
                        if ((tx<<2)+j > (ty<<2)+i) s[i][j] = -1e9f;
            for (int i = 0; i < 4; i++) {
                float mx = fmaxf(fmaxf(s[i][0], s[i][1]), fmaxf(s[i][2], s[i][3]));
                for (int off = 8; off > 0; off >>= 1)
                    mx = fmaxf(mx, __shfl_xor_sync(0xffffffffu, mx, off, 16));
                float mnew = fmaxf(m_i[i], mx);
                float p0 = __expf(s[i][0]-mnew), p1 = __expf(s[i][1]-mnew);
                float p2 = __expf(s[i][2]-mnew), p3 = __expf(s[i][3]-mnew);
                float ls = p0+p1+p2+p3;
                for (int off = 8; off > 0; off >>= 1)
                    ls += __shfl_xor_sync(0xffffffffu, ls, off, 16);
                float alpha = __expf(m_i[i] - mnew);
                l_i[i] = l_i[i]*alpha + ls;
                m_i[i] = mnew;
                acc[i][0]*=alpha; acc[i][1]*=alpha; acc[i][2]*=alpha; acc[i][3]*=alpha;
                s[i][0]=p0; s[i][1]=p1; s[i][2]=p2; s[i][3]=p3;
            }
            for (int i = 0; i < 4; i++)
                for (int j = 0; j < 4; j++)
                    Ps[((tx<<2)+j)*68 + (ty<<2)+i] = s[i][j];
            __syncthreads();
            for (int c = 0; c < 64; c++) {
                float a0 = Ps[c*68+(ty<<2)], a1 = Ps[c*68+(ty<<2)+1];
                float a2 = Ps[c*68+(ty<<2)+2], a3 = Ps[c*68+(ty<<2)+3];
                float b0 = Vs[c*68+(tx<<2)], b1 = Vs[c*68+(tx<<2)+1];
                float b2 = Vs[c*68+(tx<<2)+2], b3 = Vs[c*68+(tx<<2)+3];
                acc[0][0]+=a0*b0; acc[0][1]+=a0*b1; acc[0][2]+=a0*b2; acc[0][3]+=a0*b3;
                acc[1][0]+=a1*b0; acc[1][1]+=a1*b1; acc[1][2]+=a1*b2; acc[1][3]+=a1*b3;
                acc[2][0]+=a2*b0; acc[2][1]+=a2*b1; acc[2][2]+=a2*b2; acc[2][3]+=a2*b3;
                acc[3][0]+=a3*b0; acc[3][1]+=a3*b1; acc[3][2]+=a3*b2; acc[3][3]+=a3*b3;
            }
        }
        for (int i = 0; i < 4; i++) {
            float inv = 1.0f / l_i[i];
            for (int j = 0; j < 4; j++) {
                float v = acc[i][j] * inv;
                size_t o = ((size_t)b * SEQ + q0 + (ty<<2)+i) * DM + h * HD + (tx<<2)+j;
                __nv_bfloat16 hb = __float2bfloat16_rn(v);
                g_val_hi[o] = hb;
                g_val_lo[o] = __float2bfloat16_rn(v - __bfloat162float(hb));
            }
        }
        __syncthreads();
    }
#endif
}

// ---------------------------------------------------------------------------
// Launch
// ---------------------------------------------------------------------------
extern "C" void kernel_launch(void* const* d_in, const int* in_sizes, int n_in,
                              void* d_out, int out_size)
{
    const float* x    = (const float*)d_in[0];
    const float* Wqkv = (const float*)d_in[1];
    const float* bqkv = (const float*)d_in[2];
    const float* Wout = (const float*)d_in[3];
    const float* bout = (const float*)d_in[4];
    float* out = (float*)d_out;

    __nv_bfloat16 *x_hi, *x_lo, *qkv_hi, *qkv_lo, *val_hi, *val_lo;
    __nv_bfloat16 *wq_hi, *wq_lo, *wo_hi, *wo_lo;
    cudaGetSymbolAddress((void**)&x_hi,   g_x_hi);
    cudaGetSymbolAddress((void**)&x_lo,   g_x_lo);
    cudaGetSymbolAddress((void**)&qkv_hi, g_qkv_hi);
    cudaGetSymbolAddress((void**)&qkv_lo, g_qkv_lo);
    cudaGetSymbolAddress((void**)&val_hi, g_val_hi);
    cudaGetSymbolAddress((void**)&val_lo, g_val_lo);
    cudaGetSymbolAddress((void**)&wq_hi,  g_wqkvT_hi);
    cudaGetSymbolAddress((void**)&wq_lo,  g_wqkvT_lo);
    cudaGetSymbolAddress((void**)&wo_hi,  g_woutT_hi);
    cudaGetSymbolAddress((void**)&wo_lo,  g_woutT_lo);

    const int gemm_smem = 1024 + 3 * GSTG + 512 + 64;
    const int attn_smem = ATTN_SMEM_BYTES;
    cudaFuncSetAttribute(gemm_bf16pre_kernel,
                         cudaFuncAttributeMaxDynamicSharedMemorySize, gemm_smem);
    cudaFuncSetAttribute(attn_tc_kernel,
                         cudaFuncAttributeMaxDynamicSharedMemorySize, attn_smem);

    // Preludes
    split_f32_kernel<<<(BSROWS * DM) / (256 * 8), 256>>>(x, x_hi, x_lo);
    transpose_split_kernel<<<dim3(QLD / 32, DM / 32), dim3(32, 8)>>>(Wqkv, wq_hi, wq_lo, DM, QLD);
    transpose_split_kernel<<<dim3(DM / 32, DM / 32), dim3(32, 8)>>>(Wout, wo_hi, wo_lo, DM, DM);

    // QKV projection -> bf16 hi/lo qkv
    gemm_bf16pre_kernel<<<dim3(QLD / 128, BSROWS / 128), 256, gemm_smem>>>(
        x_hi, x_lo, wq_hi, wq_lo, bqkv, nullptr, qkv_hi, qkv_lo, BSROWS, QLD, DM);

    // Attention -> bf16 hi/lo val
    attn_tc_kernel<<<dim3(SEQ / 128, NH, BATCH), 256, attn_smem>>>();

    // Output projection -> fp32 out
    gemm_bf16pre_kernel<<<dim3(DM / 128, BSROWS / 128), 256, gemm_smem>>>(
        val_hi, val_lo, wo_hi, wo_lo, bout, out, nullptr, nullptr, BSROWS, DM, DM);
}